// round 1
// baseline (speedup 1.0000x reference)
#include <cuda_runtime.h>
#include <math.h>

#define B_SZ  4096
#define DIN   256
#define NOUT  32
#define MM    128
#define NH    2
#define HOC   (NH*NOUT)
#define JIT   1e-4f
#define TRILN (MM*(MM+1)/2)
#define AP    (MM+1)

// ---------------- scratch (static device globals; no runtime allocs) ----------------
__device__ float g_scal[NH*DIN];          // 1/lengthscale per head
__device__ float g_sf2v[NH];
__device__ float g_xh[NH*B_SZ*DIN];       // x / ls  (8 MB)
__device__ float g_x2[NH*B_SZ];
__device__ float g_zh[HOC*MM*DIN];        // z / ls  (16 MB)
__device__ float g_z2[HOC*MM];
__device__ float g_Pm[HOC*MM*MM];         // Kuu^{-1}            (4 MB)
__device__ float g_Gm[HOC*MM*MM];         // Ls^T Kuu^{-1}       (4 MB)
__device__ float g_cv[HOC*MM];            // Kuu^{-1} u_mean

__device__ __forceinline__ float blockReduce256(float v){
  __shared__ float s[8];
  int lane = threadIdx.x & 31;
  int w = threadIdx.x >> 5;
  #pragma unroll
  for (int o=16;o;o>>=1) v += __shfl_down_sync(0xffffffffu, v, o);
  if (lane==0) s[w] = v;
  __syncthreads();
  if (w==0){
    v = (lane < 8) ? s[lane] : 0.f;
    #pragma unroll
    for (int o=4;o;o>>=1) v += __shfl_down_sync(0xffffffffu, v, o);
  }
  return v;
}

// ---------------- hyperparameters ----------------
__global__ void k_hyper(const float* __restrict__ theta){
  int t = threadIdx.x;
  if (t < NH) g_sf2v[t] = expf(theta[t*(DIN+1)]);
  if (t < NH*DIN){
    int h = t / DIN, d = t % DIN;
    g_scal[t] = expf(-theta[h*(DIN+1)+1+d]);
  }
}

// ---------------- scale x and z by 1/ls, compute squared norms ----------------
__global__ void k_prep_x(const float* __restrict__ x){
  int bid = blockIdx.x;                 // = h*B + b
  int h = bid / B_SZ;
  int b = bid - h*B_SZ;
  int d = threadIdx.x;
  float v = x[(size_t)b*DIN + d] * g_scal[h*DIN + d];
  g_xh[(size_t)bid*DIN + d] = v;
  float s = blockReduce256(v*v);
  if (threadIdx.x == 0) g_x2[bid] = s;
}

__global__ void k_prep_z(const float* __restrict__ z){
  int bid = blockIdx.x;                 // = ho*MM + m
  int om = bid % (NOUT*MM);
  int h  = bid / (NOUT*MM);
  int d = threadIdx.x;
  float v = z[(size_t)om*DIN + d] * g_scal[h*DIN + d];
  g_zh[(size_t)bid*DIN + d] = v;
  float s = blockReduce256(v*v);
  if (threadIdx.x == 0) g_z2[bid] = s;
}

// ---------------- per-(h,o): Kuu -> chol -> L^{-1} -> P, G, c ----------------
__global__ __launch_bounds__(256) void k_factor(const float* __restrict__ u_mean,
                                                const float* __restrict__ u_tril){
  extern __shared__ float sm[];
  float* A  = sm;                 // MM x AP   (Kuu -> L -> P)
  float* W  = sm + MM*AP;         // MM x AP   (L^{-1})
  float* zt = sm + 2*MM*AP;       // MM x 17
  int ho = blockIdx.x;
  int h = ho / NOUT, o = ho % NOUT;
  int tid = threadIdx.x, tx = tid & 15, ty = tid >> 4;
  const float* zb = g_zh + (size_t)ho*MM*DIN;

  // Kuu via tiled self-GEMM over DIN
  float acc[8][8];
  #pragma unroll
  for (int i=0;i<8;i++)
    #pragma unroll
    for (int j=0;j<8;j++) acc[i][j]=0.f;

  for (int kt=0; kt<DIN; kt+=16){
    for (int idx=tid; idx<MM*16; idx+=256){
      int r = idx >> 4, c = idx & 15;
      zt[r*17+c] = zb[(size_t)r*DIN + kt + c];
    }
    __syncthreads();
    #pragma unroll
    for (int kk=0;kk<16;kk++){
      float a[8], bq[8];
      #pragma unroll
      for (int i=0;i<8;i++) a[i]  = zt[(ty*8+i)*17+kk];
      #pragma unroll
      for (int j=0;j<8;j++) bq[j] = zt[(tx*8+j)*17+kk];
      #pragma unroll
      for (int i=0;i<8;i++)
        #pragma unroll
        for (int j=0;j<8;j++) acc[i][j] += a[i]*bq[j];
    }
    __syncthreads();
  }

  float sf2 = g_sf2v[h];
  #pragma unroll
  for (int i=0;i<8;i++){
    int m = ty*8+i;
    float z2m = g_z2[ho*MM+m];
    #pragma unroll
    for (int j=0;j<8;j++){
      int n = tx*8+j;
      float d2 = fmaxf(z2m + g_z2[ho*MM+n] - 2.f*acc[i][j], 0.f);
      float v = sf2*__expf(-0.5f*d2);
      if (m==n) v += JIT;
      A[m*AP+n] = v;
    }
  }
  __syncthreads();

  // Cholesky (lower, in place)
  for (int k=0;k<MM;k++){
    float dk = A[k*AP+k];
    float inv = rsqrtf(dk);
    __syncthreads();                       // all read diag before any write
    if (tid==0) A[k*AP+k] = dk*inv;        // = sqrt(dk)
    for (int i=k+1+tid; i<MM; i+=256) A[i*AP+k] *= inv;
    __syncthreads();
    for (int i=k+1+tid; i<MM; i+=256){
      float lik = A[i*AP+k];
      for (int j=k+1;j<=i;j++) A[i*AP+j] -= lik*A[j*AP+k];
    }
    __syncthreads();
  }

  // W = L^{-1}  (one column per thread, forward substitution)
  for (int j=tid; j<MM; j+=256){
    W[j*AP+j] = 1.f/A[j*AP+j];
    for (int i=j+1;i<MM;i++){
      float s=0.f;
      for (int k=j;k<i;k++) s += A[i*AP+k]*W[k*AP+j];
      W[i*AP+j] = -s / A[i*AP+i];
    }
  }
  __syncthreads();

  // P = W^T W  (symmetric); overwrite A, store to global
  float* Pg = g_Pm + (size_t)ho*MM*MM;
  for (int idx=tid; idx<MM*MM; idx+=256){
    int i = idx >> 7, j = idx & 127;
    int k0 = i > j ? i : j;
    float s=0.f;
    for (int k=k0;k<MM;k++) s += W[k*AP+i]*W[k*AP+j];
    A[i*AP+j] = s;
    Pg[idx] = s;
  }
  __syncthreads();

  // G = Ls^T P  (Ls lower-tri packed row-major: Ls[k][i] = vec[k(k+1)/2 + i])
  const float* Lv = u_tril + (size_t)o*TRILN;
  float* Gg = g_Gm + (size_t)ho*MM*MM;
  for (int idx=tid; idx<MM*MM; idx+=256){
    int i = idx >> 7, j = idx & 127;
    float s=0.f;
    for (int k=i;k<MM;k++) s += __ldg(&Lv[(k*(k+1))/2 + i]) * A[k*AP+j];
    Gg[idx] = s;
  }
  // c = P u_mean
  const float* um = u_mean + o*MM;
  for (int i=tid;i<MM;i+=256){
    float s=0.f;
    for (int k=0;k<MM;k++) s += A[i*AP+k]*um[k];
    g_cv[ho*MM+i] = s;
  }
}

// ---------------- main fused kernel: kuf tile -> P@kuf, G@kuf -> mu/var ----------------
#define SMF (MM*MM + 2*MM*17 + MM + 2*16*MM + MM)

__global__ __launch_bounds__(256,2) void k_main(float* __restrict__ out){
  extern __shared__ float sm[];
  float* kuf = sm;                 // MM x MM (pitch MM)
  float* tA  = kuf + MM*MM;        // MM x 17
  float* tB  = tA + MM*17;         // MM x 17
  float* cs  = tB + MM*17;         // MM
  float* r1  = cs + MM;            // 16 x MM partial diag1
  float* r2  = r1 + 16*MM;         // 16 x MM partial diag2
  float* mus = r2 + 16*MM;         // MM

  int ho = blockIdx.y;
  int h  = ho / NOUT;
  int b0 = blockIdx.x * MM;
  int tid = threadIdx.x, tx = tid & 15, ty = tid >> 4;

  if (tid < MM){ cs[tid] = g_cv[ho*MM+tid]; mus[tid] = 0.f; }

  const float* zb = g_zh + (size_t)ho*MM*DIN;
  const float* xb = g_xh + ((size_t)h*B_SZ + b0)*DIN;

  // Phase A: cross[m,b] over DIN, then kuf = sf2*exp(-0.5 d2) into smem
  float acc[8][8];
  #pragma unroll
  for (int i=0;i<8;i++)
    #pragma unroll
    for (int j=0;j<8;j++) acc[i][j]=0.f;

  for (int kt=0; kt<DIN; kt+=16){
    for (int idx=tid; idx<MM*16; idx+=256){
      int r = idx>>4, c = idx&15;
      tA[r*17+c] = zb[(size_t)r*DIN + kt + c];
      tB[r*17+c] = xb[(size_t)r*DIN + kt + c];
    }
    __syncthreads();
    #pragma unroll
    for (int kk=0;kk<16;kk++){
      float a[8], bq[8];
      #pragma unroll
      for (int i=0;i<8;i++) a[i]  = tA[(ty*8+i)*17+kk];
      #pragma unroll
      for (int j=0;j<8;j++) bq[j] = tB[(tx*8+j)*17+kk];
      #pragma unroll
      for (int i=0;i<8;i++)
        #pragma unroll
        for (int j=0;j<8;j++) acc[i][j] += a[i]*bq[j];
    }
    __syncthreads();
  }
  float sf2 = g_sf2v[h];
  #pragma unroll
  for (int i=0;i<8;i++){
    float z2m = g_z2[ho*MM + ty*8+i];
    #pragma unroll
    for (int j=0;j<8;j++){
      float d2 = fmaxf(z2m + g_x2[h*B_SZ + b0 + tx*8 + j] - 2.f*acc[i][j], 0.f);
      kuf[(ty*8+i)*MM + tx*8+j] = sf2*__expf(-0.5f*d2);
    }
  }
  __syncthreads();

  // Pass 1: y1 = P @ kuf   (+ fused mu = c^T kuf on ty==0)
  const float* Pg = g_Pm + (size_t)ho*MM*MM;
  #pragma unroll
  for (int i=0;i<8;i++)
    #pragma unroll
    for (int j=0;j<8;j++) acc[i][j]=0.f;
  float mua[8];
  #pragma unroll
  for (int j=0;j<8;j++) mua[j]=0.f;

  for (int kt=0; kt<MM; kt+=16){
    for (int idx=tid; idx<MM*16; idx+=256){
      int r=idx>>4, c=idx&15;
      tA[r*17+c] = Pg[(size_t)r*MM + kt + c];
    }
    __syncthreads();
    #pragma unroll
    for (int kk=0;kk<16;kk++){
      int k = kt+kk;
      float a[8];
      #pragma unroll
      for (int i=0;i<8;i++) a[i] = tA[(ty*8+i)*17+kk];
      float4 v0 = *(const float4*)&kuf[k*MM + tx*8];
      float4 v1 = *(const float4*)&kuf[k*MM + tx*8 + 4];
      float bq[8] = {v0.x,v0.y,v0.z,v0.w,v1.x,v1.y,v1.z,v1.w};
      #pragma unroll
      for (int i=0;i<8;i++)
        #pragma unroll
        for (int j=0;j<8;j++) acc[i][j] += a[i]*bq[j];
      if (ty==0){
        float ck = cs[k];
        #pragma unroll
        for (int j=0;j<8;j++) mua[j] += ck*bq[j];
      }
    }
    __syncthreads();
  }
  {
    float d1[8];
    #pragma unroll
    for (int j=0;j<8;j++) d1[j]=0.f;
    #pragma unroll
    for (int i=0;i<8;i++){
      float4 w0 = *(const float4*)&kuf[(ty*8+i)*MM + tx*8];
      float4 w1 = *(const float4*)&kuf[(ty*8+i)*MM + tx*8 + 4];
      float kv[8] = {w0.x,w0.y,w0.z,w0.w,w1.x,w1.y,w1.z,w1.w};
      #pragma unroll
      for (int j=0;j<8;j++) d1[j] += kv[j]*acc[i][j];
    }
    #pragma unroll
    for (int j=0;j<8;j++) r1[ty*MM + tx*8+j] = d1[j];
    if (ty==0){
      #pragma unroll
      for (int j=0;j<8;j++) mus[tx*8+j] = mua[j];
    }
  }

  // Pass 2: y2 = G @ kuf, diag2 = colsum(y2^2)
  const float* Gg = g_Gm + (size_t)ho*MM*MM;
  #pragma unroll
  for (int i=0;i<8;i++)
    #pragma unroll
    for (int j=0;j<8;j++) acc[i][j]=0.f;

  for (int kt=0; kt<MM; kt+=16){
    for (int idx=tid; idx<MM*16; idx+=256){
      int r=idx>>4, c=idx&15;
      tA[r*17+c] = Gg[(size_t)r*MM + kt + c];
    }
    __syncthreads();
    #pragma unroll
    for (int kk=0;kk<16;kk++){
      int k = kt+kk;
      float a[8];
      #pragma unroll
      for (int i=0;i<8;i++) a[i] = tA[(ty*8+i)*17+kk];
      float4 v0 = *(const float4*)&kuf[k*MM + tx*8];
      float4 v1 = *(const float4*)&kuf[k*MM + tx*8 + 4];
      float bq[8] = {v0.x,v0.y,v0.z,v0.w,v1.x,v1.y,v1.z,v1.w};
      #pragma unroll
      for (int i=0;i<8;i++)
        #pragma unroll
        for (int j=0;j<8;j++) acc[i][j] += a[i]*bq[j];
    }
    __syncthreads();
  }
  {
    float d2a[8];
    #pragma unroll
    for (int j=0;j<8;j++) d2a[j]=0.f;
    #pragma unroll
    for (int i=0;i<8;i++)
      #pragma unroll
      for (int j=0;j<8;j++) d2a[j] += acc[i][j]*acc[i][j];
    #pragma unroll
    for (int j=0;j<8;j++) r2[ty*MM + tx*8+j] = d2a[j];
  }
  __syncthreads();

  if (tid < MM){
    float s1=0.f, s2=0.f;
    #pragma unroll
    for (int t=0;t<16;t++){ s1 += r1[t*MM+tid]; s2 += r2[t*MM+tid]; }
    size_t base = (size_t)ho*B_SZ + b0 + tid;
    out[base] = mus[tid];                                 // mu  (NH,OUT,B)
    out[(size_t)HOC*B_SZ + base] = sf2 - s1 + s2;         // var (NH,OUT,B)
  }
}

// ---------------- launch ----------------
extern "C" void kernel_launch(void* const* d_in, const int* in_sizes, int n_in,
                              void* d_out, int out_size){
  const float* x      = (const float*)d_in[0];
  const float* z      = (const float*)d_in[1];
  const float* u_mean = (const float*)d_in[2];
  const float* u_tril = (const float*)d_in[3];
  const float* theta  = (const float*)d_in[4];
  float* out = (float*)d_out;

  cudaFuncSetAttribute(k_factor, cudaFuncAttributeMaxDynamicSharedMemorySize,
                       (2*MM*AP + MM*17)*4);
  cudaFuncSetAttribute(k_main,   cudaFuncAttributeMaxDynamicSharedMemorySize,
                       SMF*4);

  k_hyper<<<1, 512>>>(theta);
  k_prep_x<<<NH*B_SZ, 256>>>(x);
  k_prep_z<<<HOC*MM, 256>>>(z);
  k_factor<<<HOC, 256, (2*MM*AP + MM*17)*4>>>(u_mean, u_tril);
  k_main<<<dim3(B_SZ/MM, HOC), 256, SMF*4>>>(out);
}

// round 2
// speedup vs baseline: 2.6559x; 2.6559x over previous
#include <cuda_runtime.h>
#include <math.h>

#define B_SZ  4096
#define DIN   256
#define NOUT  32
#define MM    128
#define NH    2
#define HOC   (NH*NOUT)
#define JIT   1e-4f
#define TRILN (MM*(MM+1)/2)
#define AP    132          // pitch for 128x128 smem matrices (mult of 4 for float4)
#define WP    132

// ---------------- scratch ----------------
__device__ float g_scal[NH*DIN];
__device__ float g_sf2v[NH];
__device__ float g_xh[NH*B_SZ*DIN];       // x / ls   (8 MB)
__device__ float g_x2[NH*B_SZ];
__device__ float g_zh[HOC*MM*DIN];        // z / ls   (16 MB)
__device__ float g_z2[HOC*MM];
__device__ float g_Qm[HOC*MM*MM];         // Q = P - T T^T   (4 MB)
__device__ float g_cv[HOC*MM];            // c = P u_mean

__device__ __forceinline__ float blockReduce256(float v){
  __shared__ float s[8];
  int lane = threadIdx.x & 31;
  int w = threadIdx.x >> 5;
  #pragma unroll
  for (int o=16;o;o>>=1) v += __shfl_down_sync(0xffffffffu, v, o);
  if (lane==0) s[w] = v;
  __syncthreads();
  if (w==0){
    v = (lane < 8) ? s[lane] : 0.f;
    #pragma unroll
    for (int o=4;o;o>>=1) v += __shfl_down_sync(0xffffffffu, v, o);
  }
  return v;
}

__global__ void k_hyper(const float* __restrict__ theta){
  int t = threadIdx.x;
  if (t < NH) g_sf2v[t] = expf(theta[t*(DIN+1)]);
  if (t < NH*DIN){
    int h = t / DIN, d = t % DIN;
    g_scal[t] = expf(-theta[h*(DIN+1)+1+d]);
  }
}

__global__ void k_prep_x(const float* __restrict__ x){
  int bid = blockIdx.x;                 // h*B + b
  int h = bid / B_SZ;
  int b = bid - h*B_SZ;
  int d = threadIdx.x;
  float v = x[(size_t)b*DIN + d] * g_scal[h*DIN + d];
  g_xh[(size_t)bid*DIN + d] = v;
  float s = blockReduce256(v*v);
  if (threadIdx.x == 0) g_x2[bid] = s;
}

__global__ void k_prep_z(const float* __restrict__ z){
  int bid = blockIdx.x;                 // ho*MM + m
  int om = bid % (NOUT*MM);
  int h  = bid / (NOUT*MM);
  int d = threadIdx.x;
  float v = z[(size_t)om*DIN + d] * g_scal[h*DIN + d];
  g_zh[(size_t)bid*DIN + d] = v;
  float s = blockReduce256(v*v);
  if (threadIdx.x == 0) g_z2[bid] = s;
}

// ============ k_factor: Kuu -> L -> W=L^{-1} -> P -> c, T=P*Ls -> Q=P-TT^T ============
// smem: sA[128*132] | sW[128*132] | sPan[2176]
#define FSM (MM*AP + MM*WP + 2176)

__global__ __launch_bounds__(256) void k_factor(const float* __restrict__ u_mean,
                                                const float* __restrict__ u_tril){
  extern __shared__ float sm[];
  float* sA   = sm;
  float* sW   = sm + MM*AP;
  float* sPan = sW + MM*WP;

  int ho = blockIdx.x;
  int h = ho / NOUT, o = ho % NOUT;
  int tid = threadIdx.x, tx = tid & 15, ty = tid >> 4;
  const float* zb = g_zh + (size_t)ho*MM*DIN;

  // ---- Phase 1: Kuu into sA (register-tiled GEMM, conflict-free B) ----
  {
    float* tA  = sW;           // [row][kk] pitch 17 (2176 floats)
    float* tBz = sPan;         // [kk][col] pitch 132 (2112 floats)
    float acc[8][8];
    #pragma unroll
    for (int i=0;i<8;i++)
      #pragma unroll
      for (int j=0;j<8;j++) acc[i][j]=0.f;

    for (int kt=0; kt<DIN; kt+=16){
      for (int idx=tid; idx<MM*16; idx+=256){
        int r = idx >> 4, c = idx & 15;
        float v = zb[(size_t)r*DIN + kt + c];
        tA[r*17+c] = v;
        tBz[c*132+r] = v;
      }
      __syncthreads();
      #pragma unroll
      for (int kk=0;kk<16;kk++){
        float a[8];
        #pragma unroll
        for (int i=0;i<8;i++) a[i] = tA[(ty*8+i)*17+kk];
        float4 b0 = *(const float4*)&tBz[kk*132 + tx*8];
        float4 b1 = *(const float4*)&tBz[kk*132 + tx*8 + 4];
        float bq[8] = {b0.x,b0.y,b0.z,b0.w,b1.x,b1.y,b1.z,b1.w};
        #pragma unroll
        for (int i=0;i<8;i++)
          #pragma unroll
          for (int j=0;j<8;j++) acc[i][j] += a[i]*bq[j];
      }
      __syncthreads();
    }
    float sf2 = g_sf2v[h];
    #pragma unroll
    for (int i=0;i<8;i++){
      int m = ty*8+i;
      float z2m = g_z2[ho*MM+m];
      float vals[8];
      #pragma unroll
      for (int j=0;j<8;j++){
        int n = tx*8+j;
        float d2 = fmaxf(z2m + g_z2[ho*MM+n] - 2.f*acc[i][j], 0.f);
        float v = sf2*__expf(-0.5f*d2);
        if (m==n) v += JIT;
        vals[j] = v;
      }
      *(float4*)&sA[m*AP + tx*8]     = make_float4(vals[0],vals[1],vals[2],vals[3]);
      *(float4*)&sA[m*AP + tx*8 + 4] = make_float4(vals[4],vals[5],vals[6],vals[7]);
    }
  }
  __syncthreads();

  // zero sW (needed: W upper triangle must be 0)
  for (int idx=tid; idx<MM*WP; idx+=256) sW[idx] = 0.f;
  __syncthreads();

  // ---- Phase 2: blocked Cholesky (panel 16), in-place in sA, full-square sym update ----
  for (int p=0;p<8;p++){
    int k0 = 16*p;
    // diag block factor: warp 0
    if (tid < 32){
      #pragma unroll 1
      for (int t=0;t<16;t++){
        int k = k0+t;
        float dk = sA[k*AP+k];
        float inv = rsqrtf(dk);
        __syncwarp();
        if (tid == 0) sA[k*AP+k] = dk*inv;
        if (tid > t && tid < 16) sA[(k0+tid)*AP + k] *= inv;
        __syncwarp();
        if (tid > t && tid < 16){
          int i = k0+tid;
          float lik = sA[i*AP+k];
          for (int j=k+1;j<=i;j++) sA[i*AP+j] -= lik * sA[j*AP+k];
        }
        __syncwarp();
      }
    }
    __syncthreads();
    int R = 112 - 16*p;
    if (R > 0){
      // panel TRSM: rows below
      if (tid < R){
        int i = k0+16+tid;
        float v[16];
        #pragma unroll
        for (int t=0;t<16;t++) v[t] = sA[i*AP + k0 + t];
        #pragma unroll
        for (int t=0;t<16;t++){
          #pragma unroll
          for (int s=0;s<16;s++) if (s<t) v[t] -= v[s]*sA[(k0+t)*AP + k0+s];
          v[t] /= sA[(k0+t)*AP + k0+t];
        }
        #pragma unroll
        for (int t=0;t<16;t++) sA[i*AP + k0+t] = v[t];
      }
      __syncthreads();
      // trailing update: 4x4 register tiles, full square (keeps symmetry)
      int rt = R >> 2;
      int nt = rt*rt;
      for (int tile = tid; tile < nt; tile += 256){
        int tr = tile / rt, tc = tile % rt;
        int i0 = k0+16+4*tr, j0 = k0+16+4*tc;
        float accu[16];
        #pragma unroll
        for (int u=0;u<16;u++) accu[u]=0.f;
        #pragma unroll
        for (int t=0;t<16;t++){
          float a4[4], b4[4];
          #pragma unroll
          for (int r=0;r<4;r++) a4[r] = sA[(i0+r)*AP + k0+t];
          #pragma unroll
          for (int c=0;c<4;c++) b4[c] = sA[(j0+c)*AP + k0+t];
          #pragma unroll
          for (int r=0;r<4;r++)
            #pragma unroll
            for (int c=0;c<4;c++) accu[r*4+c] += a4[r]*b4[c];
        }
        #pragma unroll
        for (int r=0;r<4;r++)
          #pragma unroll
          for (int c=0;c<4;c++) sA[(i0+r)*AP + j0+c] -= accu[r*4+c];
      }
      __syncthreads();
    }
  }

  // ---- Phase 3: W = L^{-1} blocked ----
  // 3a: diag blocks (128 threads, one per (block, col))
  if (tid < 128){
    int p = tid >> 4, jl = tid & 15, k0 = p*16;
    float w[16];
    #pragma unroll
    for (int u=0;u<16;u++) w[u]=0.f;
    #pragma unroll
    for (int u=0;u<16;u++){
      if (u == jl){
        w[u] = 1.0f / sA[(k0+u)*AP + k0+u];
      } else if (u > jl){
        float s = 0.f;
        #pragma unroll
        for (int k=0;k<15;k++)
          if (k >= jl && k < u) s += sA[(k0+u)*AP + k0+k] * w[k];
        w[u] = -s / sA[(k0+u)*AP + k0+u];
      }
    }
    #pragma unroll
    for (int u=0;u<16;u++) if (u >= jl) sW[(k0+u)*WP + k0+jl] = w[u];
  }
  __syncthreads();
  // 3b: off-diagonal blocks by diagonal distance s
  for (int s=1;s<8;s++){
    int total = (8-s) << 8;
    for (int idx=tid; idx<total; idx+=256){
      int q = idx >> 8, rc = idx & 255, r = rc >> 4, c = rc & 15;
      int irow = (q+s)*16 + r, q0 = q*16;
      float acc = 0.f;
      for (int k=16*q; k<16*(q+s); k++) acc += sA[irow*AP+k] * sW[k*WP + q0+c];
      sPan[idx] = acc;
    }
    __syncthreads();
    for (int idx=tid; idx<total; idx+=256){
      int q = idx >> 8, rc = idx & 255, r = rc >> 4, c = rc & 15;
      int i0 = (q+s)*16, q0 = q*16;
      float acc = 0.f;
      for (int u=0; u<=r; u++) acc += sW[(i0+r)*WP + i0+u] * sPan[(q<<8) + u*16 + c];
      sW[(i0+r)*WP + q0 + c] = -acc;
    }
    __syncthreads();
  }

  // ---- Phase 4: P = W^T W -> sA (overwrite L) ----
  {
    float acc[8][8];
    #pragma unroll
    for (int i=0;i<8;i++)
      #pragma unroll
      for (int j=0;j<8;j++) acc[i][j]=0.f;
    #pragma unroll 4
    for (int k=0;k<MM;k++){
      float a[8];
      #pragma unroll
      for (int i=0;i<8;i++) a[i] = sW[k*WP + ty*8+i];
      float4 b0 = *(const float4*)&sW[k*WP + tx*8];
      float4 b1 = *(const float4*)&sW[k*WP + tx*8 + 4];
      float bq[8] = {b0.x,b0.y,b0.z,b0.w,b1.x,b1.y,b1.z,b1.w};
      #pragma unroll
      for (int i=0;i<8;i++)
        #pragma unroll
        for (int j=0;j<8;j++) acc[i][j] += a[i]*bq[j];
    }
    __syncthreads();   // everyone done reading sW(L uses)/sA(L) before P overwrite
    #pragma unroll
    for (int i=0;i<8;i++){
      *(float4*)&sA[(ty*8+i)*AP + tx*8]     = make_float4(acc[i][0],acc[i][1],acc[i][2],acc[i][3]);
      *(float4*)&sA[(ty*8+i)*AP + tx*8 + 4] = make_float4(acc[i][4],acc[i][5],acc[i][6],acc[i][7]);
    }
  }
  __syncthreads();

  // ---- Phase 5: c = P u_mean (threads 0-127) ; load Ls into sW lower (threads 128-255) ----
  if (tid < MM){
    const float* um = u_mean + o*MM;
    float s = 0.f;
    for (int k=0;k<MM;k++) s += sA[tid*AP+k]*um[k];
    g_cv[ho*MM+tid] = s;
  } else {
    int r = tid - MM;
    const float* Lv = u_tril + (size_t)o*TRILN + ((size_t)r*(r+1))/2;
    for (int c=0;c<=r;c++) sW[r*WP + c] = Lv[c];
  }
  __syncthreads();

  // ---- Phase 6: T = P * Ls, in-place into sW, 16-column panels ----
  for (int q8=0;q8<8;q8++){
    int q0 = q8*16;
    for (int idx=tid; idx<MM*16; idx+=256){
      int k = idx >> 4, jj = idx & 15;
      sPan[k*17+jj] = sW[k*WP + q0+jj];
    }
    __syncthreads();
    int tr = tid >> 3, tc = tid & 7;
    int i0 = tr*4, jj0 = tc*2;
    float acc8[8];
    #pragma unroll
    for (int u=0;u<8;u++) acc8[u]=0.f;
    for (int k=q0;k<MM;k++){
      float bb0 = sPan[k*17+jj0], bb1 = sPan[k*17+jj0+1];
      #pragma unroll
      for (int r=0;r<4;r++){
        float av = sA[(i0+r)*AP + k];
        acc8[r*2]   += av*bb0;
        acc8[r*2+1] += av*bb1;
      }
    }
    #pragma unroll
    for (int r=0;r<4;r++){
      sW[(i0+r)*WP + q0+jj0]   = acc8[r*2];
      sW[(i0+r)*WP + q0+jj0+1] = acc8[r*2+1];
    }
    __syncthreads();
  }

  // ---- Phase 7: Q = P - T T^T -> global ----
  {
    float acc[8][8];
    #pragma unroll
    for (int i=0;i<8;i++)
      #pragma unroll
      for (int j=0;j<8;j++) acc[i][j]=0.f;
    for (int kt=0; kt<MM; kt+=16){
      for (int idx=tid; idx<MM*16; idx+=256){
        int kk = idx & 15, col = idx >> 4;
        sPan[kk*132 + col] = sW[col*WP + kt+kk];
      }
      __syncthreads();
      #pragma unroll
      for (int kk=0;kk<16;kk++){
        int k = kt+kk;
        float a[8];
        #pragma unroll
        for (int i=0;i<8;i++) a[i] = sW[(ty*8+i)*WP + k];
        float4 b0 = *(const float4*)&sPan[kk*132 + tx*8];
        float4 b1 = *(const float4*)&sPan[kk*132 + tx*8 + 4];
        float bq[8] = {b0.x,b0.y,b0.z,b0.w,b1.x,b1.y,b1.z,b1.w};
        #pragma unroll
        for (int i=0;i<8;i++)
          #pragma unroll
          for (int j=0;j<8;j++) acc[i][j] += a[i]*bq[j];
      }
      __syncthreads();
    }
    float* Qg = g_Qm + (size_t)ho*MM*MM;
    #pragma unroll
    for (int i=0;i<8;i++){
      float4 p0 = *(const float4*)&sA[(ty*8+i)*AP + tx*8];
      float4 p1 = *(const float4*)&sA[(ty*8+i)*AP + tx*8 + 4];
      float4 o0 = make_float4(p0.x-acc[i][0], p0.y-acc[i][1], p0.z-acc[i][2], p0.w-acc[i][3]);
      float4 o1 = make_float4(p1.x-acc[i][4], p1.y-acc[i][5], p1.z-acc[i][6], p1.w-acc[i][7]);
      *(float4*)&Qg[(size_t)(ty*8+i)*MM + tx*8]     = o0;
      *(float4*)&Qg[(size_t)(ty*8+i)*MM + tx*8 + 4] = o1;
    }
  }
}

// ============ k_main: kuf tile -> Q@kuf -> mu/var ============
// smem: kuf[128*128] | tA[2176] | tB[2112] | cs[128] | r1[16*128]
#define SMF (MM*MM + 2176 + 2112 + 128 + 16*MM)

__global__ __launch_bounds__(256,2) void k_main(float* __restrict__ out){
  extern __shared__ float sm[];
  float* kuf = sm;
  float* tA  = sm + MM*MM;
  float* tB  = tA + 2176;
  float* cs  = tB + 2112;
  float* r1  = cs + 128;

  int ho = blockIdx.y;
  int h  = ho / NOUT;
  int b0 = blockIdx.x * MM;
  int tid = threadIdx.x, tx = tid & 15, ty = tid >> 4;

  if (tid < MM) cs[tid] = g_cv[ho*MM+tid];

  const float* zb = g_zh + (size_t)ho*MM*DIN;
  const float* xb = g_xh + ((size_t)h*B_SZ + b0)*DIN;

  // Phase A: cross-GEMM over DIN -> kuf
  float acc[8][8];
  #pragma unroll
  for (int i=0;i<8;i++)
    #pragma unroll
    for (int j=0;j<8;j++) acc[i][j]=0.f;

  for (int kt=0; kt<DIN; kt+=16){
    for (int idx=tid; idx<MM*16; idx+=256){
      int r = idx >> 4, c = idx & 15;
      tA[r*17+c]   = zb[(size_t)r*DIN + kt + c];
      tB[c*132+r]  = xb[(size_t)r*DIN + kt + c];
    }
    __syncthreads();
    #pragma unroll
    for (int kk=0;kk<16;kk++){
      float a[8];
      #pragma unroll
      for (int i=0;i<8;i++) a[i] = tA[(ty*8+i)*17+kk];
      float4 b0v = *(const float4*)&tB[kk*132 + tx*8];
      float4 b1v = *(const float4*)&tB[kk*132 + tx*8 + 4];
      float bq[8] = {b0v.x,b0v.y,b0v.z,b0v.w,b1v.x,b1v.y,b1v.z,b1v.w};
      #pragma unroll
      for (int i=0;i<8;i++)
        #pragma unroll
        for (int j=0;j<8;j++) acc[i][j] += a[i]*bq[j];
    }
    __syncthreads();
  }
  float sf2 = g_sf2v[h];
  #pragma unroll
  for (int i=0;i<8;i++){
    int m = ty*8+i;
    float z2m = g_z2[ho*MM + m];
    float vals[8];
    #pragma unroll
    for (int j=0;j<8;j++){
      float d2 = fmaxf(z2m + g_x2[h*B_SZ + b0 + tx*8 + j] - 2.f*acc[i][j], 0.f);
      vals[j] = sf2*__expf(-0.5f*d2);
    }
    *(float4*)&kuf[m*MM + tx*8]     = make_float4(vals[0],vals[1],vals[2],vals[3]);
    *(float4*)&kuf[m*MM + tx*8 + 4] = make_float4(vals[4],vals[5],vals[6],vals[7]);
  }
  __syncthreads();

  // Phase B: y = Q @ kuf (+ fused mu on ty==0)
  const float* Qg = g_Qm + (size_t)ho*MM*MM;
  #pragma unroll
  for (int i=0;i<8;i++)
    #pragma unroll
    for (int j=0;j<8;j++) acc[i][j]=0.f;
  float mua[8];
  #pragma unroll
  for (int j=0;j<8;j++) mua[j]=0.f;

  for (int kt=0; kt<MM; kt+=16){
    for (int idx=tid; idx<MM*16; idx+=256){
      int r = idx >> 4, c = idx & 15;
      tA[r*17+c] = Qg[(size_t)r*MM + kt + c];
    }
    __syncthreads();
    #pragma unroll
    for (int kk=0;kk<16;kk++){
      int k = kt+kk;
      float a[8];
      #pragma unroll
      for (int i=0;i<8;i++) a[i] = tA[(ty*8+i)*17+kk];
      float4 v0 = *(const float4*)&kuf[k*MM + tx*8];
      float4 v1 = *(const float4*)&kuf[k*MM + tx*8 + 4];
      float bq[8] = {v0.x,v0.y,v0.z,v0.w,v1.x,v1.y,v1.z,v1.w};
      #pragma unroll
      for (int i=0;i<8;i++)
        #pragma unroll
        for (int j=0;j<8;j++) acc[i][j] += a[i]*bq[j];
      if (ty==0){
        float ck = cs[k];
        #pragma unroll
        for (int j=0;j<8;j++) mua[j] += ck*bq[j];
      }
    }
    __syncthreads();
  }

  // diag partial: d[j] = sum_i kuf[m][b] * y[m][b]
  {
    float d[8];
    #pragma unroll
    for (int j=0;j<8;j++) d[j]=0.f;
    #pragma unroll
    for (int i=0;i<8;i++){
      float4 w0 = *(const float4*)&kuf[(ty*8+i)*MM + tx*8];
      float4 w1 = *(const float4*)&kuf[(ty*8+i)*MM + tx*8 + 4];
      float kv[8] = {w0.x,w0.y,w0.z,w0.w,w1.x,w1.y,w1.z,w1.w};
      #pragma unroll
      for (int j=0;j<8;j++) d[j] += kv[j]*acc[i][j];
    }
    #pragma unroll
    for (int j=0;j<8;j++) r1[ty*MM + tx*8+j] = d[j];
    if (ty==0){
      size_t base = (size_t)ho*B_SZ + b0 + tx*8;
      #pragma unroll
      for (int j=0;j<8;j++) out[base+j] = mua[j];
    }
  }
  __syncthreads();

  if (tid < MM){
    float s = 0.f;
    #pragma unroll
    for (int t=0;t<16;t++) s += r1[t*MM+tid];
    out[(size_t)HOC*B_SZ + (size_t)ho*B_SZ + b0 + tid] = sf2 - s;
  }
}

// ---------------- launch ----------------
extern "C" void kernel_launch(void* const* d_in, const int* in_sizes, int n_in,
                              void* d_out, int out_size){
  const float* x      = (const float*)d_in[0];
  const float* z      = (const float*)d_in[1];
  const float* u_mean = (const float*)d_in[2];
  const float* u_tril = (const float*)d_in[3];
  const float* theta  = (const float*)d_in[4];
  float* out = (float*)d_out;

  cudaFuncSetAttribute(k_factor, cudaFuncAttributeMaxDynamicSharedMemorySize, FSM*4);
  cudaFuncSetAttribute(k_main,   cudaFuncAttributeMaxDynamicSharedMemorySize, SMF*4);

  k_hyper<<<1, 512>>>(theta);
  k_prep_x<<<NH*B_SZ, 256>>>(x);
  k_prep_z<<<HOC*MM, 256>>>(z);
  k_factor<<<HOC, 256, FSM*4>>>(u_mean, u_tril);
  k_main<<<dim3(B_SZ/MM, HOC), 256, SMF*4>>>(out);
}

// round 4
// speedup vs baseline: 7.2209x; 2.7188x over previous
#include <cuda_runtime.h>
#include <cuda_bf16.h>
#include <math.h>
#include <cstdint>

#define B_SZ  4096
#define DIN   256
#define NOUT  32
#define MM    128
#define NH    2
#define HOC   (NH*NOUT)
#define JIT   1e-4f
#define TRILN (MM*(MM+1)/2)
#define AP    132
#define WP    132

// ---------------- scratch ----------------
__device__ float g_scal[NH*DIN];
__device__ float g_sf2v[NH];
__device__ float g_x2[NH*B_SZ];
__device__ float g_zh[HOC*MM*DIN];        // z/ls fp32 (k_factor)
__device__ float g_z2[HOC*MM];
__device__ float g_cv[HOC*MM];
__device__ __align__(16) __nv_bfloat16 g_xb[NH*B_SZ*DIN];
__device__ __align__(16) __nv_bfloat16 g_zb[HOC*MM*DIN];
__device__ __align__(16) __nv_bfloat16 g_Qb[HOC*MM*MM];

// ---------------- helpers ----------------
__device__ __forceinline__ uint32_t smem_u32(const void* p){
  uint32_t a;
  asm("{ .reg .u64 t; cvta.to.shared.u64 t, %1; cvt.u32.u64 %0, t; }" : "=r"(a) : "l"(p));
  return a;
}
__device__ __forceinline__ void ldsm4(uint32_t addr, uint32_t* r){
  asm volatile("ldmatrix.sync.aligned.m8n8.x4.shared.b16 {%0,%1,%2,%3}, [%4];"
    : "=r"(r[0]),"=r"(r[1]),"=r"(r[2]),"=r"(r[3]) : "r"(addr));
}
__device__ __forceinline__ void mma16816(float* c, const uint32_t* a, const uint32_t* b){
  asm volatile("mma.sync.aligned.m16n8k16.row.col.f32.bf16.bf16.f32 "
    "{%0,%1,%2,%3}, {%4,%5,%6,%7}, {%8,%9}, {%0,%1,%2,%3};"
    : "+f"(c[0]),"+f"(c[1]),"+f"(c[2]),"+f"(c[3])
    : "r"(a[0]),"r"(a[1]),"r"(a[2]),"r"(a[3]), "r"(b[0]),"r"(b[1]));
}
#define CP16(dst, src) asm volatile("cp.async.cg.shared.global [%0], [%1], 16;" :: "r"(dst), "l"(src))
#define CP_COMMIT()    asm volatile("cp.async.commit_group;" ::: "memory")
#define CP_WAIT(n)     asm volatile("cp.async.wait_group %0;" :: "n"(n) : "memory")

__device__ __forceinline__ uint32_t pack_bf16x2(float lo, float hi){
  uint32_t r;
  asm("cvt.rn.satfinite.bf16x2.f32 %0, %1, %2;" : "=r"(r) : "f"(hi), "f"(lo));
  return r;
}

__device__ __forceinline__ float blockReduce256(float v){
  __shared__ float s[8];
  int lane = threadIdx.x & 31, w = threadIdx.x >> 5;
  #pragma unroll
  for (int o=16;o;o>>=1) v += __shfl_down_sync(0xffffffffu, v, o);
  if (lane==0) s[w] = v;
  __syncthreads();
  if (w==0){
    v = (lane < 8) ? s[lane] : 0.f;
    #pragma unroll
    for (int o=4;o;o>>=1) v += __shfl_down_sync(0xffffffffu, v, o);
  }
  return v;
}

// ---------------- hyper / prep ----------------
__global__ void k_hyper(const float* __restrict__ theta){
  int t = threadIdx.x;
  if (t < NH) g_sf2v[t] = expf(theta[t*(DIN+1)]);
  if (t < NH*DIN){
    int h = t / DIN, d = t % DIN;
    g_scal[t] = expf(-theta[h*(DIN+1)+1+d]);
  }
}
__global__ void k_prep_x(const float* __restrict__ x){
  int bid = blockIdx.x;  int h = bid / B_SZ, b = bid - h*B_SZ;
  int d = threadIdx.x;
  float v = x[(size_t)b*DIN + d] * g_scal[h*DIN + d];
  g_xb[(size_t)bid*DIN + d] = __float2bfloat16(v);
  float s = blockReduce256(v*v);
  if (threadIdx.x == 0) g_x2[bid] = s;
}
__global__ void k_prep_z(const float* __restrict__ z){
  int bid = blockIdx.x;
  int om = bid % (NOUT*MM);
  int d = threadIdx.x;
  int h = bid / (NOUT*MM);
  float v = z[(size_t)om*DIN + d] * g_scal[h*DIN + d];
  g_zh[(size_t)bid*DIN + d] = v;
  g_zb[(size_t)bid*DIN + d] = __float2bfloat16(v);
  float s = blockReduce256(v*v);
  if (threadIdx.x == 0) g_z2[bid] = s;
}

// ============ k_factor (same algorithm as R2; Q emitted bf16) ============
#define FSM (MM*AP + MM*WP + 2176)

__global__ __launch_bounds__(256) void k_factor(const float* __restrict__ u_mean,
                                                const float* __restrict__ u_tril){
  extern __shared__ float sm[];
  float* sA   = sm;
  float* sW   = sm + MM*AP;
  float* sPan = sW + MM*WP;

  int ho = blockIdx.x;
  int h = ho / NOUT, o = ho % NOUT;
  int tid = threadIdx.x, tx = tid & 15, ty = tid >> 4;
  const float* zb = g_zh + (size_t)ho*MM*DIN;

  // Phase 1: Kuu
  {
    float* tA  = sW;
    float* tBz = sPan;
    float acc[8][8];
    #pragma unroll
    for (int i=0;i<8;i++)
      #pragma unroll
      for (int j=0;j<8;j++) acc[i][j]=0.f;
    for (int kt=0; kt<DIN; kt+=16){
      for (int idx=tid; idx<MM*16; idx+=256){
        int r = idx >> 4, c = idx & 15;
        float v = zb[(size_t)r*DIN + kt + c];
        tA[r*17+c] = v;
        tBz[c*132+r] = v;
      }
      __syncthreads();
      #pragma unroll
      for (int kk=0;kk<16;kk++){
        float a[8];
        #pragma unroll
        for (int i=0;i<8;i++) a[i] = tA[(ty*8+i)*17+kk];
        float4 b0 = *(const float4*)&tBz[kk*132 + tx*8];
        float4 b1 = *(const float4*)&tBz[kk*132 + tx*8 + 4];
        float bq[8] = {b0.x,b0.y,b0.z,b0.w,b1.x,b1.y,b1.z,b1.w};
        #pragma unroll
        for (int i=0;i<8;i++)
          #pragma unroll
          for (int j=0;j<8;j++) acc[i][j] += a[i]*bq[j];
      }
      __syncthreads();
    }
    float sf2 = g_sf2v[h];
    #pragma unroll
    for (int i=0;i<8;i++){
      int m = ty*8+i;
      float z2m = g_z2[ho*MM+m];
      float vals[8];
      #pragma unroll
      for (int j=0;j<8;j++){
        int n = tx*8+j;
        float d2 = fmaxf(z2m + g_z2[ho*MM+n] - 2.f*acc[i][j], 0.f);
        float v = sf2*__expf(-0.5f*d2);
        if (m==n) v += JIT;
        vals[j] = v;
      }
      *(float4*)&sA[m*AP + tx*8]     = make_float4(vals[0],vals[1],vals[2],vals[3]);
      *(float4*)&sA[m*AP + tx*8 + 4] = make_float4(vals[4],vals[5],vals[6],vals[7]);
    }
  }
  __syncthreads();

  for (int idx=tid; idx<MM*WP; idx+=256) sW[idx] = 0.f;
  __syncthreads();

  // Phase 2: blocked Cholesky
  for (int p=0;p<8;p++){
    int k0 = 16*p;
    if (tid < 32){
      #pragma unroll 1
      for (int t=0;t<16;t++){
        int k = k0+t;
        float dk = sA[k*AP+k];
        float inv = rsqrtf(dk);
        __syncwarp();
        if (tid == 0) sA[k*AP+k] = dk*inv;
        if (tid > t && tid < 16) sA[(k0+tid)*AP + k] *= inv;
        __syncwarp();
        if (tid > t && tid < 16){
          int i = k0+tid;
          float lik = sA[i*AP+k];
          for (int j=k+1;j<=i;j++) sA[i*AP+j] -= lik * sA[j*AP+k];
        }
        __syncwarp();
      }
    }
    __syncthreads();
    int R = 112 - 16*p;
    if (R > 0){
      if (tid < R){
        int i = k0+16+tid;
        float v[16];
        #pragma unroll
        for (int t=0;t<16;t++) v[t] = sA[i*AP + k0 + t];
        #pragma unroll
        for (int t=0;t<16;t++){
          #pragma unroll
          for (int s=0;s<16;s++) if (s<t) v[t] -= v[s]*sA[(k0+t)*AP + k0+s];
          v[t] /= sA[(k0+t)*AP + k0+t];
        }
        #pragma unroll
        for (int t=0;t<16;t++) sA[i*AP + k0+t] = v[t];
      }
      __syncthreads();
      int rt = R >> 2;
      int nt = rt*rt;
      for (int tile = tid; tile < nt; tile += 256){
        int tr = tile / rt, tc = tile % rt;
        int i0 = k0+16+4*tr, j0 = k0+16+4*tc;
        float accu[16];
        #pragma unroll
        for (int u=0;u<16;u++) accu[u]=0.f;
        #pragma unroll
        for (int t=0;t<16;t++){
          float a4[4], b4[4];
          #pragma unroll
          for (int r=0;r<4;r++) a4[r] = sA[(i0+r)*AP + k0+t];
          #pragma unroll
          for (int c=0;c<4;c++) b4[c] = sA[(j0+c)*AP + k0+t];
          #pragma unroll
          for (int r=0;r<4;r++)
            #pragma unroll
            for (int c=0;c<4;c++) accu[r*4+c] += a4[r]*b4[c];
        }
        #pragma unroll
        for (int r=0;r<4;r++)
          #pragma unroll
          for (int c=0;c<4;c++) sA[(i0+r)*AP + j0+c] -= accu[r*4+c];
      }
      __syncthreads();
    }
  }

  // Phase 3: W = L^{-1}
  if (tid < 128){
    int p = tid >> 4, jl = tid & 15, k0 = p*16;
    float w[16];
    #pragma unroll
    for (int u=0;u<16;u++) w[u]=0.f;
    #pragma unroll
    for (int u=0;u<16;u++){
      if (u == jl){
        w[u] = 1.0f / sA[(k0+u)*AP + k0+u];
      } else if (u > jl){
        float s = 0.f;
        #pragma unroll
        for (int k=0;k<15;k++)
          if (k >= jl && k < u) s += sA[(k0+u)*AP + k0+k] * w[k];
        w[u] = -s / sA[(k0+u)*AP + k0+u];
      }
    }
    #pragma unroll
    for (int u=0;u<16;u++) if (u >= jl) sW[(k0+u)*WP + k0+jl] = w[u];
  }
  __syncthreads();
  for (int s=1;s<8;s++){
    int total = (8-s) << 8;
    for (int idx=tid; idx<total; idx+=256){
      int q = idx >> 8, rc = idx & 255, r = rc >> 4, c = rc & 15;
      int irow = (q+s)*16 + r, q0 = q*16;
      float acc = 0.f;
      for (int k=16*q; k<16*(q+s); k++) acc += sA[irow*AP+k] * sW[k*WP + q0+c];
      sPan[idx] = acc;
    }
    __syncthreads();
    for (int idx=tid; idx<total; idx+=256){
      int q = idx >> 8, rc = idx & 255, r = rc >> 4, c = rc & 15;
      int i0 = (q+s)*16, q0 = q*16;
      float acc = 0.f;
      for (int u=0; u<=r; u++) acc += sW[(i0+r)*WP + i0+u] * sPan[(q<<8) + u*16 + c];
      sW[(i0+r)*WP + q0 + c] = -acc;
    }
    __syncthreads();
  }

  // Phase 4: P = W^T W
  {
    float acc[8][8];
    #pragma unroll
    for (int i=0;i<8;i++)
      #pragma unroll
      for (int j=0;j<8;j++) acc[i][j]=0.f;
    #pragma unroll 4
    for (int k=0;k<MM;k++){
      float a[8];
      #pragma unroll
      for (int i=0;i<8;i++) a[i] = sW[k*WP + ty*8+i];
      float4 b0 = *(const float4*)&sW[k*WP + tx*8];
      float4 b1 = *(const float4*)&sW[k*WP + tx*8 + 4];
      float bq[8] = {b0.x,b0.y,b0.z,b0.w,b1.x,b1.y,b1.z,b1.w};
      #pragma unroll
      for (int i=0;i<8;i++)
        #pragma unroll
        for (int j=0;j<8;j++) acc[i][j] += a[i]*bq[j];
    }
    __syncthreads();
    #pragma unroll
    for (int i=0;i<8;i++){
      *(float4*)&sA[(ty*8+i)*AP + tx*8]     = make_float4(acc[i][0],acc[i][1],acc[i][2],acc[i][3]);
      *(float4*)&sA[(ty*8+i)*AP + tx*8 + 4] = make_float4(acc[i][4],acc[i][5],acc[i][6],acc[i][7]);
    }
  }
  __syncthreads();

  // Phase 5: c = P u_mean ; load Ls
  if (tid < MM){
    const float* um = u_mean + o*MM;
    float s = 0.f;
    for (int k=0;k<MM;k++) s += sA[tid*AP+k]*um[k];
    g_cv[ho*MM+tid] = s;
  } else {
    int r = tid - MM;
    const float* Lv = u_tril + (size_t)o*TRILN + ((size_t)r*(r+1))/2;
    for (int c=0;c<=r;c++) sW[r*WP + c] = Lv[c];
  }
  __syncthreads();

  // Phase 6: T = P * Ls
  for (int q8=0;q8<8;q8++){
    int q0 = q8*16;
    for (int idx=tid; idx<MM*16; idx+=256){
      int k = idx >> 4, jj = idx & 15;
      sPan[k*17+jj] = sW[k*WP + q0+jj];
    }
    __syncthreads();
    int tr = tid >> 3, tc = tid & 7;
    int i0 = tr*4, jj0 = tc*2;
    float acc8[8];
    #pragma unroll
    for (int u=0;u<8;u++) acc8[u]=0.f;
    for (int k=q0;k<MM;k++){
      float bb0 = sPan[k*17+jj0], bb1 = sPan[k*17+jj0+1];
      #pragma unroll
      for (int r=0;r<4;r++){
        float av = sA[(i0+r)*AP + k];
        acc8[r*2]   += av*bb0;
        acc8[r*2+1] += av*bb1;
      }
    }
    #pragma unroll
    for (int r=0;r<4;r++){
      sW[(i0+r)*WP + q0+jj0]   = acc8[r*2];
      sW[(i0+r)*WP + q0+jj0+1] = acc8[r*2+1];
    }
    __syncthreads();
  }

  // Phase 7: Q = P - T T^T -> bf16
  {
    float acc[8][8];
    #pragma unroll
    for (int i=0;i<8;i++)
      #pragma unroll
      for (int j=0;j<8;j++) acc[i][j]=0.f;
    for (int kt=0; kt<MM; kt+=16){
      for (int idx=tid; idx<MM*16; idx+=256){
        int kk = idx & 15, col = idx >> 4;
        sPan[kk*132 + col] = sW[col*WP + kt+kk];
      }
      __syncthreads();
      #pragma unroll
      for (int kk=0;kk<16;kk++){
        int k = kt+kk;
        float a[8];
        #pragma unroll
        for (int i=0;i<8;i++) a[i] = sW[(ty*8+i)*WP + k];
        float4 b0 = *(const float4*)&sPan[kk*132 + tx*8];
        float4 b1 = *(const float4*)&sPan[kk*132 + tx*8 + 4];
        float bq[8] = {b0.x,b0.y,b0.z,b0.w,b1.x,b1.y,b1.z,b1.w};
        #pragma unroll
        for (int i=0;i<8;i++)
          #pragma unroll
          for (int j=0;j<8;j++) acc[i][j] += a[i]*bq[j];
      }
      __syncthreads();
    }
    __nv_bfloat16* Qg = g_Qb + (size_t)ho*MM*MM;
    #pragma unroll
    for (int i=0;i<8;i++){
      float4 p0 = *(const float4*)&sA[(ty*8+i)*AP + tx*8];
      float4 p1 = *(const float4*)&sA[(ty*8+i)*AP + tx*8 + 4];
      float q[8] = {p0.x-acc[i][0], p0.y-acc[i][1], p0.z-acc[i][2], p0.w-acc[i][3],
                    p1.x-acc[i][4], p1.y-acc[i][5], p1.z-acc[i][6], p1.w-acc[i][7]};
      uint4 pk;
      pk.x = pack_bf16x2(q[0],q[1]); pk.y = pack_bf16x2(q[2],q[3]);
      pk.z = pack_bf16x2(q[4],q[5]); pk.w = pack_bf16x2(q[6],q[7]);
      *(uint4*)&Qg[(size_t)(ty*8+i)*MM + tx*8] = pk;
    }
  }
}

// ============ k_main: mma.sync bf16 ============
// smem byte layout
#define OFF_CS    0
#define OFF_X2    512
#define OFF_Z2    1024
#define OFF_PMU   1536
#define OFF_PVAR  2560
#define OFF_XS0   3584
#define OFF_ZS0   9728
#define OFF_XS1   15872
#define OFF_ZS1   22016
#define OFF_KUF   28160
#define OFF_Q     62976
#define SMEM_MAIN 97792
#define SPITCH    48      // staging pitch bytes (24 bf16)
#define KPITCH    272     // kuf/Q pitch bytes (136 bf16)

__global__ __launch_bounds__(256,2) void k_main(float* __restrict__ out){
  extern __shared__ char smc[];
  uint32_t sb = smem_u32(smc);
  float* cs  = (float*)(smc + OFF_CS);
  float* sx2 = (float*)(smc + OFF_X2);
  float* sz2 = (float*)(smc + OFF_Z2);
  float* pmu = (float*)(smc + OFF_PMU);
  float* pvar= (float*)(smc + OFF_PVAR);

  int ho = blockIdx.y;
  int h  = ho / NOUT;
  int b0 = blockIdx.x * MM;
  int tid = threadIdx.x;
  int wid = tid >> 5, lane = tid & 31;
  int wr = wid >> 1, wc = wid & 1;       // warp tile: rows wr*32, cols wc*64
  int l15 = lane & 15, lh = lane >> 4;
  int lane4 = lane >> 2, lpair = (lane & 3)*2;

  if (tid < MM){
    cs[tid]  = g_cv[ho*MM + tid];
    sz2[tid] = g_z2[ho*MM + tid];
    sx2[tid] = g_x2[h*B_SZ + b0 + tid];
  }

  const __nv_bfloat16* xb = g_xb + ((size_t)h*B_SZ + b0)*DIN;
  const __nv_bfloat16* zb = g_zb + (size_t)ho*MM*DIN;

  // staging addresses for this thread (one 16B chunk per array per k-chunk)
  int sr = tid >> 1, shalf = tid & 1;    // row 0..127, k-half 0/1
  uint32_t xs_dst[2], zs_dst[2];
  xs_dst[0] = sb + OFF_XS0 + sr*SPITCH + shalf*16;
  zs_dst[0] = sb + OFF_ZS0 + sr*SPITCH + shalf*16;
  xs_dst[1] = sb + OFF_XS1 + sr*SPITCH + shalf*16;
  zs_dst[1] = sb + OFF_ZS1 + sr*SPITCH + shalf*16;

  // prefetch chunk 0
  CP16(xs_dst[0], xb + (size_t)sr*DIN + shalf*8);
  CP16(zs_dst[0], zb + (size_t)sr*DIN + shalf*8);
  CP_COMMIT();

  float acc[16][4];
  #pragma unroll
  for (int i=0;i<16;i++)
    #pragma unroll
    for (int j=0;j<4;j++) acc[i][j]=0.f;

  // ---- Phase A: cross = x . z^T, K=256 in 16 chunks ----
  uint32_t aoffA = (wr*32 + l15)*SPITCH + lh*16;
  uint32_t boffA = (wc*64 + l15)*SPITCH + lh*16;
  #pragma unroll 1
  for (int c=0;c<16;c++){
    int cur = c & 1;
    if (c < 15){
      int nxt = cur ^ 1;
      int kg = (c+1)*16;
      CP16(xs_dst[nxt], xb + (size_t)sr*DIN + kg + shalf*8);
      CP16(zs_dst[nxt], zb + (size_t)sr*DIN + kg + shalf*8);
      CP_COMMIT();
      CP_WAIT(1);
    } else {
      CP_WAIT(0);
    }
    __syncthreads();
    uint32_t aB = sb + (cur ? OFF_XS1 : OFF_XS0) + aoffA;
    uint32_t bB = sb + (cur ? OFF_ZS1 : OFF_ZS0) + boffA;
    uint32_t af[2][4], bt[4], bfr[8][2];
    #pragma unroll
    for (int mt=0;mt<2;mt++) ldsm4(aB + mt*16*SPITCH, af[mt]);
    #pragma unroll
    for (int nn=0;nn<4;nn++){
      ldsm4(bB + nn*16*SPITCH, bt);
      bfr[nn*2][0]=bt[0]; bfr[nn*2][1]=bt[2];
      bfr[nn*2+1][0]=bt[1]; bfr[nn*2+1][1]=bt[3];
    }
    #pragma unroll
    for (int mt=0;mt<2;mt++)
      #pragma unroll
      for (int nf=0;nf<8;nf++)
        mma16816(acc[mt*8+nf], af[mt], bfr[nf]);
    __syncthreads();
  }

  // ---- stage Q tile [m'][m] bf16 pitch 136 ----
  {
    const __nv_bfloat16* Qg = g_Qb + (size_t)ho*MM*MM;
    #pragma unroll
    for (int it=0; it<8; it++){
      int t = tid + it*256;
      int r = t >> 4, cg = t & 15;
      uint4 v = *(const uint4*)(Qg + (size_t)r*MM + cg*8);
      *(uint4*)(smc + OFF_Q + r*KPITCH + cg*16) = v;
    }
  }

  // ---- epilogue A: kuf = sf2*exp(-.5 d2) -> bf16 smem; fused mu partials ----
  float sf2 = g_sf2v[h];
  {
    float mu_acc[4] = {0.f,0.f,0.f,0.f};
    #pragma unroll
    for (int mt=0;mt<2;mt++){
      int r0 = wr*32 + mt*16 + lane4;
      int r1 = r0 + 8;
      float x20 = sx2[r0], x21 = sx2[r1];
      #pragma unroll
      for (int nf=0;nf<8;nf++){
        int cb = wc*64 + nf*8 + lpair;
        float z20 = sz2[cb], z21 = sz2[cb+1];
        float* a4 = acc[mt*8+nf];
        float k00 = sf2*__expf(-0.5f*fmaxf(x20 + z20 - 2.f*a4[0], 0.f));
        float k01 = sf2*__expf(-0.5f*fmaxf(x20 + z21 - 2.f*a4[1], 0.f));
        float k10 = sf2*__expf(-0.5f*fmaxf(x21 + z20 - 2.f*a4[2], 0.f));
        float k11 = sf2*__expf(-0.5f*fmaxf(x21 + z21 - 2.f*a4[3], 0.f));
        *(uint32_t*)(smc + OFF_KUF + r0*KPITCH + cb*2) = pack_bf16x2(k00,k01);
        *(uint32_t*)(smc + OFF_KUF + r1*KPITCH + cb*2) = pack_bf16x2(k10,k11);
        float c0 = cs[cb], c1 = cs[cb+1];
        mu_acc[mt*2+0] += k00*c0 + k01*c1;
        mu_acc[mt*2+1] += k10*c0 + k11*c1;
      }
    }
    #pragma unroll
    for (int u=0;u<4;u++){
      float v = mu_acc[u];
      v += __shfl_xor_sync(0xffffffffu, v, 1);
      v += __shfl_xor_sync(0xffffffffu, v, 2);
      if ((lane & 3) == 0){
        int row = wr*32 + (u>>1)*16 + (u&1)*8 + lane4;
        pmu[wc*128 + row] = v;
      }
    }
  }
  __syncthreads();

  // ---- Phase B: y = kuf @ Q^T (Q symmetric), K=128 ----
  #pragma unroll
  for (int i=0;i<16;i++)
    #pragma unroll
    for (int j=0;j<4;j++) acc[i][j]=0.f;
  {
    uint32_t aB0 = sb + OFF_KUF + (wr*32 + l15)*KPITCH + lh*16;
    uint32_t bB0 = sb + OFF_Q   + (wc*64 + l15)*KPITCH + lh*16;
    #pragma unroll
    for (int ks=0;ks<8;ks++){
      uint32_t aB = aB0 + ks*32, bB = bB0 + ks*32;
      uint32_t af[2][4], bt[4], bfr[8][2];
      #pragma unroll
      for (int mt=0;mt<2;mt++) ldsm4(aB + mt*16*KPITCH, af[mt]);
      #pragma unroll
      for (int nn=0;nn<4;nn++){
        ldsm4(bB + nn*16*KPITCH, bt);
        bfr[nn*2][0]=bt[0]; bfr[nn*2][1]=bt[2];
        bfr[nn*2+1][0]=bt[1]; bfr[nn*2+1][1]=bt[3];
      }
      #pragma unroll
      for (int mt=0;mt<2;mt++)
        #pragma unroll
        for (int nf=0;nf<8;nf++)
          mma16816(acc[mt*8+nf], af[mt], bfr[nf]);
    }
  }

  // ---- epilogue B: var partials = sum kuf .* y ----
  {
    float v_acc[4] = {0.f,0.f,0.f,0.f};
    #pragma unroll
    for (int mt=0;mt<2;mt++){
      int r0 = wr*32 + mt*16 + lane4;
      int r1 = r0 + 8;
      #pragma unroll
      for (int nf=0;nf<8;nf++){
        int cb = wc*64 + nf*8 + lpair;
        uint32_t p0 = *(const uint32_t*)(smc + OFF_KUF + r0*KPITCH + cb*2);
        uint32_t p1 = *(const uint32_t*)(smc + OFF_KUF + r1*KPITCH + cb*2);
        __nv_bfloat162 h0 = *reinterpret_cast<__nv_bfloat162*>(&p0);
        __nv_bfloat162 h1 = *reinterpret_cast<__nv_bfloat162*>(&p1);
        float* a4 = acc[mt*8+nf];
        v_acc[mt*2+0] += __low2float(h0)*a4[0] + __high2float(h0)*a4[1];
        v_acc[mt*2+1] += __low2float(h1)*a4[2] + __high2float(h1)*a4[3];
      }
    }
    #pragma unroll
    for (int u=0;u<4;u++){
      float v = v_acc[u];
      v += __shfl_xor_sync(0xffffffffu, v, 1);
      v += __shfl_xor_sync(0xffffffffu, v, 2);
      if ((lane & 3) == 0){
        int row = wr*32 + (u>>1)*16 + (u&1)*8 + lane4;
        pvar[wc*128 + row] = v;
      }
    }
  }
  __syncthreads();

  if (tid < MM){
    size_t base = (size_t)ho*B_SZ + b0 + tid;
    out[base] = pmu[tid] + pmu[128+tid];
    out[(size_t)HOC*B_SZ + base] = sf2 - (pvar[tid] + pvar[128+tid]);
  }
}

// ---------------- launch ----------------
extern "C" void kernel_launch(void* const* d_in, const int* in_sizes, int n_in,
                              void* d_out, int out_size){
  const float* x      = (const float*)d_in[0];
  const float* z      = (const float*)d_in[1];
  const float* u_mean = (const float*)d_in[2];
  const float* u_tril = (const float*)d_in[3];
  const float* theta  = (const float*)d_in[4];
  float* out = (float*)d_out;

  cudaFuncSetAttribute(k_factor, cudaFuncAttributeMaxDynamicSharedMemorySize, FSM*4);
  cudaFuncSetAttribute(k_main,   cudaFuncAttributeMaxDynamicSharedMemorySize, SMEM_MAIN);

  k_hyper<<<1, 512>>>(theta);
  k_prep_x<<<NH*B_SZ, 256>>>(x);
  k_prep_z<<<HOC*MM, 256>>>(z);
  k_factor<<<HOC, 256, FSM*4>>>(u_mean, u_tril);
  k_main<<<dim3(B_SZ/MM, HOC), 256, SMEM_MAIN>>>(out);
}

// round 5
// speedup vs baseline: 8.9418x; 1.2383x over previous
#include <cuda_runtime.h>
#include <cuda_bf16.h>
#include <math.h>
#include <cstdint>

#define B_SZ  4096
#define DIN   256
#define NOUT  32
#define MM    128
#define NH    2
#define HOC   (NH*NOUT)
#define JIT   1e-4f
#define TRILN (MM*(MM+1)/2)
#define AP    132
#define WP    132

// ---------------- scratch ----------------
__device__ float g_scal[NH*DIN];
__device__ float g_sf2v[NH];
__device__ float g_x2[NH*B_SZ];
__device__ float g_z2[HOC*MM];
__device__ float g_cv[HOC*MM];
__device__ __align__(16) __nv_bfloat16 g_xb[NH*B_SZ*DIN];
__device__ __align__(16) __nv_bfloat16 g_zb[HOC*MM*DIN];
__device__ __align__(16) __nv_bfloat16 g_Qb[HOC*MM*MM];

// ---------------- helpers ----------------
__device__ __forceinline__ uint32_t smem_u32(const void* p){
  uint32_t a;
  asm("{ .reg .u64 t; cvta.to.shared.u64 t, %1; cvt.u32.u64 %0, t; }" : "=r"(a) : "l"(p));
  return a;
}
__device__ __forceinline__ void ldsm4(uint32_t addr, uint32_t* r){
  asm volatile("ldmatrix.sync.aligned.m8n8.x4.shared.b16 {%0,%1,%2,%3}, [%4];"
    : "=r"(r[0]),"=r"(r[1]),"=r"(r[2]),"=r"(r[3]) : "r"(addr));
}
__device__ __forceinline__ void mma16816(float* c, const uint32_t* a, const uint32_t* b){
  asm volatile("mma.sync.aligned.m16n8k16.row.col.f32.bf16.bf16.f32 "
    "{%0,%1,%2,%3}, {%4,%5,%6,%7}, {%8,%9}, {%0,%1,%2,%3};"
    : "+f"(c[0]),"+f"(c[1]),"+f"(c[2]),"+f"(c[3])
    : "r"(a[0]),"r"(a[1]),"r"(a[2]),"r"(a[3]), "r"(b[0]),"r"(b[1]));
}
#define CP16(dst, src) asm volatile("cp.async.cg.shared.global [%0], [%1], 16;" :: "r"(dst), "l"(src))
#define CP_COMMIT()    asm volatile("cp.async.commit_group;" ::: "memory")
#define CP_WAIT(n)     asm volatile("cp.async.wait_group %0;" :: "n"(n) : "memory")

__device__ __forceinline__ uint32_t pack_bf16x2(float lo, float hi){
  uint32_t r;
  asm("cvt.rn.satfinite.bf16x2.f32 %0, %1, %2;" : "=r"(r) : "f"(hi), "f"(lo));
  return r;
}

__device__ __forceinline__ float blockReduce256(float v){
  __shared__ float s[8];
  int lane = threadIdx.x & 31, w = threadIdx.x >> 5;
  #pragma unroll
  for (int o=16;o;o>>=1) v += __shfl_down_sync(0xffffffffu, v, o);
  if (lane==0) s[w] = v;
  __syncthreads();
  if (w==0){
    v = (lane < 8) ? s[lane] : 0.f;
    #pragma unroll
    for (int o=4;o;o>>=1) v += __shfl_down_sync(0xffffffffu, v, o);
  }
  return v;
}

// ---------------- hyper / prep ----------------
__global__ void k_hyper(const float* __restrict__ theta){
  int t = threadIdx.x;
  if (t < NH) g_sf2v[t] = expf(theta[t*(DIN+1)]);
  if (t < NH*DIN){
    int h = t / DIN, d = t % DIN;
    g_scal[t] = expf(-theta[h*(DIN+1)+1+d]);
  }
}
__global__ void k_prep_x(const float* __restrict__ x){
  int bid = blockIdx.x;  int h = bid / B_SZ, b = bid - h*B_SZ;
  int d = threadIdx.x;
  float v = x[(size_t)b*DIN + d] * g_scal[h*DIN + d];
  g_xb[(size_t)bid*DIN + d] = __float2bfloat16(v);
  float s = blockReduce256(v*v);
  if (threadIdx.x == 0) g_x2[bid] = s;
}
__global__ void k_prep_z(const float* __restrict__ z){
  int bid = blockIdx.x;
  int om = bid % (NOUT*MM);
  int d = threadIdx.x;
  int h = bid / (NOUT*MM);
  float v = z[(size_t)om*DIN + d] * g_scal[h*DIN + d];
  g_zb[(size_t)bid*DIN + d] = __float2bfloat16(v);
  float s = blockReduce256(v*v);
  if (threadIdx.x == 0) g_z2[bid] = s;
}

// ============ k_factor: tensor-core Kuu + fp32 chol/inv + tensor-core P/T/Q ============
// smem bytes:
#define F_SA   0           // fp32 128x132 (Kuu->L)          67584
#define F_SW   67584       // fp32 128x132 (W)               67584
#define F_ST0  135168      // stage buf0 (128x48B)           6144
#define F_ST1  141312      // stage buf1                     6144
#define F_UM   147456      // um[128] f32                    512
#define F_PC   147968      // pc[2][128] f32                 1024
#define F_TOT  148992
// bf16 tile buffers carved from fp32 regions once those are dead:
#define F_BUFA F_SA        // Wb -> Lsb -> Tb   (128x272B = 34816)
#define F_BUFB F_SW        // Pb               (34816)
#define SPITCH 48
#define KPITCH 272

__global__ __launch_bounds__(256) void k_factor(const float* __restrict__ u_mean,
                                                const float* __restrict__ u_tril){
  extern __shared__ char smc[];
  uint32_t sb = smem_u32(smc);
  float* sA   = (float*)(smc + F_SA);
  float* sW   = (float*)(smc + F_SW);
  float* sPan = (float*)(smc + F_ST0);   // 3072 floats scratch for inversion
  float* um   = (float*)(smc + F_UM);
  float* pc   = (float*)(smc + F_PC);

  int ho = blockIdx.x;
  int h = ho / NOUT, o = ho % NOUT;
  int tid = threadIdx.x;
  int wid = tid >> 5, lane = tid & 31;
  int wr = wid >> 1, wc = wid & 1;
  int l15 = lane & 15, lh = lane >> 4;
  int lane4 = lane >> 2, lpair = (lane & 3)*2;

  const __nv_bfloat16* zb = g_zb + (size_t)ho*MM*DIN;

  if (tid < MM) um[tid] = u_mean[o*MM + tid];

  // ---- Phase 1: Kuu via bf16 mma (K=256, A=B=z tile) ----
  {
    int sr = tid >> 1, shalf = tid & 1;
    uint32_t st_dst[2] = { sb + F_ST0 + sr*SPITCH + shalf*16,
                           sb + F_ST1 + sr*SPITCH + shalf*16 };
    CP16(st_dst[0], zb + (size_t)sr*DIN + shalf*8);
    CP_COMMIT();

    float acc[16][4];
    #pragma unroll
    for (int i=0;i<16;i++)
      #pragma unroll
      for (int j=0;j<4;j++) acc[i][j]=0.f;

    uint32_t aoff = (wr*32 + l15)*SPITCH + lh*16;
    uint32_t boff = (wc*64 + l15)*SPITCH + lh*16;
    #pragma unroll 1
    for (int c=0;c<16;c++){
      int cur = c & 1;
      if (c < 15){
        CP16(st_dst[cur^1], zb + (size_t)sr*DIN + (c+1)*16 + shalf*8);
        CP_COMMIT();
        CP_WAIT(1);
      } else {
        CP_WAIT(0);
      }
      __syncthreads();
      uint32_t base = sb + (cur ? F_ST1 : F_ST0);
      uint32_t af[2][4], bt[4], bfr[8][2];
      #pragma unroll
      for (int mt=0;mt<2;mt++) ldsm4(base + aoff + mt*16*SPITCH, af[mt]);
      #pragma unroll
      for (int nn=0;nn<4;nn++){
        ldsm4(base + boff + nn*16*SPITCH, bt);
        bfr[nn*2][0]=bt[0]; bfr[nn*2][1]=bt[2];
        bfr[nn*2+1][0]=bt[1]; bfr[nn*2+1][1]=bt[3];
      }
      #pragma unroll
      for (int mt=0;mt<2;mt++)
        #pragma unroll
        for (int nf=0;nf<8;nf++)
          mma16816(acc[mt*8+nf], af[mt], bfr[nf]);
      __syncthreads();
    }

    float sf2 = g_sf2v[h];
    #pragma unroll
    for (int mt=0;mt<2;mt++){
      int r0 = wr*32 + mt*16 + lane4;
      int r1 = r0 + 8;
      float z20 = g_z2[ho*MM+r0], z21 = g_z2[ho*MM+r1];
      #pragma unroll
      for (int nf=0;nf<8;nf++){
        int cb = wc*64 + nf*8 + lpair;
        float zc0 = g_z2[ho*MM+cb], zc1 = g_z2[ho*MM+cb+1];
        float* a4 = acc[mt*8+nf];
        float v00 = (r0==cb  ) ? sf2+JIT : sf2*__expf(-0.5f*fmaxf(z20+zc0-2.f*a4[0],0.f));
        float v01 = (r0==cb+1) ? sf2+JIT : sf2*__expf(-0.5f*fmaxf(z20+zc1-2.f*a4[1],0.f));
        float v10 = (r1==cb  ) ? sf2+JIT : sf2*__expf(-0.5f*fmaxf(z21+zc0-2.f*a4[2],0.f));
        float v11 = (r1==cb+1) ? sf2+JIT : sf2*__expf(-0.5f*fmaxf(z21+zc1-2.f*a4[3],0.f));
        sA[r0*AP+cb] = v00; sA[r0*AP+cb+1] = v01;
        sA[r1*AP+cb] = v10; sA[r1*AP+cb+1] = v11;
      }
    }
  }
  __syncthreads();

  // zero sW (upper triangle of W must be 0)
  for (int idx=tid; idx<MM*WP; idx+=256) sW[idx] = 0.f;
  __syncthreads();

  // ---- Phase 2: blocked Cholesky (fp32, in-place in sA) ----
  for (int p=0;p<8;p++){
    int k0 = 16*p;
    if (tid < 32){
      #pragma unroll 1
      for (int t=0;t<16;t++){
        int k = k0+t;
        float dk = sA[k*AP+k];
        float inv = rsqrtf(dk);
        __syncwarp();
        if (tid == 0) sA[k*AP+k] = dk*inv;
        if (tid > t && tid < 16) sA[(k0+tid)*AP + k] *= inv;
        __syncwarp();
        if (tid > t && tid < 16){
          int i = k0+tid;
          float lik = sA[i*AP+k];
          for (int j=k+1;j<=i;j++) sA[i*AP+j] -= lik * sA[j*AP+k];
        }
        __syncwarp();
      }
    }
    __syncthreads();
    int R = 112 - 16*p;
    if (R > 0){
      if (tid < R){
        int i = k0+16+tid;
        float v[16];
        #pragma unroll
        for (int t=0;t<16;t++) v[t] = sA[i*AP + k0 + t];
        #pragma unroll
        for (int t=0;t<16;t++){
          #pragma unroll
          for (int s=0;s<16;s++) if (s<t) v[t] -= v[s]*sA[(k0+t)*AP + k0+s];
          v[t] /= sA[(k0+t)*AP + k0+t];
        }
        #pragma unroll
        for (int t=0;t<16;t++) sA[i*AP + k0+t] = v[t];
      }
      __syncthreads();
      int rt = R >> 2;
      int nt = rt*rt;
      for (int tile = tid; tile < nt; tile += 256){
        int tr = tile / rt, tc = tile % rt;
        int i0 = k0+16+4*tr, j0 = k0+16+4*tc;
        float accu[16];
        #pragma unroll
        for (int u=0;u<16;u++) accu[u]=0.f;
        #pragma unroll
        for (int t=0;t<16;t++){
          float a4[4], b4[4];
          #pragma unroll
          for (int r=0;r<4;r++) a4[r] = sA[(i0+r)*AP + k0+t];
          #pragma unroll
          for (int c=0;c<4;c++) b4[c] = sA[(j0+c)*AP + k0+t];
          #pragma unroll
          for (int r=0;r<4;r++)
            #pragma unroll
            for (int c=0;c<4;c++) accu[r*4+c] += a4[r]*b4[c];
        }
        #pragma unroll
        for (int r=0;r<4;r++)
          #pragma unroll
          for (int c=0;c<4;c++) sA[(i0+r)*AP + j0+c] -= accu[r*4+c];
      }
      __syncthreads();
    }
  }

  // ---- Phase 3: W = L^{-1} (fp32 blocked) ----
  if (tid < 128){
    int p = tid >> 4, jl = tid & 15, k0 = p*16;
    float w[16];
    #pragma unroll
    for (int u=0;u<16;u++) w[u]=0.f;
    #pragma unroll
    for (int u=0;u<16;u++){
      if (u == jl){
        w[u] = 1.0f / sA[(k0+u)*AP + k0+u];
      } else if (u > jl){
        float s = 0.f;
        #pragma unroll
        for (int k=0;k<15;k++)
          if (k >= jl && k < u) s += sA[(k0+u)*AP + k0+k] * w[k];
        w[u] = -s / sA[(k0+u)*AP + k0+u];
      }
    }
    #pragma unroll
    for (int u=0;u<16;u++) if (u >= jl) sW[(k0+u)*WP + k0+jl] = w[u];
  }
  __syncthreads();
  for (int s=1;s<8;s++){
    int total = (8-s) << 8;
    for (int idx=tid; idx<total; idx+=256){
      int q = idx >> 8, rc = idx & 255, r = rc >> 4, c = rc & 15;
      int irow = (q+s)*16 + r, q0 = q*16;
      float acc = 0.f;
      for (int k=16*q; k<16*(q+s); k++) acc += sA[irow*AP+k] * sW[k*WP + q0+c];
      sPan[idx] = acc;
    }
    __syncthreads();
    for (int idx=tid; idx<total; idx+=256){
      int q = idx >> 8, rc = idx & 255, r = rc >> 4, c = rc & 15;
      int i0 = (q+s)*16, q0 = q*16;
      float acc = 0.f;
      for (int u=0; u<=r; u++) acc += sW[(i0+r)*WP + i0+u] * sPan[(q<<8) + u*16 + c];
      sW[(i0+r)*WP + q0 + c] = -acc;
    }
    __syncthreads();
  }

  // ---- Phase 4: Wb[i][k] = bf16(W[k][i]) into BufA (L in sA is dead) ----
  {
    // idx -> (i = idx&127, kp = idx>>7), pack k=2kp,2kp+1
    for (int it=0; it<32; it++){
      int idx = tid + it*256;
      int i = idx & 127, kp = idx >> 7;
      float w0 = sW[(2*kp)*WP + i];
      float w1 = sW[(2*kp+1)*WP + i];
      *(uint32_t*)(smc + F_BUFA + i*KPITCH + kp*4) = pack_bf16x2(w0, w1);
    }
  }
  __syncthreads();

  // ---- Phase 5: P = Wb @ Wb^T (mma), fused c = P um; store Pb -> BufB ----
  {
    float acc[16][4];
    #pragma unroll
    for (int i=0;i<16;i++)
      #pragma unroll
      for (int j=0;j<4;j++) acc[i][j]=0.f;
    uint32_t aB0 = sb + F_BUFA + (wr*32 + l15)*KPITCH + lh*16;
    uint32_t bB0 = sb + F_BUFA + (wc*64 + l15)*KPITCH + lh*16;
    #pragma unroll
    for (int ks=0;ks<8;ks++){
      uint32_t af[2][4], bt[4], bfr[8][2];
      #pragma unroll
      for (int mt=0;mt<2;mt++) ldsm4(aB0 + ks*32 + mt*16*KPITCH, af[mt]);
      #pragma unroll
      for (int nn=0;nn<4;nn++){
        ldsm4(bB0 + ks*32 + nn*16*KPITCH, bt);
        bfr[nn*2][0]=bt[0]; bfr[nn*2][1]=bt[2];
        bfr[nn*2+1][0]=bt[1]; bfr[nn*2+1][1]=bt[3];
      }
      #pragma unroll
      for (int mt=0;mt<2;mt++)
        #pragma unroll
        for (int nf=0;nf<8;nf++)
          mma16816(acc[mt*8+nf], af[mt], bfr[nf]);
    }
    __syncthreads();   // all reads of Wb(BufA)/need BufB(W fp32) dead before overwrite
    float c_acc[4] = {0.f,0.f,0.f,0.f};
    #pragma unroll
    for (int mt=0;mt<2;mt++){
      int r0 = wr*32 + mt*16 + lane4;
      int r1 = r0 + 8;
      #pragma unroll
      for (int nf=0;nf<8;nf++){
        int cb = wc*64 + nf*8 + lpair;
        float* a4 = acc[mt*8+nf];
        *(uint32_t*)(smc + F_BUFB + r0*KPITCH + cb*2) = pack_bf16x2(a4[0],a4[1]);
        *(uint32_t*)(smc + F_BUFB + r1*KPITCH + cb*2) = pack_bf16x2(a4[2],a4[3]);
        float u0 = um[cb], u1 = um[cb+1];
        c_acc[mt*2+0] += a4[0]*u0 + a4[1]*u1;
        c_acc[mt*2+1] += a4[2]*u0 + a4[3]*u1;
      }
    }
    #pragma unroll
    for (int u=0;u<4;u++){
      float v = c_acc[u];
      v += __shfl_xor_sync(0xffffffffu, v, 1);
      v += __shfl_xor_sync(0xffffffffu, v, 2);
      if ((lane & 3) == 0){
        int row = wr*32 + (u>>1)*16 + (u&1)*8 + lane4;
        pc[wc*128 + row] = v;
      }
    }
  }
  __syncthreads();
  if (tid < MM) g_cv[ho*MM + tid] = pc[tid] + pc[128+tid];

  // ---- Phase 6: Lsb[j][k] = Ls[k][j] (k>=j) into BufA (Wb dead) ----
  {
    const float* Lv = u_tril + (size_t)o*TRILN;
    for (int it=0; it<32; it++){
      int idx = tid + it*256;
      int j = idx & 127, kp = (idx >> 7)*2;
      float v0 = (kp   >= j) ? Lv[(kp*(kp+1))/2 + j] : 0.f;
      float v1 = (kp+1 >= j) ? Lv[((kp+1)*(kp+2))/2 + j] : 0.f;
      *(uint32_t*)(smc + F_BUFA + j*KPITCH + kp*2) = pack_bf16x2(v0, v1);
    }
  }
  __syncthreads();

  // ---- Phase 7: T = Pb @ Lsb^T (mma); Tb -> BufA (overwrite Lsb after sync) ----
  {
    float acc[16][4];
    #pragma unroll
    for (int i=0;i<16;i++)
      #pragma unroll
      for (int j=0;j<4;j++) acc[i][j]=0.f;
    uint32_t aB0 = sb + F_BUFB + (wr*32 + l15)*KPITCH + lh*16;
    uint32_t bB0 = sb + F_BUFA + (wc*64 + l15)*KPITCH + lh*16;
    #pragma unroll
    for (int ks=0;ks<8;ks++){
      uint32_t af[2][4], bt[4], bfr[8][2];
      #pragma unroll
      for (int mt=0;mt<2;mt++) ldsm4(aB0 + ks*32 + mt*16*KPITCH, af[mt]);
      #pragma unroll
      for (int nn=0;nn<4;nn++){
        ldsm4(bB0 + ks*32 + nn*16*KPITCH, bt);
        bfr[nn*2][0]=bt[0]; bfr[nn*2][1]=bt[2];
        bfr[nn*2+1][0]=bt[1]; bfr[nn*2+1][1]=bt[3];
      }
      #pragma unroll
      for (int mt=0;mt<2;mt++)
        #pragma unroll
        for (int nf=0;nf<8;nf++)
          mma16816(acc[mt*8+nf], af[mt], bfr[nf]);
    }
    __syncthreads();   // everyone done reading Lsb before Tb overwrites BufA
    #pragma unroll
    for (int mt=0;mt<2;mt++){
      int r0 = wr*32 + mt*16 + lane4;
      int r1 = r0 + 8;
      #pragma unroll
      for (int nf=0;nf<8;nf++){
        int cb = wc*64 + nf*8 + lpair;
        float* a4 = acc[mt*8+nf];
        *(uint32_t*)(smc + F_BUFA + r0*KPITCH + cb*2) = pack_bf16x2(a4[0],a4[1]);
        *(uint32_t*)(smc + F_BUFA + r1*KPITCH + cb*2) = pack_bf16x2(a4[2],a4[3]);
      }
    }
  }
  __syncthreads();

  // ---- Phase 8: Q = Pb - Tb @ Tb^T (mma) -> g_Qb bf16 ----
  {
    float acc[16][4];
    #pragma unroll
    for (int i=0;i<16;i++)
      #pragma unroll
      for (int j=0;j<4;j++) acc[i][j]=0.f;
    uint32_t aB0 = sb + F_BUFA + (wr*32 + l15)*KPITCH + lh*16;
    uint32_t bB0 = sb + F_BUFA + (wc*64 + l15)*KPITCH + lh*16;
    #pragma unroll
    for (int ks=0;ks<8;ks++){
      uint32_t af[2][4], bt[4], bfr[8][2];
      #pragma unroll
      for (int mt=0;mt<2;mt++) ldsm4(aB0 + ks*32 + mt*16*KPITCH, af[mt]);
      #pragma unroll
      for (int nn=0;nn<4;nn++){
        ldsm4(bB0 + ks*32 + nn*16*KPITCH, bt);
        bfr[nn*2][0]=bt[0]; bfr[nn*2][1]=bt[2];
        bfr[nn*2+1][0]=bt[1]; bfr[nn*2+1][1]=bt[3];
      }
      #pragma unroll
      for (int mt=0;mt<2;mt++)
        #pragma unroll
        for (int nf=0;nf<8;nf++)
          mma16816(acc[mt*8+nf], af[mt], bfr[nf]);
    }
    __nv_bfloat16* Qg = g_Qb + (size_t)ho*MM*MM;
    #pragma unroll
    for (int mt=0;mt<2;mt++){
      int r0 = wr*32 + mt*16 + lane4;
      int r1 = r0 + 8;
      #pragma unroll
      for (int nf=0;nf<8;nf++){
        int cb = wc*64 + nf*8 + lpair;
        uint32_t p0 = *(const uint32_t*)(smc + F_BUFB + r0*KPITCH + cb*2);
        uint32_t p1 = *(const uint32_t*)(smc + F_BUFB + r1*KPITCH + cb*2);
        __nv_bfloat162 h0 = *reinterpret_cast<__nv_bfloat162*>(&p0);
        __nv_bfloat162 h1 = *reinterpret_cast<__nv_bfloat162*>(&p1);
        float* a4 = acc[mt*8+nf];
        *(uint32_t*)&Qg[(size_t)r0*MM + cb] = pack_bf16x2(__low2float(h0)-a4[0], __high2float(h0)-a4[1]);
        *(uint32_t*)&Qg[(size_t)r1*MM + cb] = pack_bf16x2(__low2float(h1)-a4[2], __high2float(h1)-a4[3]);
      }
    }
  }
}

// ============ k_main: mma.sync bf16 (unchanged from R4) ============
#define OFF_CS    0
#define OFF_X2    512
#define OFF_Z2    1024
#define OFF_PMU   1536
#define OFF_PVAR  2560
#define OFF_XS0   3584
#define OFF_ZS0   9728
#define OFF_XS1   15872
#define OFF_ZS1   22016
#define OFF_KUF   28160
#define OFF_Q     62976
#define SMEM_MAIN 97792

__global__ __launch_bounds__(256,2) void k_main(float* __restrict__ out){
  extern __shared__ char smc[];
  uint32_t sb = smem_u32(smc);
  float* cs  = (float*)(smc + OFF_CS);
  float* sx2 = (float*)(smc + OFF_X2);
  float* sz2 = (float*)(smc + OFF_Z2);
  float* pmu = (float*)(smc + OFF_PMU);
  float* pvar= (float*)(smc + OFF_PVAR);

  int ho = blockIdx.y;
  int h  = ho / NOUT;
  int b0 = blockIdx.x * MM;
  int tid = threadIdx.x;
  int wid = tid >> 5, lane = tid & 31;
  int wr = wid >> 1, wc = wid & 1;
  int l15 = lane & 15, lh = lane >> 4;
  int lane4 = lane >> 2, lpair = (lane & 3)*2;

  if (tid < MM){
    cs[tid]  = g_cv[ho*MM + tid];
    sz2[tid] = g_z2[ho*MM + tid];
    sx2[tid] = g_x2[h*B_SZ + b0 + tid];
  }

  const __nv_bfloat16* xb = g_xb + ((size_t)h*B_SZ + b0)*DIN;
  const __nv_bfloat16* zb = g_zb + (size_t)ho*MM*DIN;

  int sr = tid >> 1, shalf = tid & 1;
  uint32_t xs_dst[2], zs_dst[2];
  xs_dst[0] = sb + OFF_XS0 + sr*SPITCH + shalf*16;
  zs_dst[0] = sb + OFF_ZS0 + sr*SPITCH + shalf*16;
  xs_dst[1] = sb + OFF_XS1 + sr*SPITCH + shalf*16;
  zs_dst[1] = sb + OFF_ZS1 + sr*SPITCH + shalf*16;

  CP16(xs_dst[0], xb + (size_t)sr*DIN + shalf*8);
  CP16(zs_dst[0], zb + (size_t)sr*DIN + shalf*8);
  CP_COMMIT();

  float acc[16][4];
  #pragma unroll
  for (int i=0;i<16;i++)
    #pragma unroll
    for (int j=0;j<4;j++) acc[i][j]=0.f;

  uint32_t aoffA = (wr*32 + l15)*SPITCH + lh*16;
  uint32_t boffA = (wc*64 + l15)*SPITCH + lh*16;
  #pragma unroll 1
  for (int c=0;c<16;c++){
    int cur = c & 1;
    if (c < 15){
      int nxt = cur ^ 1;
      int kg = (c+1)*16;
      CP16(xs_dst[nxt], xb + (size_t)sr*DIN + kg + shalf*8);
      CP16(zs_dst[nxt], zb + (size_t)sr*DIN + kg + shalf*8);
      CP_COMMIT();
      CP_WAIT(1);
    } else {
      CP_WAIT(0);
    }
    __syncthreads();
    uint32_t aB = sb + (cur ? OFF_XS1 : OFF_XS0) + aoffA;
    uint32_t bB = sb + (cur ? OFF_ZS1 : OFF_ZS0) + boffA;
    uint32_t af[2][4], bt[4], bfr[8][2];
    #pragma unroll
    for (int mt=0;mt<2;mt++) ldsm4(aB + mt*16*SPITCH, af[mt]);
    #pragma unroll
    for (int nn=0;nn<4;nn++){
      ldsm4(bB + nn*16*SPITCH, bt);
      bfr[nn*2][0]=bt[0]; bfr[nn*2][1]=bt[2];
      bfr[nn*2+1][0]=bt[1]; bfr[nn*2+1][1]=bt[3];
    }
    #pragma unroll
    for (int mt=0;mt<2;mt++)
      #pragma unroll
      for (int nf=0;nf<8;nf++)
        mma16816(acc[mt*8+nf], af[mt], bfr[nf]);
    __syncthreads();
  }

  {
    const __nv_bfloat16* Qg = g_Qb + (size_t)ho*MM*MM;
    #pragma unroll
    for (int it=0; it<8; it++){
      int t = tid + it*256;
      int r = t >> 4, cg = t & 15;
      uint4 v = *(const uint4*)(Qg + (size_t)r*MM + cg*8);
      *(uint4*)(smc + OFF_Q + r*KPITCH + cg*16) = v;
    }
  }

  float sf2 = g_sf2v[h];
  {
    float mu_acc[4] = {0.f,0.f,0.f,0.f};
    #pragma unroll
    for (int mt=0;mt<2;mt++){
      int r0 = wr*32 + mt*16 + lane4;
      int r1 = r0 + 8;
      float x20 = sx2[r0], x21 = sx2[r1];
      #pragma unroll
      for (int nf=0;nf<8;nf++){
        int cb = wc*64 + nf*8 + lpair;
        float z20 = sz2[cb], z21 = sz2[cb+1];
        float* a4 = acc[mt*8+nf];
        float k00 = sf2*__expf(-0.5f*fmaxf(x20 + z20 - 2.f*a4[0], 0.f));
        float k01 = sf2*__expf(-0.5f*fmaxf(x20 + z21 - 2.f*a4[1], 0.f));
        float k10 = sf2*__expf(-0.5f*fmaxf(x21 + z20 - 2.f*a4[2], 0.f));
        float k11 = sf2*__expf(-0.5f*fmaxf(x21 + z21 - 2.f*a4[3], 0.f));
        *(uint32_t*)(smc + OFF_KUF + r0*KPITCH + cb*2) = pack_bf16x2(k00,k01);
        *(uint32_t*)(smc + OFF_KUF + r1*KPITCH + cb*2) = pack_bf16x2(k10,k11);
        float c0 = cs[cb], c1 = cs[cb+1];
        mu_acc[mt*2+0] += k00*c0 + k01*c1;
        mu_acc[mt*2+1] += k10*c0 + k11*c1;
      }
    }
    #pragma unroll
    for (int u=0;u<4;u++){
      float v = mu_acc[u];
      v += __shfl_xor_sync(0xffffffffu, v, 1);
      v += __shfl_xor_sync(0xffffffffu, v, 2);
      if ((lane & 3) == 0){
        int row = wr*32 + (u>>1)*16 + (u&1)*8 + lane4;
        pmu[wc*128 + row] = v;
      }
    }
  }
  __syncthreads();

  #pragma unroll
  for (int i=0;i<16;i++)
    #pragma unroll
    for (int j=0;j<4;j++) acc[i][j]=0.f;
  {
    uint32_t aB0 = sb + OFF_KUF + (wr*32 + l15)*KPITCH + lh*16;
    uint32_t bB0 = sb + OFF_Q   + (wc*64 + l15)*KPITCH + lh*16;
    #pragma unroll
    for (int ks=0;ks<8;ks++){
      uint32_t aB = aB0 + ks*32, bB = bB0 + ks*32;
      uint32_t af[2][4], bt[4], bfr[8][2];
      #pragma unroll
      for (int mt=0;mt<2;mt++) ldsm4(aB + mt*16*KPITCH, af[mt]);
      #pragma unroll
      for (int nn=0;nn<4;nn++){
        ldsm4(bB + nn*16*KPITCH, bt);
        bfr[nn*2][0]=bt[0]; bfr[nn*2][1]=bt[2];
        bfr[nn*2+1][0]=bt[1]; bfr[nn*2+1][1]=bt[3];
      }
      #pragma unroll
      for (int mt=0;mt<2;mt++)
        #pragma unroll
        for (int nf=0;nf<8;nf++)
          mma16816(acc[mt*8+nf], af[mt], bfr[nf]);
    }
  }

  {
    float v_acc[4] = {0.f,0.f,0.f,0.f};
    #pragma unroll
    for (int mt=0;mt<2;mt++){
      int r0 = wr*32 + mt*16 + lane4;
      int r1 = r0 + 8;
      #pragma unroll
      for (int nf=0;nf<8;nf++){
        int cb = wc*64 + nf*8 + lpair;
        uint32_t p0 = *(const uint32_t*)(smc + OFF_KUF + r0*KPITCH + cb*2);
        uint32_t p1 = *(const uint32_t*)(smc + OFF_KUF + r1*KPITCH + cb*2);
        __nv_bfloat162 h0 = *reinterpret_cast<__nv_bfloat162*>(&p0);
        __nv_bfloat162 h1 = *reinterpret_cast<__nv_bfloat162*>(&p1);
        float* a4 = acc[mt*8+nf];
        v_acc[mt*2+0] += __low2float(h0)*a4[0] + __high2float(h0)*a4[1];
        v_acc[mt*2+1] += __low2float(h1)*a4[2] + __high2float(h1)*a4[3];
      }
    }
    #pragma unroll
    for (int u=0;u<4;u++){
      float v = v_acc[u];
      v += __shfl_xor_sync(0xffffffffu, v, 1);
      v += __shfl_xor_sync(0xffffffffu, v, 2);
      if ((lane & 3) == 0){
        int row = wr*32 + (u>>1)*16 + (u&1)*8 + lane4;
        pvar[wc*128 + row] = v;
      }
    }
  }
  __syncthreads();

  if (tid < MM){
    size_t base = (size_t)ho*B_SZ + b0 + tid;
    out[base] = pmu[tid] + pmu[128+tid];
    out[(size_t)HOC*B_SZ + base] = sf2 - (pvar[tid] + pvar[128+tid]);
  }
}

// ---------------- launch ----------------
extern "C" void kernel_launch(void* const* d_in, const int* in_sizes, int n_in,
                              void* d_out, int out_size){
  const float* x      = (const float*)d_in[0];
  const float* z      = (const float*)d_in[1];
  const float* u_mean = (const float*)d_in[2];
  const float* u_tril = (const float*)d_in[3];
  const float* theta  = (const float*)d_in[4];
  float* out = (float*)d_out;

  cudaFuncSetAttribute(k_factor, cudaFuncAttributeMaxDynamicSharedMemorySize, F_TOT);
  cudaFuncSetAttribute(k_main,   cudaFuncAttributeMaxDynamicSharedMemorySize, SMEM_MAIN);

  k_hyper<<<1, 512>>>(theta);
  k_prep_x<<<NH*B_SZ, 256>>>(x);
  k_prep_z<<<HOC*MM, 256>>>(z);
  k_factor<<<HOC, 256, F_TOT>>>(u_mean, u_tril);
  k_main<<<dim3(B_SZ/MM, HOC), 256, SMEM_MAIN>>>(out);
}

// round 6
// speedup vs baseline: 9.1742x; 1.0260x over previous
#include <cuda_runtime.h>
#include <cuda_bf16.h>
#include <math.h>
#include <cstdint>

#define B_SZ  4096
#define DIN   256
#define NOUT  32
#define MM    128
#define NH    2
#define HOC   (NH*NOUT)
#define JIT   1e-4f
#define TRILN (MM*(MM+1)/2)

// ---------------- scratch ----------------
__device__ float g_scal[NH*DIN];
__device__ float g_sf2v[NH];
__device__ float g_x2[NH*B_SZ];
__device__ float g_z2[HOC*MM];
__device__ float g_cv[HOC*MM];
__device__ __align__(16) __nv_bfloat16 g_xb[NH*B_SZ*DIN];
__device__ __align__(16) __nv_bfloat16 g_zb[HOC*MM*DIN];
__device__ __align__(16) __nv_bfloat16 g_Qb[HOC*MM*MM];

// ---------------- helpers ----------------
__device__ __forceinline__ uint32_t smem_u32(const void* p){
  uint32_t a;
  asm("{ .reg .u64 t; cvta.to.shared.u64 t, %1; cvt.u32.u64 %0, t; }" : "=r"(a) : "l"(p));
  return a;
}
__device__ __forceinline__ void ldsm4(uint32_t addr, uint32_t* r){
  asm volatile("ldmatrix.sync.aligned.m8n8.x4.shared.b16 {%0,%1,%2,%3}, [%4];"
    : "=r"(r[0]),"=r"(r[1]),"=r"(r[2]),"=r"(r[3]) : "r"(addr));
}
__device__ __forceinline__ void mma16816(float* c, const uint32_t* a, const uint32_t* b){
  asm volatile("mma.sync.aligned.m16n8k16.row.col.f32.bf16.bf16.f32 "
    "{%0,%1,%2,%3}, {%4,%5,%6,%7}, {%8,%9}, {%0,%1,%2,%3};"
    : "+f"(c[0]),"+f"(c[1]),"+f"(c[2]),"+f"(c[3])
    : "r"(a[0]),"r"(a[1]),"r"(a[2]),"r"(a[3]), "r"(b[0]),"r"(b[1]));
}
#define CP16(dst, src) asm volatile("cp.async.cg.shared.global [%0], [%1], 16;" :: "r"(dst), "l"(src))
#define CP_COMMIT()    asm volatile("cp.async.commit_group;" ::: "memory")
#define CP_WAIT(n)     asm volatile("cp.async.wait_group %0;" :: "n"(n) : "memory")

__device__ __forceinline__ uint32_t pack_bf16x2(float lo, float hi){
  uint32_t r;
  asm("cvt.rn.satfinite.bf16x2.f32 %0, %1, %2;" : "=r"(r) : "f"(hi), "f"(lo));
  return r;
}

__device__ __forceinline__ float blockReduce256(float v){
  __shared__ float s[8];
  int lane = threadIdx.x & 31, w = threadIdx.x >> 5;
  #pragma unroll
  for (int o=16;o;o>>=1) v += __shfl_down_sync(0xffffffffu, v, o);
  if (lane==0) s[w] = v;
  __syncthreads();
  if (w==0){
    v = (lane < 8) ? s[lane] : 0.f;
    #pragma unroll
    for (int o=4;o;o>>=1) v += __shfl_down_sync(0xffffffffu, v, o);
  }
  return v;
}

#define SPITCH 48
#define KPITCH 272

// 128x128x128 bf16 block GEMM: acc += A(row-major tile at aBase) * B(row-major tile at bBase)^T
__device__ __forceinline__ void mm128(uint32_t aBase, uint32_t bBase,
                                      int wr, int wc, int l15, int lh,
                                      float acc[16][4]){
  uint32_t aB0 = aBase + (wr*32 + l15)*KPITCH + lh*16;
  uint32_t bB0 = bBase + (wc*64 + l15)*KPITCH + lh*16;
  #pragma unroll
  for (int ks=0;ks<8;ks++){
    uint32_t af[2][4], bt[4], bfr[8][2];
    #pragma unroll
    for (int mt=0;mt<2;mt++) ldsm4(aB0 + ks*32 + mt*16*KPITCH, af[mt]);
    #pragma unroll
    for (int nn=0;nn<4;nn++){
      ldsm4(bB0 + ks*32 + nn*16*KPITCH, bt);
      bfr[nn*2][0]=bt[0]; bfr[nn*2][1]=bt[2];
      bfr[nn*2+1][0]=bt[1]; bfr[nn*2+1][1]=bt[3];
    }
    #pragma unroll
    for (int mt=0;mt<2;mt++)
      #pragma unroll
      for (int nf=0;nf<8;nf++)
        mma16816(acc[mt*8+nf], af[mt], bfr[nf]);
  }
}

// ---------------- hyper / prep ----------------
__global__ void k_hyper(const float* __restrict__ theta){
  int t = threadIdx.x;
  if (t < NH) g_sf2v[t] = expf(theta[t*(DIN+1)]);
  if (t < NH*DIN){
    int h = t / DIN, d = t % DIN;
    g_scal[t] = expf(-theta[h*(DIN+1)+1+d]);
  }
}
__global__ void k_prep_x(const float* __restrict__ x){
  int bid = blockIdx.x;  int h = bid / B_SZ, b = bid - h*B_SZ;
  int d = threadIdx.x;
  float v = x[(size_t)b*DIN + d] * g_scal[h*DIN + d];
  g_xb[(size_t)bid*DIN + d] = __float2bfloat16(v);
  float s = blockReduce256(v*v);
  if (threadIdx.x == 0) g_x2[bid] = s;
}
__global__ void k_prep_z(const float* __restrict__ z){
  int bid = blockIdx.x;
  int om = bid % (NOUT*MM);
  int d = threadIdx.x;
  int h = bid / (NOUT*MM);
  float v = z[(size_t)om*DIN + d] * g_scal[h*DIN + d];
  g_zb[(size_t)bid*DIN + d] = __float2bfloat16(v);
  float s = blockReduce256(v*v);
  if (threadIdx.x == 0) g_z2[bid] = s;
}

// ============ k_factor: Kuu (mma) -> Newton-Schulz P (mma) -> T,Q,c (mma) ============
// smem bytes:
#define N_KB   0        // Kb bf16 128x272      34816  (later: Lsb)
#define N_XB   34816    // Xb (P iterate)       34816
#define N_YB   69632    // Yb / Tb              34816  (staging bufs live here first)
#define N_ST0  69632    // stage buf0 6144
#define N_ST1  75776    // stage buf1 6144
#define N_UM   104448   // um[128] f32          512
#define N_PC   104960   // pc[2][128] f32       1024
#define N_TOT  105984

__global__ __launch_bounds__(256) void k_factor(const float* __restrict__ u_mean,
                                                const float* __restrict__ u_tril){
  extern __shared__ char smc[];
  uint32_t sb = smem_u32(smc);
  float* um = (float*)(smc + N_UM);
  float* pc = (float*)(smc + N_PC);

  int ho = blockIdx.x;
  int h = ho / NOUT, o = ho % NOUT;
  int tid = threadIdx.x;
  int wid = tid >> 5, lane = tid & 31;
  int wr = wid >> 1, wc = wid & 1;
  int l15 = lane & 15, lh = lane >> 4;
  int lane4 = lane >> 2, lpair = (lane & 3)*2;

  const __nv_bfloat16* zb = g_zb + (size_t)ho*MM*DIN;
  float sf2 = g_sf2v[h];
  float dK  = sf2 + JIT;          // exact diagonal of Kuu
  float c0  = 1.0f / dK;          // Jacobi seed

  if (tid < MM) um[tid] = u_mean[o*MM + tid];

  // ---- Phase 1: Kuu via bf16 mma (K=256) -> Kb bf16; X0 = c0*I -> Xb ----
  {
    int sr = tid >> 1, shalf = tid & 1;
    uint32_t st_dst[2] = { sb + N_ST0 + sr*SPITCH + shalf*16,
                           sb + N_ST1 + sr*SPITCH + shalf*16 };
    CP16(st_dst[0], zb + (size_t)sr*DIN + shalf*8);
    CP_COMMIT();

    float acc[16][4];
    #pragma unroll
    for (int i=0;i<16;i++)
      #pragma unroll
      for (int j=0;j<4;j++) acc[i][j]=0.f;

    uint32_t aoff = (wr*32 + l15)*SPITCH + lh*16;
    uint32_t boff = (wc*64 + l15)*SPITCH + lh*16;
    #pragma unroll 1
    for (int c=0;c<16;c++){
      int cur = c & 1;
      if (c < 15){
        CP16(st_dst[cur^1], zb + (size_t)sr*DIN + (c+1)*16 + shalf*8);
        CP_COMMIT();
        CP_WAIT(1);
      } else {
        CP_WAIT(0);
      }
      __syncthreads();
      uint32_t base = sb + (cur ? N_ST1 : N_ST0);
      uint32_t af[2][4], bt[4], bfr[8][2];
      #pragma unroll
      for (int mt=0;mt<2;mt++) ldsm4(base + aoff + mt*16*SPITCH, af[mt]);
      #pragma unroll
      for (int nn=0;nn<4;nn++){
        ldsm4(base + boff + nn*16*SPITCH, bt);
        bfr[nn*2][0]=bt[0]; bfr[nn*2][1]=bt[2];
        bfr[nn*2+1][0]=bt[1]; bfr[nn*2+1][1]=bt[3];
      }
      #pragma unroll
      for (int mt=0;mt<2;mt++)
        #pragma unroll
        for (int nf=0;nf<8;nf++)
          mma16816(acc[mt*8+nf], af[mt], bfr[nf]);
      __syncthreads();
    }

    // epilogue: Kb = sf2*exp(-0.5 d2), diag = sf2+JIT ; Xb = c0*I
    #pragma unroll
    for (int mt=0;mt<2;mt++){
      int r0 = wr*32 + mt*16 + lane4;
      int r1 = r0 + 8;
      float z20 = g_z2[ho*MM+r0], z21 = g_z2[ho*MM+r1];
      #pragma unroll
      for (int nf=0;nf<8;nf++){
        int cb = wc*64 + nf*8 + lpair;
        float zc0 = g_z2[ho*MM+cb], zc1 = g_z2[ho*MM+cb+1];
        float* a4 = acc[mt*8+nf];
        float v00 = (r0==cb  ) ? dK : sf2*__expf(-0.5f*fmaxf(z20+zc0-2.f*a4[0],0.f));
        float v01 = (r0==cb+1) ? dK : sf2*__expf(-0.5f*fmaxf(z20+zc1-2.f*a4[1],0.f));
        float v10 = (r1==cb  ) ? dK : sf2*__expf(-0.5f*fmaxf(z21+zc0-2.f*a4[2],0.f));
        float v11 = (r1==cb+1) ? dK : sf2*__expf(-0.5f*fmaxf(z21+zc1-2.f*a4[3],0.f));
        *(uint32_t*)(smc + N_KB + r0*KPITCH + cb*2) = pack_bf16x2(v00,v01);
        *(uint32_t*)(smc + N_KB + r1*KPITCH + cb*2) = pack_bf16x2(v10,v11);
        float x00 = (r0==cb  ) ? c0 : 0.f;
        float x01 = (r0==cb+1) ? c0 : 0.f;
        float x10 = (r1==cb  ) ? c0 : 0.f;
        float x11 = (r1==cb+1) ? c0 : 0.f;
        *(uint32_t*)(smc + N_XB + r0*KPITCH + cb*2) = pack_bf16x2(x00,x01);
        *(uint32_t*)(smc + N_XB + r1*KPITCH + cb*2) = pack_bf16x2(x10,x11);
      }
    }
  }

  // ---- Phase 2: Newton-Schulz, 3 iterations: Y = K X ; X <- 2X - X Y ----
  #pragma unroll 1
  for (int it=0; it<3; it++){
    __syncthreads();   // Xb (and Kb) writes visible
    {
      float acc[16][4];
      #pragma unroll
      for (int i=0;i<16;i++)
        #pragma unroll
        for (int j=0;j<4;j++) acc[i][j]=0.f;
      mm128(sb + N_KB, sb + N_XB, wr, wc, l15, lh, acc);
      // write Yb (nothing reads Yb concurrently)
      #pragma unroll
      for (int mt=0;mt<2;mt++){
        int r0 = wr*32 + mt*16 + lane4;
        int r1 = r0 + 8;
        #pragma unroll
        for (int nf=0;nf<8;nf++){
          int cb = wc*64 + nf*8 + lpair;
          float* a4 = acc[mt*8+nf];
          *(uint32_t*)(smc + N_YB + r0*KPITCH + cb*2) = pack_bf16x2(a4[0],a4[1]);
          *(uint32_t*)(smc + N_YB + r1*KPITCH + cb*2) = pack_bf16x2(a4[2],a4[3]);
        }
      }
    }
    __syncthreads();
    {
      float acc[16][4];
      #pragma unroll
      for (int i=0;i<16;i++)
        #pragma unroll
        for (int j=0;j<4;j++) acc[i][j]=0.f;
      mm128(sb + N_XB, sb + N_YB, wr, wc, l15, lh, acc);
      __syncthreads();   // all warps done reading Xb before overwrite
      float c_acc[4] = {0.f,0.f,0.f,0.f};
      #pragma unroll
      for (int mt=0;mt<2;mt++){
        int r0 = wr*32 + mt*16 + lane4;
        int r1 = r0 + 8;
        #pragma unroll
        for (int nf=0;nf<8;nf++){
          int cb = wc*64 + nf*8 + lpair;
          uint32_t p0 = *(const uint32_t*)(smc + N_XB + r0*KPITCH + cb*2);
          uint32_t p1 = *(const uint32_t*)(smc + N_XB + r1*KPITCH + cb*2);
          __nv_bfloat162 h0 = *reinterpret_cast<__nv_bfloat162*>(&p0);
          __nv_bfloat162 h1 = *reinterpret_cast<__nv_bfloat162*>(&p1);
          float* a4 = acc[mt*8+nf];
          float n00 = 2.f*__low2float(h0)  - a4[0];
          float n01 = 2.f*__high2float(h0) - a4[1];
          float n10 = 2.f*__low2float(h1)  - a4[2];
          float n11 = 2.f*__high2float(h1) - a4[3];
          *(uint32_t*)(smc + N_XB + r0*KPITCH + cb*2) = pack_bf16x2(n00,n01);
          *(uint32_t*)(smc + N_XB + r1*KPITCH + cb*2) = pack_bf16x2(n10,n11);
          if (it == 2){
            float u0 = um[cb], u1 = um[cb+1];
            c_acc[mt*2+0] += n00*u0 + n01*u1;
            c_acc[mt*2+1] += n10*u0 + n11*u1;
          }
        }
      }
      if (it == 2){
        #pragma unroll
        for (int u=0;u<4;u++){
          float v = c_acc[u];
          v += __shfl_xor_sync(0xffffffffu, v, 1);
          v += __shfl_xor_sync(0xffffffffu, v, 2);
          if ((lane & 3) == 0){
            int row = wr*32 + (u>>1)*16 + (u&1)*8 + lane4;
            pc[wc*128 + row] = v;
          }
        }
      }
    }
  }
  __syncthreads();
  if (tid < MM) g_cv[ho*MM + tid] = pc[tid] + pc[128+tid];

  // ---- Phase 3: Lsb[j][k] = Ls[k][j] (k>=j) into Kb region (Kb dead) ----
  {
    const float* Lv = u_tril + (size_t)o*TRILN;
    for (int it=0; it<32; it++){
      int idx = tid + it*256;
      int j = idx & 127, kp = (idx >> 7)*2;
      float v0 = (kp   >= j) ? Lv[(kp*(kp+1))/2 + j] : 0.f;
      float v1 = (kp+1 >= j) ? Lv[((kp+1)*(kp+2))/2 + j] : 0.f;
      *(uint32_t*)(smc + N_KB + j*KPITCH + kp*2) = pack_bf16x2(v0, v1);
    }
  }
  __syncthreads();

  // ---- Phase 4: T = P @ Ls (mma) -> Tb in Yb region ----
  {
    float acc[16][4];
    #pragma unroll
    for (int i=0;i<16;i++)
      #pragma unroll
      for (int j=0;j<4;j++) acc[i][j]=0.f;
    mm128(sb + N_XB, sb + N_KB, wr, wc, l15, lh, acc);
    __syncthreads();   // done reading old Yb?? (Yb dead) — barrier orders Tb write vs next GEMM reads
    #pragma unroll
    for (int mt=0;mt<2;mt++){
      int r0 = wr*32 + mt*16 + lane4;
      int r1 = r0 + 8;
      #pragma unroll
      for (int nf=0;nf<8;nf++){
        int cb = wc*64 + nf*8 + lpair;
        float* a4 = acc[mt*8+nf];
        *(uint32_t*)(smc + N_YB + r0*KPITCH + cb*2) = pack_bf16x2(a4[0],a4[1]);
        *(uint32_t*)(smc + N_YB + r1*KPITCH + cb*2) = pack_bf16x2(a4[2],a4[3]);
      }
    }
  }
  __syncthreads();

  // ---- Phase 5: Q = P - T T^T (mma) -> g_Qb ----
  {
    float acc[16][4];
    #pragma unroll
    for (int i=0;i<16;i++)
      #pragma unroll
      for (int j=0;j<4;j++) acc[i][j]=0.f;
    mm128(sb + N_YB, sb + N_YB, wr, wc, l15, lh, acc);
    __nv_bfloat16* Qg = g_Qb + (size_t)ho*MM*MM;
    #pragma unroll
    for (int mt=0;mt<2;mt++){
      int r0 = wr*32 + mt*16 + lane4;
      int r1 = r0 + 8;
      #pragma unroll
      for (int nf=0;nf<8;nf++){
        int cb = wc*64 + nf*8 + lpair;
        uint32_t p0 = *(const uint32_t*)(smc + N_XB + r0*KPITCH + cb*2);
        uint32_t p1 = *(const uint32_t*)(smc + N_XB + r1*KPITCH + cb*2);
        __nv_bfloat162 h0 = *reinterpret_cast<__nv_bfloat162*>(&p0);
        __nv_bfloat162 h1 = *reinterpret_cast<__nv_bfloat162*>(&p1);
        float* a4 = acc[mt*8+nf];
        *(uint32_t*)&Qg[(size_t)r0*MM + cb] = pack_bf16x2(__low2float(h0)-a4[0], __high2float(h0)-a4[1]);
        *(uint32_t*)&Qg[(size_t)r1*MM + cb] = pack_bf16x2(__low2float(h1)-a4[2], __high2float(h1)-a4[3]);
      }
    }
  }
}

// ============ k_main: mma.sync bf16 (unchanged from R4/R5) ============
#define OFF_CS    0
#define OFF_X2    512
#define OFF_Z2    1024
#define OFF_PMU   1536
#define OFF_PVAR  2560
#define OFF_XS0   3584
#define OFF_ZS0   9728
#define OFF_XS1   15872
#define OFF_ZS1   22016
#define OFF_KUF   28160
#define OFF_Q     62976
#define SMEM_MAIN 97792

__global__ __launch_bounds__(256,2) void k_main(float* __restrict__ out){
  extern __shared__ char smc[];
  uint32_t sb = smem_u32(smc);
  float* cs  = (float*)(smc + OFF_CS);
  float* sx2 = (float*)(smc + OFF_X2);
  float* sz2 = (float*)(smc + OFF_Z2);
  float* pmu = (float*)(smc + OFF_PMU);
  float* pvar= (float*)(smc + OFF_PVAR);

  int ho = blockIdx.y;
  int h  = ho / NOUT;
  int b0 = blockIdx.x * MM;
  int tid = threadIdx.x;
  int wid = tid >> 5, lane = tid & 31;
  int wr = wid >> 1, wc = wid & 1;
  int l15 = lane & 15, lh = lane >> 4;
  int lane4 = lane >> 2, lpair = (lane & 3)*2;

  if (tid < MM){
    cs[tid]  = g_cv[ho*MM + tid];
    sz2[tid] = g_z2[ho*MM + tid];
    sx2[tid] = g_x2[h*B_SZ + b0 + tid];
  }

  const __nv_bfloat16* xb = g_xb + ((size_t)h*B_SZ + b0)*DIN;
  const __nv_bfloat16* zb = g_zb + (size_t)ho*MM*DIN;

  int sr = tid >> 1, shalf = tid & 1;
  uint32_t xs_dst[2], zs_dst[2];
  xs_dst[0] = sb + OFF_XS0 + sr*SPITCH + shalf*16;
  zs_dst[0] = sb + OFF_ZS0 + sr*SPITCH + shalf*16;
  xs_dst[1] = sb + OFF_XS1 + sr*SPITCH + shalf*16;
  zs_dst[1] = sb + OFF_ZS1 + sr*SPITCH + shalf*16;

  CP16(xs_dst[0], xb + (size_t)sr*DIN + shalf*8);
  CP16(zs_dst[0], zb + (size_t)sr*DIN + shalf*8);
  CP_COMMIT();

  float acc[16][4];
  #pragma unroll
  for (int i=0;i<16;i++)
    #pragma unroll
    for (int j=0;j<4;j++) acc[i][j]=0.f;

  uint32_t aoffA = (wr*32 + l15)*SPITCH + lh*16;
  uint32_t boffA = (wc*64 + l15)*SPITCH + lh*16;
  #pragma unroll 1
  for (int c=0;c<16;c++){
    int cur = c & 1;
    if (c < 15){
      int nxt = cur ^ 1;
      int kg = (c+1)*16;
      CP16(xs_dst[nxt], xb + (size_t)sr*DIN + kg + shalf*8);
      CP16(zs_dst[nxt], zb + (size_t)sr*DIN + kg + shalf*8);
      CP_COMMIT();
      CP_WAIT(1);
    } else {
      CP_WAIT(0);
    }
    __syncthreads();
    uint32_t aB = sb + (cur ? OFF_XS1 : OFF_XS0) + aoffA;
    uint32_t bB = sb + (cur ? OFF_ZS1 : OFF_ZS0) + boffA;
    uint32_t af[2][4], bt[4], bfr[8][2];
    #pragma unroll
    for (int mt=0;mt<2;mt++) ldsm4(aB + mt*16*SPITCH, af[mt]);
    #pragma unroll
    for (int nn=0;nn<4;nn++){
      ldsm4(bB + nn*16*SPITCH, bt);
      bfr[nn*2][0]=bt[0]; bfr[nn*2][1]=bt[2];
      bfr[nn*2+1][0]=bt[1]; bfr[nn*2+1][1]=bt[3];
    }
    #pragma unroll
    for (int mt=0;mt<2;mt++)
      #pragma unroll
      for (int nf=0;nf<8;nf++)
        mma16816(acc[mt*8+nf], af[mt], bfr[nf]);
    __syncthreads();
  }

  {
    const __nv_bfloat16* Qg = g_Qb + (size_t)ho*MM*MM;
    #pragma unroll
    for (int it=0; it<8; it++){
      int t = tid + it*256;
      int r = t >> 4, cg = t & 15;
      uint4 v = *(const uint4*)(Qg + (size_t)r*MM + cg*8);
      *(uint4*)(smc + OFF_Q + r*KPITCH + cg*16) = v;
    }
  }

  float sf2 = g_sf2v[h];
  {
    float mu_acc[4] = {0.f,0.f,0.f,0.f};
    #pragma unroll
    for (int mt=0;mt<2;mt++){
      int r0 = wr*32 + mt*16 + lane4;
      int r1 = r0 + 8;
      float x20 = sx2[r0], x21 = sx2[r1];
      #pragma unroll
      for (int nf=0;nf<8;nf++){
        int cb = wc*64 + nf*8 + lpair;
        float z20 = sz2[cb], z21 = sz2[cb+1];
        float* a4 = acc[mt*8+nf];
        float k00 = sf2*__expf(-0.5f*fmaxf(x20 + z20 - 2.f*a4[0], 0.f));
        float k01 = sf2*__expf(-0.5f*fmaxf(x20 + z21 - 2.f*a4[1], 0.f));
        float k10 = sf2*__expf(-0.5f*fmaxf(x21 + z20 - 2.f*a4[2], 0.f));
        float k11 = sf2*__expf(-0.5f*fmaxf(x21 + z21 - 2.f*a4[3], 0.f));
        *(uint32_t*)(smc + OFF_KUF + r0*KPITCH + cb*2) = pack_bf16x2(k00,k01);
        *(uint32_t*)(smc + OFF_KUF + r1*KPITCH + cb*2) = pack_bf16x2(k10,k11);
        float c0 = cs[cb], c1 = cs[cb+1];
        mu_acc[mt*2+0] += k00*c0 + k01*c1;
        mu_acc[mt*2+1] += k10*c0 + k11*c1;
      }
    }
    #pragma unroll
    for (int u=0;u<4;u++){
      float v = mu_acc[u];
      v += __shfl_xor_sync(0xffffffffu, v, 1);
      v += __shfl_xor_sync(0xffffffffu, v, 2);
      if ((lane & 3) == 0){
        int row = wr*32 + (u>>1)*16 + (u&1)*8 + lane4;
        pmu[wc*128 + row] = v;
      }
    }
  }
  __syncthreads();

  #pragma unroll
  for (int i=0;i<16;i++)
    #pragma unroll
    for (int j=0;j<4;j++) acc[i][j]=0.f;
  mm128(sb + OFF_KUF, sb + OFF_Q, wr, wc, l15, lh, acc);

  {
    float v_acc[4] = {0.f,0.f,0.f,0.f};
    #pragma unroll
    for (int mt=0;mt<2;mt++){
      int r0 = wr*32 + mt*16 + lane4;
      int r1 = r0 + 8;
      #pragma unroll
      for (int nf=0;nf<8;nf++){
        int cb = wc*64 + nf*8 + lpair;
        uint32_t p0 = *(const uint32_t*)(smc + OFF_KUF + r0*KPITCH + cb*2);
        uint32_t p1 = *(const uint32_t*)(smc + OFF_KUF + r1*KPITCH + cb*2);
        __nv_bfloat162 h0 = *reinterpret_cast<__nv_bfloat162*>(&p0);
        __nv_bfloat162 h1 = *reinterpret_cast<__nv_bfloat162*>(&p1);
        float* a4 = acc[mt*8+nf];
        v_acc[mt*2+0] += __low2float(h0)*a4[0] + __high2float(h0)*a4[1];
        v_acc[mt*2+1] += __low2float(h1)*a4[2] + __high2float(h1)*a4[3];
      }
    }
    #pragma unroll
    for (int u=0;u<4;u++){
      float v = v_acc[u];
      v += __shfl_xor_sync(0xffffffffu, v, 1);
      v += __shfl_xor_sync(0xffffffffu, v, 2);
      if ((lane & 3) == 0){
        int row = wr*32 + (u>>1)*16 + (u&1)*8 + lane4;
        pvar[wc*128 + row] = v;
      }
    }
  }
  __syncthreads();

  if (tid < MM){
    size_t base = (size_t)ho*B_SZ + b0 + tid;
    out[base] = pmu[tid] + pmu[128+tid];
    out[(size_t)HOC*B_SZ + base] = sf2 - (pvar[tid] + pvar[128+tid]);
  }
}

// ---------------- launch ----------------
extern "C" void kernel_launch(void* const* d_in, const int* in_sizes, int n_in,
                              void* d_out, int out_size){
  const float* x      = (const float*)d_in[0];
  const float* z      = (const float*)d_in[1];
  const float* u_mean = (const float*)d_in[2];
  const float* u_tril = (const float*)d_in[3];
  const float* theta  = (const float*)d_in[4];
  float* out = (float*)d_out;

  cudaFuncSetAttribute(k_factor, cudaFuncAttributeMaxDynamicSharedMemorySize, N_TOT);
  cudaFuncSetAttribute(k_main,   cudaFuncAttributeMaxDynamicSharedMemorySize, SMEM_MAIN);

  k_hyper<<<1, 512>>>(theta);
  k_prep_x<<<NH*B_SZ, 256>>>(x);
  k_prep_z<<<HOC*MM, 256>>>(z);
  k_factor<<<HOC, 256, N_TOT>>>(u_mean, u_tril);
  k_main<<<dim3(B_SZ/MM, HOC), 256, SMEM_MAIN>>>(out);
}

// round 8
// speedup vs baseline: 13.5883x; 1.4811x over previous
#include <cuda_runtime.h>
#include <cuda_bf16.h>
#include <math.h>
#include <cstdint>

#define B_SZ  4096
#define DIN   256
#define NOUT  32
#define MM    128
#define NH    2
#define HOC   (NH*NOUT)
#define JIT   1e-4f
#define TRILN (MM*(MM+1)/2)
#define D2CUT 170.0f

// ---------------- scratch ----------------
__device__ float g_sf2v[NH];
__device__ float g_x2[NH*B_SZ];
__device__ float g_z2[HOC*MM];
__device__ float g_cv[HOC*MM];
__device__ __align__(16) __nv_bfloat16 g_xb[NH*B_SZ*DIN];
__device__ __align__(16) __nv_bfloat16 g_zb[HOC*MM*DIN];
__device__ __align__(16) __nv_bfloat16 g_Qb[HOC*MM*MM];

// ---------------- helpers ----------------
__device__ __forceinline__ uint32_t smem_u32(const void* p){
  uint32_t a;
  asm("{ .reg .u64 t; cvta.to.shared.u64 t, %1; cvt.u32.u64 %0, t; }" : "=r"(a) : "l"(p));
  return a;
}
__device__ __forceinline__ void ldsm4(uint32_t addr, uint32_t* r){
  asm volatile("ldmatrix.sync.aligned.m8n8.x4.shared.b16 {%0,%1,%2,%3}, [%4];"
    : "=r"(r[0]),"=r"(r[1]),"=r"(r[2]),"=r"(r[3]) : "r"(addr));
}
__device__ __forceinline__ void mma16816(float* c, const uint32_t* a, const uint32_t* b){
  asm volatile("mma.sync.aligned.m16n8k16.row.col.f32.bf16.bf16.f32 "
    "{%0,%1,%2,%3}, {%4,%5,%6,%7}, {%8,%9}, {%0,%1,%2,%3};"
    : "+f"(c[0]),"+f"(c[1]),"+f"(c[2]),"+f"(c[3])
    : "r"(a[0]),"r"(a[1]),"r"(a[2]),"r"(a[3]), "r"(b[0]),"r"(b[1]));
}
#define CP16(dst, src) asm volatile("cp.async.cg.shared.global [%0], [%1], 16;" :: "r"(dst), "l"(src))
#define CP_COMMIT()    asm volatile("cp.async.commit_group;" ::: "memory")
#define CP_WAIT(n)     asm volatile("cp.async.wait_group %0;" :: "n"(n) : "memory")

__device__ __forceinline__ uint32_t pack_bf16x2(float lo, float hi){
  uint32_t r;
  asm("cvt.rn.satfinite.bf16x2.f32 %0, %1, %2;" : "=r"(r) : "f"(hi), "f"(lo));
  return r;
}
__device__ __forceinline__ float rbf(float sf2, float d2){
  return (d2 < D2CUT) ? sf2*__expf(-0.5f*d2) : 0.f;
}

__device__ __forceinline__ float blockReduce256(float v){
  __shared__ float s[8];
  int lane = threadIdx.x & 31, w = threadIdx.x >> 5;
  #pragma unroll
  for (int o=16;o;o>>=1) v += __shfl_down_sync(0xffffffffu, v, o);
  if (lane==0) s[w] = v;
  __syncthreads();
  if (w==0){
    v = (lane < 8) ? s[lane] : 0.f;
    #pragma unroll
    for (int o=4;o;o>>=1) v += __shfl_down_sync(0xffffffffu, v, o);
  }
  return v;
}

#define SPITCH 48
#define KPITCH 272

// 128x128x128 bf16 block GEMM: acc += A(tile at aBase) * B(tile at bBase)^T
__device__ __forceinline__ void mm128(uint32_t aBase, uint32_t bBase,
                                      int wr, int wc, int l15, int lh,
                                      float acc[16][4]){
  uint32_t aB0 = aBase + (wr*32 + l15)*KPITCH + lh*16;
  uint32_t bB0 = bBase + (wc*64 + l15)*KPITCH + lh*16;
  #pragma unroll
  for (int ks=0;ks<8;ks++){
    uint32_t af[2][4], bt[4], bfr[8][2];
    #pragma unroll
    for (int mt=0;mt<2;mt++) ldsm4(aB0 + ks*32 + mt*16*KPITCH, af[mt]);
    #pragma unroll
    for (int nn=0;nn<4;nn++){
      ldsm4(bB0 + ks*32 + nn*16*KPITCH, bt);
      bfr[nn*2][0]=bt[0]; bfr[nn*2][1]=bt[2];
      bfr[nn*2+1][0]=bt[1]; bfr[nn*2+1][1]=bt[3];
    }
    #pragma unroll
    for (int mt=0;mt<2;mt++)
      #pragma unroll
      for (int nf=0;nf<8;nf++)
        mma16816(acc[mt*8+nf], af[mt], bfr[nf]);
  }
}

// ---------------- fused prep: scal inline, x & z scaled to bf16, norms, sf2 ----------------
__global__ void k_prep(const float* __restrict__ x, const float* __restrict__ z,
                       const float* __restrict__ theta){
  int bid = blockIdx.x;
  int d = threadIdx.x;
  if (bid < NH*B_SZ){
    int h = bid / B_SZ, b = bid - h*B_SZ;
    float sc = expf(-theta[h*(DIN+1)+1+d]);
    float v = x[(size_t)b*DIN + d] * sc;
    g_xb[(size_t)bid*DIN + d] = __float2bfloat16(v);
    float s = blockReduce256(v*v);
    if (d == 0){
      g_x2[bid] = s;
      if (bid < NH) g_sf2v[bid] = expf(theta[bid*(DIN+1)]);
    }
  } else {
    int id = bid - NH*B_SZ;           // ho*MM + m
    int h  = id / (NOUT*MM);
    int om = id % (NOUT*MM);
    float sc = expf(-theta[h*(DIN+1)+1+d]);
    float v = z[(size_t)om*DIN + d] * sc;
    g_zb[(size_t)id*DIN + d] = __float2bfloat16(v);
    float s = blockReduce256(v*v);
    if (d == 0) g_z2[id] = s;
  }
}

// ============ k_factor: Kuu (mma) -> Newton-Schulz P -> T,Q,c ============
#define N_KB   0        // Kb bf16 128x272   34816  (later: Lsb)
#define N_XB   34816    // Xb (P iterate)    34816
#define N_YB   69632    // Yb / Tb           34816  (3 stage bufs live here first)
#define N_UM   104448   // um[128] f32       512
#define N_PC   104960   // pc[2][128] f32    1024
#define N_TOT  105984

__global__ __launch_bounds__(256) void k_factor(const float* __restrict__ u_mean,
                                                const float* __restrict__ u_tril){
  extern __shared__ char smc[];
  uint32_t sb = smem_u32(smc);
  float* um = (float*)(smc + N_UM);
  float* pc = (float*)(smc + N_PC);

  int ho = blockIdx.x;
  int h = ho / NOUT, o = ho % NOUT;
  int tid = threadIdx.x;
  int wid = tid >> 5, lane = tid & 31;
  int wr = wid >> 1, wc = wid & 1;
  int l15 = lane & 15, lh = lane >> 4;
  int lane4 = lane >> 2, lpair = (lane & 3)*2;

  const __nv_bfloat16* zb = g_zb + (size_t)ho*MM*DIN;
  float sf2 = g_sf2v[h];
  float dK  = sf2 + JIT;
  float c0  = 1.0f / dK;

  if (tid < MM) um[tid] = u_mean[o*MM + tid];

  // ---- Phase 1: Kuu via bf16 mma, K=256, 3-stage ring (A=B=z tile) ----
  {
    int sr = tid >> 1, shalf = tid & 1;
    uint32_t zs_dst[3], zs_base[3];
    #pragma unroll
    for (int s=0;s<3;s++){
      zs_base[s] = sb + N_YB + s*6144;
      zs_dst[s]  = zs_base[s] + sr*SPITCH + shalf*16;
    }
    CP16(zs_dst[0], zb + (size_t)sr*DIN + 0  + shalf*8); CP_COMMIT();
    CP16(zs_dst[1], zb + (size_t)sr*DIN + 16 + shalf*8); CP_COMMIT();

    float acc[16][4];
    #pragma unroll
    for (int i=0;i<16;i++)
      #pragma unroll
      for (int j=0;j<4;j++) acc[i][j]=0.f;

    uint32_t aoff = (wr*32 + l15)*SPITCH + lh*16;
    uint32_t boff = (wc*64 + l15)*SPITCH + lh*16;
    #pragma unroll 1
    for (int c=0;c<16;c++){
      if (c == 15) { CP_WAIT(0); } else { CP_WAIT(1); }
      __syncthreads();
      int cur = c % 3;
      uint32_t base = zs_base[cur];
      uint32_t af[2][4], bt[4], bfr[8][2];
      #pragma unroll
      for (int mt=0;mt<2;mt++) ldsm4(base + aoff + mt*16*SPITCH, af[mt]);
      #pragma unroll
      for (int nn=0;nn<4;nn++){
        ldsm4(base + boff + nn*16*SPITCH, bt);
        bfr[nn*2][0]=bt[0]; bfr[nn*2][1]=bt[2];
        bfr[nn*2+1][0]=bt[1]; bfr[nn*2+1][1]=bt[3];
      }
      #pragma unroll
      for (int mt=0;mt<2;mt++)
        #pragma unroll
        for (int nf=0;nf<8;nf++)
          mma16816(acc[mt*8+nf], af[mt], bfr[nf]);
      if (c < 14){
        CP16(zs_dst[(c+2)%3], zb + (size_t)sr*DIN + (c+2)*16 + shalf*8);
        CP_COMMIT();
      }
    }

    // epilogue: Kb = rbf(d2), diag = dK ; Xb = c0*I
    #pragma unroll
    for (int mt=0;mt<2;mt++){
      int r0 = wr*32 + mt*16 + lane4;
      int r1 = r0 + 8;
      float z20 = g_z2[ho*MM+r0], z21 = g_z2[ho*MM+r1];
      #pragma unroll
      for (int nf=0;nf<8;nf++){
        int cb = wc*64 + nf*8 + lpair;
        float zc0 = g_z2[ho*MM+cb], zc1 = g_z2[ho*MM+cb+1];
        float* a4 = acc[mt*8+nf];
        float v00 = (r0==cb  ) ? dK : rbf(sf2, fmaxf(z20+zc0-2.f*a4[0],0.f));
        float v01 = (r0==cb+1) ? dK : rbf(sf2, fmaxf(z20+zc1-2.f*a4[1],0.f));
        float v10 = (r1==cb  ) ? dK : rbf(sf2, fmaxf(z21+zc0-2.f*a4[2],0.f));
        float v11 = (r1==cb+1) ? dK : rbf(sf2, fmaxf(z21+zc1-2.f*a4[3],0.f));
        *(uint32_t*)(smc + N_KB + r0*KPITCH + cb*2) = pack_bf16x2(v00,v01);
        *(uint32_t*)(smc + N_KB + r1*KPITCH + cb*2) = pack_bf16x2(v10,v11);
        float x00 = (r0==cb  ) ? c0 : 0.f;
        float x01 = (r0==cb+1) ? c0 : 0.f;
        float x10 = (r1==cb  ) ? c0 : 0.f;
        float x11 = (r1==cb+1) ? c0 : 0.f;
        *(uint32_t*)(smc + N_XB + r0*KPITCH + cb*2) = pack_bf16x2(x00,x01);
        *(uint32_t*)(smc + N_XB + r1*KPITCH + cb*2) = pack_bf16x2(x10,x11);
      }
    }
  }

  // ---- Phase 2: Newton-Schulz, 2 iterations: Y = K X ; X <- 2X - X Y ----
  #pragma unroll 1
  for (int it=0; it<2; it++){
    __syncthreads();
    {
      float acc[16][4];
      #pragma unroll
      for (int i=0;i<16;i++)
        #pragma unroll
        for (int j=0;j<4;j++) acc[i][j]=0.f;
      mm128(sb + N_KB, sb + N_XB, wr, wc, l15, lh, acc);
      #pragma unroll
      for (int mt=0;mt<2;mt++){
        int r0 = wr*32 + mt*16 + lane4;
        int r1 = r0 + 8;
        #pragma unroll
        for (int nf=0;nf<8;nf++){
          int cb = wc*64 + nf*8 + lpair;
          float* a4 = acc[mt*8+nf];
          *(uint32_t*)(smc + N_YB + r0*KPITCH + cb*2) = pack_bf16x2(a4[0],a4[1]);
          *(uint32_t*)(smc + N_YB + r1*KPITCH + cb*2) = pack_bf16x2(a4[2],a4[3]);
        }
      }
    }
    __syncthreads();
    {
      float acc[16][4];
      #pragma unroll
      for (int i=0;i<16;i++)
        #pragma unroll
        for (int j=0;j<4;j++) acc[i][j]=0.f;
      mm128(sb + N_XB, sb + N_YB, wr, wc, l15, lh, acc);
      __syncthreads();
      float c_acc[4] = {0.f,0.f,0.f,0.f};
      #pragma unroll
      for (int mt=0;mt<2;mt++){
        int r0 = wr*32 + mt*16 + lane4;
        int r1 = r0 + 8;
        #pragma unroll
        for (int nf=0;nf<8;nf++){
          int cb = wc*64 + nf*8 + lpair;
          uint32_t p0 = *(const uint32_t*)(smc + N_XB + r0*KPITCH + cb*2);
          uint32_t p1 = *(const uint32_t*)(smc + N_XB + r1*KPITCH + cb*2);
          __nv_bfloat162 h0 = *reinterpret_cast<__nv_bfloat162*>(&p0);
          __nv_bfloat162 h1 = *reinterpret_cast<__nv_bfloat162*>(&p1);
          float* a4 = acc[mt*8+nf];
          float n00 = 2.f*__low2float(h0)  - a4[0];
          float n01 = 2.f*__high2float(h0) - a4[1];
          float n10 = 2.f*__low2float(h1)  - a4[2];
          float n11 = 2.f*__high2float(h1) - a4[3];
          *(uint32_t*)(smc + N_XB + r0*KPITCH + cb*2) = pack_bf16x2(n00,n01);
          *(uint32_t*)(smc + N_XB + r1*KPITCH + cb*2) = pack_bf16x2(n10,n11);
          if (it == 1){
            float u0 = um[cb], u1 = um[cb+1];
            c_acc[mt*2+0] += n00*u0 + n01*u1;
            c_acc[mt*2+1] += n10*u0 + n11*u1;
          }
        }
      }
      if (it == 1){
        #pragma unroll
        for (int u=0;u<4;u++){
          float v = c_acc[u];
          v += __shfl_xor_sync(0xffffffffu, v, 1);
          v += __shfl_xor_sync(0xffffffffu, v, 2);
          if ((lane & 3) == 0){
            int row = wr*32 + (u>>1)*16 + (u&1)*8 + lane4;
            pc[wc*128 + row] = v;
          }
        }
      }
    }
  }
  __syncthreads();
  if (tid < MM) g_cv[ho*MM + tid] = pc[tid] + pc[128+tid];

  // ---- Phase 3: Lsb[j][k] = Ls[k][j] (k>=j) into Kb region ----
  {
    const float* Lv = u_tril + (size_t)o*TRILN;
    for (int it=0; it<32; it++){
      int idx = tid + it*256;
      int j = idx & 127, kp = (idx >> 7)*2;
      float v0 = (kp   >= j) ? Lv[(kp*(kp+1))/2 + j] : 0.f;
      float v1 = (kp+1 >= j) ? Lv[((kp+1)*(kp+2))/2 + j] : 0.f;
      *(uint32_t*)(smc + N_KB + j*KPITCH + kp*2) = pack_bf16x2(v0, v1);
    }
  }
  __syncthreads();

  // ---- Phase 4: T = P @ Ls -> Tb in Yb region ----
  {
    float acc[16][4];
    #pragma unroll
    for (int i=0;i<16;i++)
      #pragma unroll
      for (int j=0;j<4;j++) acc[i][j]=0.f;
    mm128(sb + N_XB, sb + N_KB, wr, wc, l15, lh, acc);
    __syncthreads();
    #pragma unroll
    for (int mt=0;mt<2;mt++){
      int r0 = wr*32 + mt*16 + lane4;
      int r1 = r0 + 8;
      #pragma unroll
      for (int nf=0;nf<8;nf++){
        int cb = wc*64 + nf*8 + lpair;
        float* a4 = acc[mt*8+nf];
        *(uint32_t*)(smc + N_YB + r0*KPITCH + cb*2) = pack_bf16x2(a4[0],a4[1]);
        *(uint32_t*)(smc + N_YB + r1*KPITCH + cb*2) = pack_bf16x2(a4[2],a4[3]);
      }
    }
  }
  __syncthreads();

  // ---- Phase 5: Q = P - T T^T -> g_Qb ----
  {
    float acc[16][4];
    #pragma unroll
    for (int i=0;i<16;i++)
      #pragma unroll
      for (int j=0;j<4;j++) acc[i][j]=0.f;
    mm128(sb + N_YB, sb + N_YB, wr, wc, l15, lh, acc);
    __nv_bfloat16* Qg = g_Qb + (size_t)ho*MM*MM;
    #pragma unroll
    for (int mt=0;mt<2;mt++){
      int r0 = wr*32 + mt*16 + lane4;
      int r1 = r0 + 8;
      #pragma unroll
      for (int nf=0;nf<8;nf++){
        int cb = wc*64 + nf*8 + lpair;
        uint32_t p0 = *(const uint32_t*)(smc + N_XB + r0*KPITCH + cb*2);
        uint32_t p1 = *(const uint32_t*)(smc + N_XB + r1*KPITCH + cb*2);
        __nv_bfloat162 h0 = *reinterpret_cast<__nv_bfloat162*>(&p0);
        __nv_bfloat162 h1 = *reinterpret_cast<__nv_bfloat162*>(&p1);
        float* a4 = acc[mt*8+nf];
        *(uint32_t*)&Qg[(size_t)r0*MM + cb] = pack_bf16x2(__low2float(h0)-a4[0], __high2float(h0)-a4[1]);
        *(uint32_t*)&Qg[(size_t)r1*MM + cb] = pack_bf16x2(__low2float(h1)-a4[2], __high2float(h1)-a4[3]);
      }
    }
  }
}

// ============ k_main: mma.sync bf16, 3-stage ring ============
#define OFF_CS    0
#define OFF_X2    512
#define OFF_Z2    1024
#define OFF_PMU   1536
#define OFF_PVAR  2560
#define OFF_S0X   3584
#define OFF_S0Z   9728
#define OFF_S1X   15872
#define OFF_S1Z   22016
#define OFF_S2X   28160
#define OFF_S2Z   34304
#define OFF_KUF   40448
#define OFF_Q     75264
#define SMEM_MAIN 110080

__global__ __launch_bounds__(256,2) void k_main(float* __restrict__ out){
  extern __shared__ char smc[];
  uint32_t sb = smem_u32(smc);
  float* cs  = (float*)(smc + OFF_CS);
  float* sx2 = (float*)(smc + OFF_X2);
  float* sz2 = (float*)(smc + OFF_Z2);
  float* pmu = (float*)(smc + OFF_PMU);
  float* pvar= (float*)(smc + OFF_PVAR);

  int ho = blockIdx.y;
  int h  = ho / NOUT;
  int b0 = blockIdx.x * MM;
  int tid = threadIdx.x;
  int wid = tid >> 5, lane = tid & 31;
  int wr = wid >> 1, wc = wid & 1;
  int l15 = lane & 15, lh = lane >> 4;
  int lane4 = lane >> 2, lpair = (lane & 3)*2;

  if (tid < MM){
    cs[tid]  = g_cv[ho*MM + tid];
    sz2[tid] = g_z2[ho*MM + tid];
    sx2[tid] = g_x2[h*B_SZ + b0 + tid];
  }

  const __nv_bfloat16* xb = g_xb + ((size_t)h*B_SZ + b0)*DIN;
  const __nv_bfloat16* zb = g_zb + (size_t)ho*MM*DIN;

  int sr = tid >> 1, shalf = tid & 1;
  uint32_t xs_dst[3], zs_dst[3], xbase[3], zbase[3];
  xbase[0] = sb + OFF_S0X; zbase[0] = sb + OFF_S0Z;
  xbase[1] = sb + OFF_S1X; zbase[1] = sb + OFF_S1Z;
  xbase[2] = sb + OFF_S2X; zbase[2] = sb + OFF_S2Z;
  #pragma unroll
  for (int s=0;s<3;s++){
    xs_dst[s] = xbase[s] + sr*SPITCH + shalf*16;
    zs_dst[s] = zbase[s] + sr*SPITCH + shalf*16;
  }

  CP16(xs_dst[0], xb + (size_t)sr*DIN + 0  + shalf*8);
  CP16(zs_dst[0], zb + (size_t)sr*DIN + 0  + shalf*8);
  CP_COMMIT();
  CP16(xs_dst[1], xb + (size_t)sr*DIN + 16 + shalf*8);
  CP16(zs_dst[1], zb + (size_t)sr*DIN + 16 + shalf*8);
  CP_COMMIT();

  float acc[16][4];
  #pragma unroll
  for (int i=0;i<16;i++)
    #pragma unroll
    for (int j=0;j<4;j++) acc[i][j]=0.f;

  uint32_t aoffA = (wr*32 + l15)*SPITCH + lh*16;
  uint32_t boffA = (wc*64 + l15)*SPITCH + lh*16;
  #pragma unroll 1
  for (int c=0;c<16;c++){
    if (c == 15) { CP_WAIT(0); } else { CP_WAIT(1); }
    __syncthreads();
    int cur = c % 3;
    uint32_t aB = xbase[cur] + aoffA;
    uint32_t bB = zbase[cur] + boffA;
    uint32_t af[2][4], bt[4], bfr[8][2];
    #pragma unroll
    for (int mt=0;mt<2;mt++) ldsm4(aB + mt*16*SPITCH, af[mt]);
    #pragma unroll
    for (int nn=0;nn<4;nn++){
      ldsm4(bB + nn*16*SPITCH, bt);
      bfr[nn*2][0]=bt[0]; bfr[nn*2][1]=bt[2];
      bfr[nn*2+1][0]=bt[1]; bfr[nn*2+1][1]=bt[3];
    }
    #pragma unroll
    for (int mt=0;mt<2;mt++)
      #pragma unroll
      for (int nf=0;nf<8;nf++)
        mma16816(acc[mt*8+nf], af[mt], bfr[nf]);
    if (c < 14){
      int nx = (c+2)%3;
      CP16(xs_dst[nx], xb + (size_t)sr*DIN + (c+2)*16 + shalf*8);
      CP16(zs_dst[nx], zb + (size_t)sr*DIN + (c+2)*16 + shalf*8);
      CP_COMMIT();
    }
  }

  // stage Q tile while epilogue computes
  {
    const __nv_bfloat16* Qg = g_Qb + (size_t)ho*MM*MM;
    #pragma unroll
    for (int it=0; it<8; it++){
      int t = tid + it*256;
      int r = t >> 4, cg = t & 15;
      uint4 v = *(const uint4*)(Qg + (size_t)r*MM + cg*8);
      *(uint4*)(smc + OFF_Q + r*KPITCH + cg*16) = v;
    }
  }

  float sf2 = g_sf2v[h];
  {
    float mu_acc[4] = {0.f,0.f,0.f,0.f};
    #pragma unroll
    for (int mt=0;mt<2;mt++){
      int r0 = wr*32 + mt*16 + lane4;
      int r1 = r0 + 8;
      float x20 = sx2[r0], x21 = sx2[r1];
      #pragma unroll
      for (int nf=0;nf<8;nf++){
        int cb = wc*64 + nf*8 + lpair;
        float z20 = sz2[cb], z21 = sz2[cb+1];
        float* a4 = acc[mt*8+nf];
        float k00 = rbf(sf2, fmaxf(x20 + z20 - 2.f*a4[0], 0.f));
        float k01 = rbf(sf2, fmaxf(x20 + z21 - 2.f*a4[1], 0.f));
        float k10 = rbf(sf2, fmaxf(x21 + z20 - 2.f*a4[2], 0.f));
        float k11 = rbf(sf2, fmaxf(x21 + z21 - 2.f*a4[3], 0.f));
        *(uint32_t*)(smc + OFF_KUF + r0*KPITCH + cb*2) = pack_bf16x2(k00,k01);
        *(uint32_t*)(smc + OFF_KUF + r1*KPITCH + cb*2) = pack_bf16x2(k10,k11);
        float c0 = cs[cb], c1 = cs[cb+1];
        mu_acc[mt*2+0] += k00*c0 + k01*c1;
        mu_acc[mt*2+1] += k10*c0 + k11*c1;
      }
    }
    #pragma unroll
    for (int u=0;u<4;u++){
      float v = mu_acc[u];
      v += __shfl_xor_sync(0xffffffffu, v, 1);
      v += __shfl_xor_sync(0xffffffffu, v, 2);
      if ((lane & 3) == 0){
        int row = wr*32 + (u>>1)*16 + (u&1)*8 + lane4;
        pmu[wc*128 + row] = v;
      }
    }
  }
  __syncthreads();

  #pragma unroll
  for (int i=0;i<16;i++)
    #pragma unroll
    for (int j=0;j<4;j++) acc[i][j]=0.f;
  mm128(sb + OFF_KUF, sb + OFF_Q, wr, wc, l15, lh, acc);

  {
    float v_acc[4] = {0.f,0.f,0.f,0.f};
    #pragma unroll
    for (int mt=0;mt<2;mt++){
      int r0 = wr*32 + mt*16 + lane4;
      int r1 = r0 + 8;
      #pragma unroll
      for (int nf=0;nf<8;nf++){
        int cb = wc*64 + nf*8 + lpair;
        uint32_t p0 = *(const uint32_t*)(smc + OFF_KUF + r0*KPITCH + cb*2);
        uint32_t p1 = *(const uint32_t*)(smc + OFF_KUF + r1*KPITCH + cb*2);
        __nv_bfloat162 h0 = *reinterpret_cast<__nv_bfloat162*>(&p0);
        __nv_bfloat162 h1 = *reinterpret_cast<__nv_bfloat162*>(&p1);
        float* a4 = acc[mt*8+nf];
        v_acc[mt*2+0] += __low2float(h0)*a4[0] + __high2float(h0)*a4[1];
        v_acc[mt*2+1] += __low2float(h1)*a4[2] + __high2float(h1)*a4[3];
      }
    }
    #pragma unroll
    for (int u=0;u<4;u++){
      float v = v_acc[u];
      v += __shfl_xor_sync(0xffffffffu, v, 1);
      v += __shfl_xor_sync(0xffffffffu, v, 2);
      if ((lane & 3) == 0){
        int row = wr*32 + (u>>1)*16 + (u&1)*8 + lane4;
        pvar[wc*128 + row] = v;
      }
    }
  }
  __syncthreads();

  if (tid < MM){
    size_t base = (size_t)ho*B_SZ + b0 + tid;
    out[base] = pmu[tid] + pmu[128+tid];
    out[(size_t)HOC*B_SZ + base] = sf2 - (pvar[tid] + pvar[128+tid]);
  }
}

// ---------------- launch ----------------
extern "C" void kernel_launch(void* const* d_in, const int* in_sizes, int n_in,
                              void* d_out, int out_size){
  const float* x      = (const float*)d_in[0];
  const float* z      = (const float*)d_in[1];
  const float* u_mean = (const float*)d_in[2];
  const float* u_tril = (const float*)d_in[3];
  const float* theta  = (const float*)d_in[4];
  float* out = (float*)d_out;

  cudaFuncSetAttribute(k_factor, cudaFuncAttributeMaxDynamicSharedMemorySize, N_TOT);
  cudaFuncSetAttribute(k_main,   cudaFuncAttributeMaxDynamicSharedMemorySize, SMEM_MAIN);

  k_prep<<<NH*B_SZ + HOC*MM, 256>>>(x, z, theta);
  k_factor<<<HOC, 256, N_TOT>>>(u_mean, u_tril);
  k_main<<<dim3(B_SZ/MM, HOC), 256, SMEM_MAIN>>>(out);
}

// round 9
// speedup vs baseline: 19.1501x; 1.4093x over previous
#include <cuda_runtime.h>
#include <cuda_bf16.h>
#include <math.h>
#include <cstdint>

#define B_SZ  4096
#define DIN   256
#define NOUT  32
#define MM    128
#define NH    2
#define HOC   (NH*NOUT)
#define JIT   1e-4f
#define TRILN (MM*(MM+1)/2)
#define D2CUT 170.0f

// ---------------- scratch ----------------
__device__ float g_sf2v[NH];
__device__ float g_x2[NH*B_SZ];
__device__ float g_z2[HOC*MM];
__device__ float g_cv[HOC*MM];
__device__ __align__(16) __nv_bfloat16 g_xb[NH*B_SZ*DIN];
__device__ __align__(16) __nv_bfloat16 g_zb[HOC*MM*DIN];
__device__ __align__(16) __nv_bfloat16 g_Qb[HOC*MM*MM];

// ---------------- helpers ----------------
__device__ __forceinline__ uint32_t smem_u32(const void* p){
  uint32_t a;
  asm("{ .reg .u64 t; cvta.to.shared.u64 t, %1; cvt.u32.u64 %0, t; }" : "=r"(a) : "l"(p));
  return a;
}
__device__ __forceinline__ void ldsm4(uint32_t addr, uint32_t* r){
  asm volatile("ldmatrix.sync.aligned.m8n8.x4.shared.b16 {%0,%1,%2,%3}, [%4];"
    : "=r"(r[0]),"=r"(r[1]),"=r"(r[2]),"=r"(r[3]) : "r"(addr));
}
__device__ __forceinline__ void mma16816(float* c, const uint32_t* a, const uint32_t* b){
  asm volatile("mma.sync.aligned.m16n8k16.row.col.f32.bf16.bf16.f32 "
    "{%0,%1,%2,%3}, {%4,%5,%6,%7}, {%8,%9}, {%0,%1,%2,%3};"
    : "+f"(c[0]),"+f"(c[1]),"+f"(c[2]),"+f"(c[3])
    : "r"(a[0]),"r"(a[1]),"r"(a[2]),"r"(a[3]), "r"(b[0]),"r"(b[1]));
}
#define CP16(dst, src) asm volatile("cp.async.cg.shared.global [%0], [%1], 16;" :: "r"(dst), "l"(src))
#define CP_COMMIT()    asm volatile("cp.async.commit_group;" ::: "memory")
#define CP_WAIT(n)     asm volatile("cp.async.wait_group %0;" :: "n"(n) : "memory")

__device__ __forceinline__ uint32_t pack_bf16x2(float lo, float hi){
  uint32_t r;
  asm("cvt.rn.satfinite.bf16x2.f32 %0, %1, %2;" : "=r"(r) : "f"(hi), "f"(lo));
  return r;
}
__device__ __forceinline__ float rbf(float sf2, float d2){
  return (d2 < D2CUT) ? sf2*__expf(-0.5f*d2) : 0.f;
}

__device__ __forceinline__ float blockReduce256(float v){
  __shared__ float s[8];
  int lane = threadIdx.x & 31, w = threadIdx.x >> 5;
  #pragma unroll
  for (int o=16;o;o>>=1) v += __shfl_down_sync(0xffffffffu, v, o);
  if (lane==0) s[w] = v;
  __syncthreads();
  if (w==0){
    v = (lane < 8) ? s[lane] : 0.f;
    #pragma unroll
    for (int o=4;o;o>>=1) v += __shfl_down_sync(0xffffffffu, v, o);
  }
  return v;
}

#define SP2    80       // K=32 stage pitch bytes (32 bf16 + 16B pad)
#define XSTB   10240    // one K=32 stage buffer: 128*80
#define KPITCH 272

// 128x128x128 bf16 block GEMM from KPITCH tiles
__device__ __forceinline__ void mm128(uint32_t aBase, uint32_t bBase,
                                      int wr, int wc, int l15, int lh,
                                      float acc[16][4]){
  uint32_t aB0 = aBase + (wr*32 + l15)*KPITCH + lh*16;
  uint32_t bB0 = bBase + (wc*64 + l15)*KPITCH + lh*16;
  #pragma unroll
  for (int ks=0;ks<8;ks++){
    uint32_t af[2][4], bt[4], bfr[8][2];
    #pragma unroll
    for (int mt=0;mt<2;mt++) ldsm4(aB0 + ks*32 + mt*16*KPITCH, af[mt]);
    #pragma unroll
    for (int nn=0;nn<4;nn++){
      ldsm4(bB0 + ks*32 + nn*16*KPITCH, bt);
      bfr[nn*2][0]=bt[0]; bfr[nn*2][1]=bt[2];
      bfr[nn*2+1][0]=bt[1]; bfr[nn*2+1][1]=bt[3];
    }
    #pragma unroll
    for (int mt=0;mt<2;mt++)
      #pragma unroll
      for (int nf=0;nf<8;nf++)
        mma16816(acc[mt*8+nf], af[mt], bfr[nf]);
  }
}

// one K=32 chunk from SP2 stages: acc += A(32 rows)*B(64 cols)^T
__device__ __forceinline__ void chunk32(uint32_t aB, uint32_t bB, float acc[16][4]){
  #pragma unroll
  for (int ks=0;ks<2;ks++){
    uint32_t af[2][4], bt[4], bfr[8][2];
    #pragma unroll
    for (int mt=0;mt<2;mt++) ldsm4(aB + ks*32 + mt*16*SP2, af[mt]);
    #pragma unroll
    for (int nn=0;nn<4;nn++){
      ldsm4(bB + ks*32 + nn*16*SP2, bt);
      bfr[nn*2][0]=bt[0]; bfr[nn*2][1]=bt[2];
      bfr[nn*2+1][0]=bt[1]; bfr[nn*2+1][1]=bt[3];
    }
    #pragma unroll
    for (int mt=0;mt<2;mt++)
      #pragma unroll
      for (int nf=0;nf<8;nf++)
        mma16816(acc[mt*8+nf], af[mt], bfr[nf]);
  }
}

// ---------------- fused prep ----------------
__global__ void k_prep(const float* __restrict__ x, const float* __restrict__ z,
                       const float* __restrict__ theta){
  int bid = blockIdx.x;
  int d = threadIdx.x;
  if (bid < NH*B_SZ){
    int h = bid / B_SZ, b = bid - h*B_SZ;
    float sc = expf(-theta[h*(DIN+1)+1+d]);
    float v = x[(size_t)b*DIN + d] * sc;
    g_xb[(size_t)bid*DIN + d] = __float2bfloat16(v);
    float s = blockReduce256(v*v);
    if (d == 0){
      g_x2[bid] = s;
      if (bid < NH) g_sf2v[bid] = expf(theta[bid*(DIN+1)]);
    }
  } else {
    int id = bid - NH*B_SZ;
    int h  = id / (NOUT*MM);
    int om = id % (NOUT*MM);
    float sc = expf(-theta[h*(DIN+1)+1+d]);
    float v = z[(size_t)om*DIN + d] * sc;
    g_zb[(size_t)id*DIN + d] = __float2bfloat16(v);
    float s = blockReduce256(v*v);
    if (d == 0) g_z2[id] = s;
  }
}

// ============ k_factor ============
#define N_KB   0        // Kb bf16 128x272   34816  (later: Lsb)
#define N_XB   34816    // Xb                34816
#define N_YB   69632    // Yb / Tb / stages  34816
#define N_UM   104448
#define N_PC   104960
#define N_TOT  105984

__global__ __launch_bounds__(256) void k_factor(const float* __restrict__ u_mean,
                                                const float* __restrict__ u_tril){
  extern __shared__ char smc[];
  uint32_t sb = smem_u32(smc);
  float* um = (float*)(smc + N_UM);
  float* pc = (float*)(smc + N_PC);

  int ho = blockIdx.x;
  int h = ho / NOUT, o = ho % NOUT;
  int tid = threadIdx.x;
  int wid = tid >> 5, lane = tid & 31;
  int wr = wid >> 1, wc = wid & 1;
  int l15 = lane & 15, lh = lane >> 4;
  int lane4 = lane >> 2, lpair = (lane & 3)*2;

  const __nv_bfloat16* zb = g_zb + (size_t)ho*MM*DIN;
  float sf2 = g_sf2v[h];
  float dK  = sf2 + JIT;
  float c0  = 1.0f / dK;

  if (tid < MM) um[tid] = u_mean[o*MM + tid];

  // ---- Phase 1: Kuu via bf16 mma, K=256 in 8 chunks of 32, 3-stage ring ----
  {
    uint32_t zs_base[3];
    #pragma unroll
    for (int s=0;s<3;s++) zs_base[s] = sb + N_YB + s*XSTB;
    int row0 = tid >> 2, q0 = tid & 3;                 // chunk k=0
    int row1 = (tid+256) >> 2, q1 = (tid+256) & 3;     // chunk k=1
    // prefetch stages 0,1
    #pragma unroll
    for (int s=0;s<2;s++){
      CP16(zs_base[s] + row0*SP2 + q0*16, zb + (size_t)row0*DIN + s*32 + q0*8);
      CP16(zs_base[s] + row1*SP2 + q1*16, zb + (size_t)row1*DIN + s*32 + q1*8);
      CP_COMMIT();
    }

    float acc[16][4];
    #pragma unroll
    for (int i=0;i<16;i++)
      #pragma unroll
      for (int j=0;j<4;j++) acc[i][j]=0.f;

    uint32_t aoff = (wr*32 + l15)*SP2 + lh*16;
    uint32_t boff = (wc*64 + l15)*SP2 + lh*16;
    #pragma unroll 1
    for (int c=0;c<8;c++){
      if (c == 7) { CP_WAIT(0); } else { CP_WAIT(1); }
      __syncthreads();
      int cur = c % 3;
      chunk32(zs_base[cur] + aoff, zs_base[cur] + boff, acc);
      if (c < 6){
        int nx = (c+2)%3;
        CP16(zs_base[nx] + row0*SP2 + q0*16, zb + (size_t)row0*DIN + (c+2)*32 + q0*8);
        CP16(zs_base[nx] + row1*SP2 + q1*16, zb + (size_t)row1*DIN + (c+2)*32 + q1*8);
        CP_COMMIT();
      }
    }

    // epilogue: Kb, Xb = c0*I
    #pragma unroll
    for (int mt=0;mt<2;mt++){
      int r0 = wr*32 + mt*16 + lane4;
      int r1 = r0 + 8;
      float z20 = g_z2[ho*MM+r0], z21 = g_z2[ho*MM+r1];
      #pragma unroll
      for (int nf=0;nf<8;nf++){
        int cb = wc*64 + nf*8 + lpair;
        float zc0 = g_z2[ho*MM+cb], zc1 = g_z2[ho*MM+cb+1];
        float* a4 = acc[mt*8+nf];
        float v00 = (r0==cb  ) ? dK : rbf(sf2, fmaxf(z20+zc0-2.f*a4[0],0.f));
        float v01 = (r0==cb+1) ? dK : rbf(sf2, fmaxf(z20+zc1-2.f*a4[1],0.f));
        float v10 = (r1==cb  ) ? dK : rbf(sf2, fmaxf(z21+zc0-2.f*a4[2],0.f));
        float v11 = (r1==cb+1) ? dK : rbf(sf2, fmaxf(z21+zc1-2.f*a4[3],0.f));
        *(uint32_t*)(smc + N_KB + r0*KPITCH + cb*2) = pack_bf16x2(v00,v01);
        *(uint32_t*)(smc + N_KB + r1*KPITCH + cb*2) = pack_bf16x2(v10,v11);
        float x00 = (r0==cb  ) ? c0 : 0.f;
        float x01 = (r0==cb+1) ? c0 : 0.f;
        float x10 = (r1==cb  ) ? c0 : 0.f;
        float x11 = (r1==cb+1) ? c0 : 0.f;
        *(uint32_t*)(smc + N_XB + r0*KPITCH + cb*2) = pack_bf16x2(x00,x01);
        *(uint32_t*)(smc + N_XB + r1*KPITCH + cb*2) = pack_bf16x2(x10,x11);
      }
    }
  }

  // ---- Phase 2: Newton-Schulz x2 ----
  #pragma unroll 1
  for (int it=0; it<2; it++){
    __syncthreads();
    {
      float acc[16][4];
      #pragma unroll
      for (int i=0;i<16;i++)
        #pragma unroll
        for (int j=0;j<4;j++) acc[i][j]=0.f;
      mm128(sb + N_KB, sb + N_XB, wr, wc, l15, lh, acc);
      #pragma unroll
      for (int mt=0;mt<2;mt++){
        int r0 = wr*32 + mt*16 + lane4;
        int r1 = r0 + 8;
        #pragma unroll
        for (int nf=0;nf<8;nf++){
          int cb = wc*64 + nf*8 + lpair;
          float* a4 = acc[mt*8+nf];
          *(uint32_t*)(smc + N_YB + r0*KPITCH + cb*2) = pack_bf16x2(a4[0],a4[1]);
          *(uint32_t*)(smc + N_YB + r1*KPITCH + cb*2) = pack_bf16x2(a4[2],a4[3]);
        }
      }
    }
    __syncthreads();
    {
      float acc[16][4];
      #pragma unroll
      for (int i=0;i<16;i++)
        #pragma unroll
        for (int j=0;j<4;j++) acc[i][j]=0.f;
      mm128(sb + N_XB, sb + N_YB, wr, wc, l15, lh, acc);
      __syncthreads();
      float c_acc[4] = {0.f,0.f,0.f,0.f};
      #pragma unroll
      for (int mt=0;mt<2;mt++){
        int r0 = wr*32 + mt*16 + lane4;
        int r1 = r0 + 8;
        #pragma unroll
        for (int nf=0;nf<8;nf++){
          int cb = wc*64 + nf*8 + lpair;
          uint32_t p0 = *(const uint32_t*)(smc + N_XB + r0*KPITCH + cb*2);
          uint32_t p1 = *(const uint32_t*)(smc + N_XB + r1*KPITCH + cb*2);
          __nv_bfloat162 h0 = *reinterpret_cast<__nv_bfloat162*>(&p0);
          __nv_bfloat162 h1 = *reinterpret_cast<__nv_bfloat162*>(&p1);
          float* a4 = acc[mt*8+nf];
          float n00 = 2.f*__low2float(h0)  - a4[0];
          float n01 = 2.f*__high2float(h0) - a4[1];
          float n10 = 2.f*__low2float(h1)  - a4[2];
          float n11 = 2.f*__high2float(h1) - a4[3];
          *(uint32_t*)(smc + N_XB + r0*KPITCH + cb*2) = pack_bf16x2(n00,n01);
          *(uint32_t*)(smc + N_XB + r1*KPITCH + cb*2) = pack_bf16x2(n10,n11);
          if (it == 1){
            float u0 = um[cb], u1 = um[cb+1];
            c_acc[mt*2+0] += n00*u0 + n01*u1;
            c_acc[mt*2+1] += n10*u0 + n11*u1;
          }
        }
      }
      if (it == 1){
        #pragma unroll
        for (int u=0;u<4;u++){
          float v = c_acc[u];
          v += __shfl_xor_sync(0xffffffffu, v, 1);
          v += __shfl_xor_sync(0xffffffffu, v, 2);
          if ((lane & 3) == 0){
            int row = wr*32 + (u>>1)*16 + (u&1)*8 + lane4;
            pc[wc*128 + row] = v;
          }
        }
      }
    }
  }
  __syncthreads();
  if (tid < MM) g_cv[ho*MM + tid] = pc[tid] + pc[128+tid];

  // ---- Phase 3: Lsb into Kb ----
  {
    const float* Lv = u_tril + (size_t)o*TRILN;
    for (int it=0; it<32; it++){
      int idx = tid + it*256;
      int j = idx & 127, kp = (idx >> 7)*2;
      float v0 = (kp   >= j) ? Lv[(kp*(kp+1))/2 + j] : 0.f;
      float v1 = (kp+1 >= j) ? Lv[((kp+1)*(kp+2))/2 + j] : 0.f;
      *(uint32_t*)(smc + N_KB + j*KPITCH + kp*2) = pack_bf16x2(v0, v1);
    }
  }
  __syncthreads();

  // ---- Phase 4: T = P @ Ls -> Yb ----
  {
    float acc[16][4];
    #pragma unroll
    for (int i=0;i<16;i++)
      #pragma unroll
      for (int j=0;j<4;j++) acc[i][j]=0.f;
    mm128(sb + N_XB, sb + N_KB, wr, wc, l15, lh, acc);
    __syncthreads();
    #pragma unroll
    for (int mt=0;mt<2;mt++){
      int r0 = wr*32 + mt*16 + lane4;
      int r1 = r0 + 8;
      #pragma unroll
      for (int nf=0;nf<8;nf++){
        int cb = wc*64 + nf*8 + lpair;
        float* a4 = acc[mt*8+nf];
        *(uint32_t*)(smc + N_YB + r0*KPITCH + cb*2) = pack_bf16x2(a4[0],a4[1]);
        *(uint32_t*)(smc + N_YB + r1*KPITCH + cb*2) = pack_bf16x2(a4[2],a4[3]);
      }
    }
  }
  __syncthreads();

  // ---- Phase 5: Q = P - T T^T -> g_Qb ----
  {
    float acc[16][4];
    #pragma unroll
    for (int i=0;i<16;i++)
      #pragma unroll
      for (int j=0;j<4;j++) acc[i][j]=0.f;
    mm128(sb + N_YB, sb + N_YB, wr, wc, l15, lh, acc);
    __nv_bfloat16* Qg = g_Qb + (size_t)ho*MM*MM;
    #pragma unroll
    for (int mt=0;mt<2;mt++){
      int r0 = wr*32 + mt*16 + lane4;
      int r1 = r0 + 8;
      #pragma unroll
      for (int nf=0;nf<8;nf++){
        int cb = wc*64 + nf*8 + lpair;
        uint32_t p0 = *(const uint32_t*)(smc + N_XB + r0*KPITCH + cb*2);
        uint32_t p1 = *(const uint32_t*)(smc + N_XB + r1*KPITCH + cb*2);
        __nv_bfloat162 h0 = *reinterpret_cast<__nv_bfloat162*>(&p0);
        __nv_bfloat162 h1 = *reinterpret_cast<__nv_bfloat162*>(&p1);
        float* a4 = acc[mt*8+nf];
        *(uint32_t*)&Qg[(size_t)r0*MM + cb] = pack_bf16x2(__low2float(h0)-a4[0], __high2float(h0)-a4[1]);
        *(uint32_t*)&Qg[(size_t)r1*MM + cb] = pack_bf16x2(__low2float(h1)-a4[2], __high2float(h1)-a4[3]);
      }
    }
  }
}

// ============ k_main: K=32 ring, Phase-B skip when kuf tile == 0 ============
#define OFF_CS    0
#define OFF_X2    512
#define OFF_Z2    1024
#define OFF_PMU   1536
#define OFF_PVAR  2560
#define OFF_ST    3584         // 3 stages x {x,z} x 10240 = 61440 -> ends 65024
#define OFF_KUF   65024        // 34816 -> ends 99840
#define OFF_Q     OFF_ST       // overlaps dead stage ring
#define SMEM_MAIN 99840

__global__ __launch_bounds__(256,2) void k_main(float* __restrict__ out){
  extern __shared__ char smc[];
  uint32_t sb = smem_u32(smc);
  float* cs  = (float*)(smc + OFF_CS);
  float* sx2 = (float*)(smc + OFF_X2);
  float* sz2 = (float*)(smc + OFF_Z2);
  float* pmu = (float*)(smc + OFF_PMU);
  float* pvar= (float*)(smc + OFF_PVAR);

  int ho = blockIdx.y;
  int h  = ho / NOUT;
  int b0 = blockIdx.x * MM;
  int tid = threadIdx.x;
  int wid = tid >> 5, lane = tid & 31;
  int wr = wid >> 1, wc = wid & 1;
  int l15 = lane & 15, lh = lane >> 4;
  int lane4 = lane >> 2, lpair = (lane & 3)*2;

  if (tid < MM){
    cs[tid]  = g_cv[ho*MM + tid];
    sz2[tid] = g_z2[ho*MM + tid];
    sx2[tid] = g_x2[h*B_SZ + b0 + tid];
  }

  const __nv_bfloat16* xb = g_xb + ((size_t)h*B_SZ + b0)*DIN;
  const __nv_bfloat16* zb = g_zb + (size_t)ho*MM*DIN;

  uint32_t xs_base[3], zs_base[3];
  #pragma unroll
  for (int s=0;s<3;s++){
    xs_base[s] = sb + OFF_ST + s*2*XSTB;
    zs_base[s] = xs_base[s] + XSTB;
  }
  int row0 = tid >> 2, q0 = tid & 3;
  int row1 = (tid+256) >> 2, q1 = (tid+256) & 3;

  // prefetch stages 0,1
  #pragma unroll
  for (int s=0;s<2;s++){
    CP16(xs_base[s] + row0*SP2 + q0*16, xb + (size_t)row0*DIN + s*32 + q0*8);
    CP16(xs_base[s] + row1*SP2 + q1*16, xb + (size_t)row1*DIN + s*32 + q1*8);
    CP16(zs_base[s] + row0*SP2 + q0*16, zb + (size_t)row0*DIN + s*32 + q0*8);
    CP16(zs_base[s] + row1*SP2 + q1*16, zb + (size_t)row1*DIN + s*32 + q1*8);
    CP_COMMIT();
  }

  float acc[16][4];
  #pragma unroll
  for (int i=0;i<16;i++)
    #pragma unroll
    for (int j=0;j<4;j++) acc[i][j]=0.f;

  uint32_t aoffA = (wr*32 + l15)*SP2 + lh*16;
  uint32_t boffA = (wc*64 + l15)*SP2 + lh*16;
  #pragma unroll 1
  for (int c=0;c<8;c++){
    if (c == 7) { CP_WAIT(0); } else { CP_WAIT(1); }
    __syncthreads();
    int cur = c % 3;
    chunk32(xs_base[cur] + aoffA, zs_base[cur] + boffA, acc);
    if (c < 6){
      int nx = (c+2)%3;
      CP16(xs_base[nx] + row0*SP2 + q0*16, xb + (size_t)row0*DIN + (c+2)*32 + q0*8);
      CP16(xs_base[nx] + row1*SP2 + q1*16, xb + (size_t)row1*DIN + (c+2)*32 + q1*8);
      CP16(zs_base[nx] + row0*SP2 + q0*16, zb + (size_t)row0*DIN + (c+2)*32 + q0*8);
      CP16(zs_base[nx] + row1*SP2 + q1*16, zb + (size_t)row1*DIN + (c+2)*32 + q1*8);
      CP_COMMIT();
    }
  }

  // ---- epilogue A: kuf -> smem bf16, fused mu partials, zero-vote ----
  float sf2 = g_sf2v[h];
  uint32_t nzbits = 0;
  {
    float mu_acc[4] = {0.f,0.f,0.f,0.f};
    #pragma unroll
    for (int mt=0;mt<2;mt++){
      int r0 = wr*32 + mt*16 + lane4;
      int r1 = r0 + 8;
      float x20 = sx2[r0], x21 = sx2[r1];
      #pragma unroll
      for (int nf=0;nf<8;nf++){
        int cb = wc*64 + nf*8 + lpair;
        float z20 = sz2[cb], z21 = sz2[cb+1];
        float* a4 = acc[mt*8+nf];
        float k00 = rbf(sf2, fmaxf(x20 + z20 - 2.f*a4[0], 0.f));
        float k01 = rbf(sf2, fmaxf(x20 + z21 - 2.f*a4[1], 0.f));
        float k10 = rbf(sf2, fmaxf(x21 + z20 - 2.f*a4[2], 0.f));
        float k11 = rbf(sf2, fmaxf(x21 + z21 - 2.f*a4[3], 0.f));
        uint32_t w0 = pack_bf16x2(k00,k01);
        uint32_t w1 = pack_bf16x2(k10,k11);
        nzbits |= w0 | w1;
        *(uint32_t*)(smc + OFF_KUF + r0*KPITCH + cb*2) = w0;
        *(uint32_t*)(smc + OFF_KUF + r1*KPITCH + cb*2) = w1;
        float c0 = cs[cb], c1 = cs[cb+1];
        mu_acc[mt*2+0] += k00*c0 + k01*c1;
        mu_acc[mt*2+1] += k10*c0 + k11*c1;
      }
    }
    #pragma unroll
    for (int u=0;u<4;u++){
      float v = mu_acc[u];
      v += __shfl_xor_sync(0xffffffffu, v, 1);
      v += __shfl_xor_sync(0xffffffffu, v, 2);
      if ((lane & 3) == 0){
        int row = wr*32 + (u>>1)*16 + (u&1)*8 + lane4;
        pmu[wc*128 + row] = v;
      }
    }
  }

  int any = __syncthreads_or((int)nzbits);   // barrier + block-wide OR

  if (!any){
    // whole kuf tile is exactly zero: y = 0, diag = 0, mu = pmu(=0)
    if (tid < MM){
      size_t base = (size_t)ho*B_SZ + b0 + tid;
      out[base] = pmu[tid] + pmu[128+tid];
      out[(size_t)HOC*B_SZ + base] = sf2;
    }
    return;
  }

  // ---- stage Q (into dead stage-ring region) ----
  {
    const __nv_bfloat16* Qg = g_Qb + (size_t)ho*MM*MM;
    #pragma unroll
    for (int it=0; it<8; it++){
      int t = tid + it*256;
      int r = t >> 4, cg = t & 15;
      uint4 v = *(const uint4*)(Qg + (size_t)r*MM + cg*8);
      *(uint4*)(smc + OFF_Q + r*KPITCH + cg*16) = v;
    }
  }
  __syncthreads();

  // ---- Phase B: y = kuf @ Q^T ----
  #pragma unroll
  for (int i=0;i<16;i++)
    #pragma unroll
    for (int j=0;j<4;j++) acc[i][j]=0.f;
  mm128(sb + OFF_KUF, sb + OFF_Q, wr, wc, l15, lh, acc);

  {
    float v_acc[4] = {0.f,0.f,0.f,0.f};
    #pragma unroll
    for (int mt=0;mt<2;mt++){
      int r0 = wr*32 + mt*16 + lane4;
      int r1 = r0 + 8;
      #pragma unroll
      for (int nf=0;nf<8;nf++){
        int cb = wc*64 + nf*8 + lpair;
        uint32_t p0 = *(const uint32_t*)(smc + OFF_KUF + r0*KPITCH + cb*2);
        uint32_t p1 = *(const uint32_t*)(smc + OFF_KUF + r1*KPITCH + cb*2);
        __nv_bfloat162 h0 = *reinterpret_cast<__nv_bfloat162*>(&p0);
        __nv_bfloat162 h1 = *reinterpret_cast<__nv_bfloat162*>(&p1);
        float* a4 = acc[mt*8+nf];
        v_acc[mt*2+0] += __low2float(h0)*a4[0] + __high2float(h0)*a4[1];
        v_acc[mt*2+1] += __low2float(h1)*a4[2] + __high2float(h1)*a4[3];
      }
    }
    #pragma unroll
    for (int u=0;u<4;u++){
      float v = v_acc[u];
      v += __shfl_xor_sync(0xffffffffu, v, 1);
      v += __shfl_xor_sync(0xffffffffu, v, 2);
      if ((lane & 3) == 0){
        int row = wr*32 + (u>>1)*16 + (u&1)*8 + lane4;
        pvar[wc*128 + row] = v;
      }
    }
  }
  __syncthreads();

  if (tid < MM){
    size_t base = (size_t)ho*B_SZ + b0 + tid;
    out[base] = pmu[tid] + pmu[128+tid];
    out[(size_t)HOC*B_SZ + base] = sf2 - (pvar[tid] + pvar[128+tid]);
  }
}

// ---------------- launch ----------------
extern "C" void kernel_launch(void* const* d_in, const int* in_sizes, int n_in,
                              void* d_out, int out_size){
  const float* x      = (const float*)d_in[0];
  const float* z      = (const float*)d_in[1];
  const float* u_mean = (const float*)d_in[2];
  const float* u_tril = (const float*)d_in[3];
  const float* theta  = (const float*)d_in[4];
  float* out = (float*)d_out;

  cudaFuncSetAttribute(k_factor, cudaFuncAttributeMaxDynamicSharedMemorySize, N_TOT);
  cudaFuncSetAttribute(k_main,   cudaFuncAttributeMaxDynamicSharedMemorySize, SMEM_MAIN);

  k_prep<<<NH*B_SZ + HOC*MM, 256>>>(x, z, theta);
  k_factor<<<HOC, 256, N_TOT>>>(u_mean, u_tril);
  k_main<<<dim3(B_SZ/MM, HOC), 256, SMEM_MAIN>>>(out);
}

// round 10
// speedup vs baseline: 21.2715x; 1.1108x over previous
#include <cuda_runtime.h>
#include <cuda_bf16.h>
#include <math.h>
#include <cstdint>

#define B_SZ  4096
#define DIN   256
#define NOUT  32
#define MM    128
#define NH    2
#define HOC   (NH*NOUT)
#define JIT   1e-4f
#define TRILN (MM*(MM+1)/2)
#define D2CUT 170.0f

// ---------------- scratch ----------------
__device__ float g_sf2v[NH];
__device__ float g_x2[NH*B_SZ];
__device__ float g_z2[HOC*MM];
__device__ float g_cv[HOC*MM];
__device__ __align__(16) __nv_bfloat16 g_xb[NH*B_SZ*DIN];
__device__ __align__(16) __nv_bfloat16 g_zb[HOC*MM*DIN];
__device__ __align__(16) __nv_bfloat16 g_Qb[HOC*MM*MM];

// ---------------- helpers ----------------
__device__ __forceinline__ uint32_t smem_u32(const void* p){
  uint32_t a;
  asm("{ .reg .u64 t; cvta.to.shared.u64 t, %1; cvt.u32.u64 %0, t; }" : "=r"(a) : "l"(p));
  return a;
}
__device__ __forceinline__ void ldsm4(uint32_t addr, uint32_t* r){
  asm volatile("ldmatrix.sync.aligned.m8n8.x4.shared.b16 {%0,%1,%2,%3}, [%4];"
    : "=r"(r[0]),"=r"(r[1]),"=r"(r[2]),"=r"(r[3]) : "r"(addr));
}
__device__ __forceinline__ void mma16816(float* c, const uint32_t* a, const uint32_t* b){
  asm volatile("mma.sync.aligned.m16n8k16.row.col.f32.bf16.bf16.f32 "
    "{%0,%1,%2,%3}, {%4,%5,%6,%7}, {%8,%9}, {%0,%1,%2,%3};"
    : "+f"(c[0]),"+f"(c[1]),"+f"(c[2]),"+f"(c[3])
    : "r"(a[0]),"r"(a[1]),"r"(a[2]),"r"(a[3]), "r"(b[0]),"r"(b[1]));
}
#define CP16(dst, src) asm volatile("cp.async.cg.shared.global [%0], [%1], 16;" :: "r"(dst), "l"(src))
#define CP_COMMIT()    asm volatile("cp.async.commit_group;" ::: "memory")
#define CP_WAIT(n)     asm volatile("cp.async.wait_group %0;" :: "n"(n) : "memory")

__device__ __forceinline__ uint32_t pack_bf16x2(float lo, float hi){
  uint32_t r;
  asm("cvt.rn.satfinite.bf16x2.f32 %0, %1, %2;" : "=r"(r) : "f"(hi), "f"(lo));
  return r;
}
__device__ __forceinline__ float rbf(float sf2, float d2){
  return (d2 < D2CUT) ? sf2*__expf(-0.5f*d2) : 0.f;
}

#define SP2    80       // K=32 stage pitch bytes
#define XSTB   10240    // one K=32 stage buffer: 128*80
#define KPITCH 272

// 128x128x128 bf16 block GEMM from KPITCH tiles
__device__ __forceinline__ void mm128(uint32_t aBase, uint32_t bBase,
                                      int wr, int wc, int l15, int lh,
                                      float acc[16][4]){
  uint32_t aB0 = aBase + (wr*32 + l15)*KPITCH + lh*16;
  uint32_t bB0 = bBase + (wc*64 + l15)*KPITCH + lh*16;
  #pragma unroll
  for (int ks=0;ks<8;ks++){
    uint32_t af[2][4], bt[4], bfr[8][2];
    #pragma unroll
    for (int mt=0;mt<2;mt++) ldsm4(aB0 + ks*32 + mt*16*KPITCH, af[mt]);
    #pragma unroll
    for (int nn=0;nn<4;nn++){
      ldsm4(bB0 + ks*32 + nn*16*KPITCH, bt);
      bfr[nn*2][0]=bt[0]; bfr[nn*2][1]=bt[2];
      bfr[nn*2+1][0]=bt[1]; bfr[nn*2+1][1]=bt[3];
    }
    #pragma unroll
    for (int mt=0;mt<2;mt++)
      #pragma unroll
      for (int nf=0;nf<8;nf++)
        mma16816(acc[mt*8+nf], af[mt], bfr[nf]);
  }
}

// one K=32 chunk from SP2 stages
__device__ __forceinline__ void chunk32(uint32_t aB, uint32_t bB, float acc[16][4]){
  #pragma unroll
  for (int ks=0;ks<2;ks++){
    uint32_t af[2][4], bt[4], bfr[8][2];
    #pragma unroll
    for (int mt=0;mt<2;mt++) ldsm4(aB + ks*32 + mt*16*SP2, af[mt]);
    #pragma unroll
    for (int nn=0;nn<4;nn++){
      ldsm4(bB + ks*32 + nn*16*SP2, bt);
      bfr[nn*2][0]=bt[0]; bfr[nn*2][1]=bt[2];
      bfr[nn*2+1][0]=bt[1]; bfr[nn*2+1][1]=bt[3];
    }
    #pragma unroll
    for (int mt=0;mt<2;mt++)
      #pragma unroll
      for (int nf=0;nf<8;nf++)
        mma16816(acc[mt*8+nf], af[mt], bfr[nf]);
  }
}

// ---------------- vectorized prep: 4 rows/block, 4 elems/thread ----------------
__global__ void k_prep(const float* __restrict__ x, const float* __restrict__ z,
                       const float* __restrict__ theta){
  __shared__ float sw[8];
  int tid = threadIdx.x;
  int lane = tid & 31, wid = tid >> 5;
  int rloc = tid >> 6;
  int col  = (tid & 63) << 2;
  int row  = blockIdx.x*4 + rloc;

  int h; const float* src; __nv_bfloat16* dst;
  if (row < NH*B_SZ){
    h = row / B_SZ;
    int b = row - h*B_SZ;
    src = x + (size_t)b*DIN;
    dst = g_xb + (size_t)row*DIN;
  } else {
    int id = row - NH*B_SZ;
    h = id / (NOUT*MM);
    int om = id % (NOUT*MM);
    src = z + (size_t)om*DIN;
    dst = g_zb + (size_t)id*DIN;
  }
  const float* th = theta + h*(DIN+1) + 1 + col;
  float4 xv = *(const float4*)(src + col);
  float v0 = xv.x * expf(-th[0]);
  float v1 = xv.y * expf(-th[1]);
  float v2 = xv.z * expf(-th[2]);
  float v3 = xv.w * expf(-th[3]);
  uint2 pk = make_uint2(pack_bf16x2(v0,v1), pack_bf16x2(v2,v3));
  *(uint2*)(dst + col) = pk;

  float p = v0*v0 + v1*v1 + v2*v2 + v3*v3;
  #pragma unroll
  for (int o=16;o;o>>=1) p += __shfl_down_sync(0xffffffffu, p, o);
  if (lane == 0) sw[wid] = p;
  __syncthreads();
  if (tid < 4){
    float t = sw[2*tid] + sw[2*tid+1];
    int r = blockIdx.x*4 + tid;
    if (r < NH*B_SZ) g_x2[r] = t; else g_z2[r - NH*B_SZ] = t;
  }
  if (blockIdx.x == 0 && tid < NH) g_sf2v[tid] = expf(theta[tid*(DIN+1)]);
}

// ============ k_factor ============
#define N_KB   0        // Kb bf16 128x272   34816  (later: Lsb)
#define N_XB   34816    // Xb                34816
#define N_YB   69632    // Yb / Tb / stages  34816
#define N_UM   104448
#define N_PC   104960
#define N_TOT  105984

__global__ __launch_bounds__(256) void k_factor(const float* __restrict__ u_mean,
                                                const float* __restrict__ u_tril){
  extern __shared__ char smc[];
  uint32_t sb = smem_u32(smc);
  float* um = (float*)(smc + N_UM);
  float* pc = (float*)(smc + N_PC);

  int ho = blockIdx.x;
  int h = ho / NOUT, o = ho % NOUT;
  int tid = threadIdx.x;
  int wid = tid >> 5, lane = tid & 31;
  int wr = wid >> 1, wc = wid & 1;
  int l15 = lane & 15, lh = lane >> 4;
  int lane4 = lane >> 2, lpair = (lane & 3)*2;

  const __nv_bfloat16* zb = g_zb + (size_t)ho*MM*DIN;
  float sf2 = g_sf2v[h];
  float dK  = sf2 + JIT;
  float c0  = 1.0f / dK;

  if (tid < MM) um[tid] = u_mean[o*MM + tid];

  // ---- Phase 1: Kuu via bf16 mma, K=256, 8 chunks of 32, 3-stage ring ----
  int offdiag_nz = 0;
  {
    uint32_t zs_base[3];
    #pragma unroll
    for (int s=0;s<3;s++) zs_base[s] = sb + N_YB + s*XSTB;
    int row0 = tid >> 2, q0 = tid & 3;
    int row1 = (tid+256) >> 2, q1 = (tid+256) & 3;
    #pragma unroll
    for (int s=0;s<2;s++){
      CP16(zs_base[s] + row0*SP2 + q0*16, zb + (size_t)row0*DIN + s*32 + q0*8);
      CP16(zs_base[s] + row1*SP2 + q1*16, zb + (size_t)row1*DIN + s*32 + q1*8);
      CP_COMMIT();
    }

    float acc[16][4];
    #pragma unroll
    for (int i=0;i<16;i++)
      #pragma unroll
      for (int j=0;j<4;j++) acc[i][j]=0.f;

    uint32_t aoff = (wr*32 + l15)*SP2 + lh*16;
    uint32_t boff = (wc*64 + l15)*SP2 + lh*16;
    #pragma unroll 1
    for (int c=0;c<8;c++){
      if (c == 7) { CP_WAIT(0); } else { CP_WAIT(1); }
      __syncthreads();
      int cur = c % 3;
      chunk32(zs_base[cur] + aoff, zs_base[cur] + boff, acc);
      if (c < 6){
        int nx = (c+2)%3;
        CP16(zs_base[nx] + row0*SP2 + q0*16, zb + (size_t)row0*DIN + (c+2)*32 + q0*8);
        CP16(zs_base[nx] + row1*SP2 + q1*16, zb + (size_t)row1*DIN + (c+2)*32 + q1*8);
        CP_COMMIT();
      }
    }

    // epilogue: Kb, Xb = c0*I, off-diagonal zero-vote
    #pragma unroll
    for (int mt=0;mt<2;mt++){
      int r0 = wr*32 + mt*16 + lane4;
      int r1 = r0 + 8;
      float z20 = g_z2[ho*MM+r0], z21 = g_z2[ho*MM+r1];
      #pragma unroll
      for (int nf=0;nf<8;nf++){
        int cb = wc*64 + nf*8 + lpair;
        float zc0 = g_z2[ho*MM+cb], zc1 = g_z2[ho*MM+cb+1];
        float* a4 = acc[mt*8+nf];
        float v00 = (r0==cb  ) ? dK : rbf(sf2, fmaxf(z20+zc0-2.f*a4[0],0.f));
        float v01 = (r0==cb+1) ? dK : rbf(sf2, fmaxf(z20+zc1-2.f*a4[1],0.f));
        float v10 = (r1==cb  ) ? dK : rbf(sf2, fmaxf(z21+zc0-2.f*a4[2],0.f));
        float v11 = (r1==cb+1) ? dK : rbf(sf2, fmaxf(z21+zc1-2.f*a4[3],0.f));
        if ((r0!=cb   && v00!=0.f) || (r0!=cb+1 && v01!=0.f) ||
            (r1!=cb   && v10!=0.f) || (r1!=cb+1 && v11!=0.f)) offdiag_nz = 1;
        *(uint32_t*)(smc + N_KB + r0*KPITCH + cb*2) = pack_bf16x2(v00,v01);
        *(uint32_t*)(smc + N_KB + r1*KPITCH + cb*2) = pack_bf16x2(v10,v11);
        float x00 = (r0==cb  ) ? c0 : 0.f;
        float x01 = (r0==cb+1) ? c0 : 0.f;
        float x10 = (r1==cb  ) ? c0 : 0.f;
        float x11 = (r1==cb+1) ? c0 : 0.f;
        *(uint32_t*)(smc + N_XB + r0*KPITCH + cb*2) = pack_bf16x2(x00,x01);
        *(uint32_t*)(smc + N_XB + r1*KPITCH + cb*2) = pack_bf16x2(x10,x11);
      }
    }
  }

  int any = __syncthreads_or(offdiag_nz);

  if (!any){
    // Kuu = dK*I exactly (in bf16 pipeline): P = c0*I, c = c0*um,
    // T = c0*Ls, Q = c0*I - (c0*Ls)(c0*Ls)^T   — one GEMM total.
    if (tid < MM) g_cv[ho*MM + tid] = c0 * um[tid];
    {
      const float* Lv = u_tril + (size_t)o*TRILN;
      for (int it=0; it<32; it++){
        int idx = tid + it*256;
        int j = idx & 127, kp = (idx >> 7)*2;
        float v0 = (kp   >= j) ? c0*Lv[(kp*(kp+1))/2 + j] : 0.f;
        float v1 = (kp+1 >= j) ? c0*Lv[((kp+1)*(kp+2))/2 + j] : 0.f;
        *(uint32_t*)(smc + N_KB + j*KPITCH + kp*2) = pack_bf16x2(v0, v1);
      }
    }
    __syncthreads();
    float acc[16][4];
    #pragma unroll
    for (int i=0;i<16;i++)
      #pragma unroll
      for (int j=0;j<4;j++) acc[i][j]=0.f;
    mm128(sb + N_KB, sb + N_KB, wr, wc, l15, lh, acc);
    __nv_bfloat16* Qg = g_Qb + (size_t)ho*MM*MM;
    #pragma unroll
    for (int mt=0;mt<2;mt++){
      int r0 = wr*32 + mt*16 + lane4;
      int r1 = r0 + 8;
      #pragma unroll
      for (int nf=0;nf<8;nf++){
        int cb = wc*64 + nf*8 + lpair;
        float* a4 = acc[mt*8+nf];
        float q00 = ((r0==cb  ) ? c0 : 0.f) - a4[0];
        float q01 = ((r0==cb+1) ? c0 : 0.f) - a4[1];
        float q10 = ((r1==cb  ) ? c0 : 0.f) - a4[2];
        float q11 = ((r1==cb+1) ? c0 : 0.f) - a4[3];
        *(uint32_t*)&Qg[(size_t)r0*MM + cb] = pack_bf16x2(q00,q01);
        *(uint32_t*)&Qg[(size_t)r1*MM + cb] = pack_bf16x2(q10,q11);
      }
    }
    return;
  }

  // ---- slow path: Newton-Schulz x2 ----
  #pragma unroll 1
  for (int it=0; it<2; it++){
    __syncthreads();
    {
      float acc[16][4];
      #pragma unroll
      for (int i=0;i<16;i++)
        #pragma unroll
        for (int j=0;j<4;j++) acc[i][j]=0.f;
      mm128(sb + N_KB, sb + N_XB, wr, wc, l15, lh, acc);
      #pragma unroll
      for (int mt=0;mt<2;mt++){
        int r0 = wr*32 + mt*16 + lane4;
        int r1 = r0 + 8;
        #pragma unroll
        for (int nf=0;nf<8;nf++){
          int cb = wc*64 + nf*8 + lpair;
          float* a4 = acc[mt*8+nf];
          *(uint32_t*)(smc + N_YB + r0*KPITCH + cb*2) = pack_bf16x2(a4[0],a4[1]);
          *(uint32_t*)(smc + N_YB + r1*KPITCH + cb*2) = pack_bf16x2(a4[2],a4[3]);
        }
      }
    }
    __syncthreads();
    {
      float acc[16][4];
      #pragma unroll
      for (int i=0;i<16;i++)
        #pragma unroll
        for (int j=0;j<4;j++) acc[i][j]=0.f;
      mm128(sb + N_XB, sb + N_YB, wr, wc, l15, lh, acc);
      __syncthreads();
      float c_acc[4] = {0.f,0.f,0.f,0.f};
      #pragma unroll
      for (int mt=0;mt<2;mt++){
        int r0 = wr*32 + mt*16 + lane4;
        int r1 = r0 + 8;
        #pragma unroll
        for (int nf=0;nf<8;nf++){
          int cb = wc*64 + nf*8 + lpair;
          uint32_t p0 = *(const uint32_t*)(smc + N_XB + r0*KPITCH + cb*2);
          uint32_t p1 = *(const uint32_t*)(smc + N_XB + r1*KPITCH + cb*2);
          __nv_bfloat162 h0 = *reinterpret_cast<__nv_bfloat162*>(&p0);
          __nv_bfloat162 h1 = *reinterpret_cast<__nv_bfloat162*>(&p1);
          float* a4 = acc[mt*8+nf];
          float n00 = 2.f*__low2float(h0)  - a4[0];
          float n01 = 2.f*__high2float(h0) - a4[1];
          float n10 = 2.f*__low2float(h1)  - a4[2];
          float n11 = 2.f*__high2float(h1) - a4[3];
          *(uint32_t*)(smc + N_XB + r0*KPITCH + cb*2) = pack_bf16x2(n00,n01);
          *(uint32_t*)(smc + N_XB + r1*KPITCH + cb*2) = pack_bf16x2(n10,n11);
          if (it == 1){
            float u0 = um[cb], u1 = um[cb+1];
            c_acc[mt*2+0] += n00*u0 + n01*u1;
            c_acc[mt*2+1] += n10*u0 + n11*u1;
          }
        }
      }
      if (it == 1){
        #pragma unroll
        for (int u=0;u<4;u++){
          float v = c_acc[u];
          v += __shfl_xor_sync(0xffffffffu, v, 1);
          v += __shfl_xor_sync(0xffffffffu, v, 2);
          if ((lane & 3) == 0){
            int row = wr*32 + (u>>1)*16 + (u&1)*8 + lane4;
            pc[wc*128 + row] = v;
          }
        }
      }
    }
  }
  __syncthreads();
  if (tid < MM) g_cv[ho*MM + tid] = pc[tid] + pc[128+tid];

  // ---- Lsb into Kb ----
  {
    const float* Lv = u_tril + (size_t)o*TRILN;
    for (int it=0; it<32; it++){
      int idx = tid + it*256;
      int j = idx & 127, kp = (idx >> 7)*2;
      float v0 = (kp   >= j) ? Lv[(kp*(kp+1))/2 + j] : 0.f;
      float v1 = (kp+1 >= j) ? Lv[((kp+1)*(kp+2))/2 + j] : 0.f;
      *(uint32_t*)(smc + N_KB + j*KPITCH + kp*2) = pack_bf16x2(v0, v1);
    }
  }
  __syncthreads();

  // ---- T = P @ Ls -> Yb ----
  {
    float acc[16][4];
    #pragma unroll
    for (int i=0;i<16;i++)
      #pragma unroll
      for (int j=0;j<4;j++) acc[i][j]=0.f;
    mm128(sb + N_XB, sb + N_KB, wr, wc, l15, lh, acc);
    __syncthreads();
    #pragma unroll
    for (int mt=0;mt<2;mt++){
      int r0 = wr*32 + mt*16 + lane4;
      int r1 = r0 + 8;
      #pragma unroll
      for (int nf=0;nf<8;nf++){
        int cb = wc*64 + nf*8 + lpair;
        float* a4 = acc[mt*8+nf];
        *(uint32_t*)(smc + N_YB + r0*KPITCH + cb*2) = pack_bf16x2(a4[0],a4[1]);
        *(uint32_t*)(smc + N_YB + r1*KPITCH + cb*2) = pack_bf16x2(a4[2],a4[3]);
      }
    }
  }
  __syncthreads();

  // ---- Q = P - T T^T -> g_Qb ----
  {
    float acc[16][4];
    #pragma unroll
    for (int i=0;i<16;i++)
      #pragma unroll
      for (int j=0;j<4;j++) acc[i][j]=0.f;
    mm128(sb + N_YB, sb + N_YB, wr, wc, l15, lh, acc);
    __nv_bfloat16* Qg = g_Qb + (size_t)ho*MM*MM;
    #pragma unroll
    for (int mt=0;mt<2;mt++){
      int r0 = wr*32 + mt*16 + lane4;
      int r1 = r0 + 8;
      #pragma unroll
      for (int nf=0;nf<8;nf++){
        int cb = wc*64 + nf*8 + lpair;
        uint32_t p0 = *(const uint32_t*)(smc + N_XB + r0*KPITCH + cb*2);
        uint32_t p1 = *(const uint32_t*)(smc + N_XB + r1*KPITCH + cb*2);
        __nv_bfloat162 h0 = *reinterpret_cast<__nv_bfloat162*>(&p0);
        __nv_bfloat162 h1 = *reinterpret_cast<__nv_bfloat162*>(&p1);
        float* a4 = acc[mt*8+nf];
        *(uint32_t*)&Qg[(size_t)r0*MM + cb] = pack_bf16x2(__low2float(h0)-a4[0], __high2float(h0)-a4[1]);
        *(uint32_t*)&Qg[(size_t)r1*MM + cb] = pack_bf16x2(__low2float(h1)-a4[2], __high2float(h1)-a4[3]);
      }
    }
  }
}

// ============ k_main: K=32 ring, Phase-B skip when kuf tile == 0 ============
#define OFF_CS    0
#define OFF_X2    512
#define OFF_Z2    1024
#define OFF_PMU   1536
#define OFF_PVAR  2560
#define OFF_ST    3584
#define OFF_KUF   65024
#define OFF_Q     OFF_ST
#define SMEM_MAIN 99840

__global__ __launch_bounds__(256,2) void k_main(float* __restrict__ out){
  extern __shared__ char smc[];
  uint32_t sb = smem_u32(smc);
  float* cs  = (float*)(smc + OFF_CS);
  float* sx2 = (float*)(smc + OFF_X2);
  float* sz2 = (float*)(smc + OFF_Z2);
  float* pmu = (float*)(smc + OFF_PMU);
  float* pvar= (float*)(smc + OFF_PVAR);

  int ho = blockIdx.y;
  int h  = ho / NOUT;
  int b0 = blockIdx.x * MM;
  int tid = threadIdx.x;
  int wid = tid >> 5, lane = tid & 31;
  int wr = wid >> 1, wc = wid & 1;
  int l15 = lane & 15, lh = lane >> 4;
  int lane4 = lane >> 2, lpair = (lane & 3)*2;

  if (tid < MM){
    cs[tid]  = g_cv[ho*MM + tid];
    sz2[tid] = g_z2[ho*MM + tid];
    sx2[tid] = g_x2[h*B_SZ + b0 + tid];
  }

  const __nv_bfloat16* xb = g_xb + ((size_t)h*B_SZ + b0)*DIN;
  const __nv_bfloat16* zb = g_zb + (size_t)ho*MM*DIN;

  uint32_t xs_base[3], zs_base[3];
  #pragma unroll
  for (int s=0;s<3;s++){
    xs_base[s] = sb + OFF_ST + s*2*XSTB;
    zs_base[s] = xs_base[s] + XSTB;
  }
  int row0 = tid >> 2, q0 = tid & 3;
  int row1 = (tid+256) >> 2, q1 = (tid+256) & 3;

  #pragma unroll
  for (int s=0;s<2;s++){
    CP16(xs_base[s] + row0*SP2 + q0*16, xb + (size_t)row0*DIN + s*32 + q0*8);
    CP16(xs_base[s] + row1*SP2 + q1*16, xb + (size_t)row1*DIN + s*32 + q1*8);
    CP16(zs_base[s] + row0*SP2 + q0*16, zb + (size_t)row0*DIN + s*32 + q0*8);
    CP16(zs_base[s] + row1*SP2 + q1*16, zb + (size_t)row1*DIN + s*32 + q1*8);
    CP_COMMIT();
  }

  float acc[16][4];
  #pragma unroll
  for (int i=0;i<16;i++)
    #pragma unroll
    for (int j=0;j<4;j++) acc[i][j]=0.f;

  uint32_t aoffA = (wr*32 + l15)*SP2 + lh*16;
  uint32_t boffA = (wc*64 + l15)*SP2 + lh*16;
  #pragma unroll 1
  for (int c=0;c<8;c++){
    if (c == 7) { CP_WAIT(0); } else { CP_WAIT(1); }
    __syncthreads();
    int cur = c % 3;
    chunk32(xs_base[cur] + aoffA, zs_base[cur] + boffA, acc);
    if (c < 6){
      int nx = (c+2)%3;
      CP16(xs_base[nx] + row0*SP2 + q0*16, xb + (size_t)row0*DIN + (c+2)*32 + q0*8);
      CP16(xs_base[nx] + row1*SP2 + q1*16, xb + (size_t)row1*DIN + (c+2)*32 + q1*8);
      CP16(zs_base[nx] + row0*SP2 + q0*16, zb + (size_t)row0*DIN + (c+2)*32 + q0*8);
      CP16(zs_base[nx] + row1*SP2 + q1*16, zb + (size_t)row1*DIN + (c+2)*32 + q1*8);
      CP_COMMIT();
    }
  }

  // ---- epilogue A ----
  float sf2 = g_sf2v[h];
  uint32_t nzbits = 0;
  {
    float mu_acc[4] = {0.f,0.f,0.f,0.f};
    #pragma unroll
    for (int mt=0;mt<2;mt++){
      int r0 = wr*32 + mt*16 + lane4;
      int r1 = r0 + 8;
      float x20 = sx2[r0], x21 = sx2[r1];
      #pragma unroll
      for (int nf=0;nf<8;nf++){
        int cb = wc*64 + nf*8 + lpair;
        float z20 = sz2[cb], z21 = sz2[cb+1];
        float* a4 = acc[mt*8+nf];
        float k00 = rbf(sf2, fmaxf(x20 + z20 - 2.f*a4[0], 0.f));
        float k01 = rbf(sf2, fmaxf(x20 + z21 - 2.f*a4[1], 0.f));
        float k10 = rbf(sf2, fmaxf(x21 + z20 - 2.f*a4[2], 0.f));
        float k11 = rbf(sf2, fmaxf(x21 + z21 - 2.f*a4[3], 0.f));
        uint32_t w0 = pack_bf16x2(k00,k01);
        uint32_t w1 = pack_bf16x2(k10,k11);
        nzbits |= w0 | w1;
        *(uint32_t*)(smc + OFF_KUF + r0*KPITCH + cb*2) = w0;
        *(uint32_t*)(smc + OFF_KUF + r1*KPITCH + cb*2) = w1;
        float c0 = cs[cb], c1 = cs[cb+1];
        mu_acc[mt*2+0] += k00*c0 + k01*c1;
        mu_acc[mt*2+1] += k10*c0 + k11*c1;
      }
    }
    #pragma unroll
    for (int u=0;u<4;u++){
      float v = mu_acc[u];
      v += __shfl_xor_sync(0xffffffffu, v, 1);
      v += __shfl_xor_sync(0xffffffffu, v, 2);
      if ((lane & 3) == 0){
        int row = wr*32 + (u>>1)*16 + (u&1)*8 + lane4;
        pmu[wc*128 + row] = v;
      }
    }
  }

  int any = __syncthreads_or((int)nzbits);

  if (!any){
    if (tid < MM){
      size_t base = (size_t)ho*B_SZ + b0 + tid;
      out[base] = pmu[tid] + pmu[128+tid];
      out[(size_t)HOC*B_SZ + base] = sf2;
    }
    return;
  }

  // ---- stage Q ----
  {
    const __nv_bfloat16* Qg = g_Qb + (size_t)ho*MM*MM;
    #pragma unroll
    for (int it=0; it<8; it++){
      int t = tid + it*256;
      int r = t >> 4, cg = t & 15;
      uint4 v = *(const uint4*)(Qg + (size_t)r*MM + cg*8);
      *(uint4*)(smc + OFF_Q + r*KPITCH + cg*16) = v;
    }
  }
  __syncthreads();

  // ---- Phase B: y = kuf @ Q^T ----
  #pragma unroll
  for (int i=0;i<16;i++)
    #pragma unroll
    for (int j=0;j<4;j++) acc[i][j]=0.f;
  mm128(sb + OFF_KUF, sb + OFF_Q, wr, wc, l15, lh, acc);

  {
    float v_acc[4] = {0.f,0.f,0.f,0.f};
    #pragma unroll
    for (int mt=0;mt<2;mt++){
      int r0 = wr*32 + mt*16 + lane4;
      int r1 = r0 + 8;
      #pragma unroll
      for (int nf=0;nf<8;nf++){
        int cb = wc*64 + nf*8 + lpair;
        uint32_t p0 = *(const uint32_t*)(smc + OFF_KUF + r0*KPITCH + cb*2);
        uint32_t p1 = *(const uint32_t*)(smc + OFF_KUF + r1*KPITCH + cb*2);
        __nv_bfloat162 h0 = *reinterpret_cast<__nv_bfloat162*>(&p0);
        __nv_bfloat162 h1 = *reinterpret_cast<__nv_bfloat162*>(&p1);
        float* a4 = acc[mt*8+nf];
        v_acc[mt*2+0] += __low2float(h0)*a4[0] + __high2float(h0)*a4[1];
        v_acc[mt*2+1] += __low2float(h1)*a4[2] + __high2float(h1)*a4[3];
      }
    }
    #pragma unroll
    for (int u=0;u<4;u++){
      float v = v_acc[u];
      v += __shfl_xor_sync(0xffffffffu, v, 1);
      v += __shfl_xor_sync(0xffffffffu, v, 2);
      if ((lane & 3) == 0){
        int row = wr*32 + (u>>1)*16 + (u&1)*8 + lane4;
        pvar[wc*128 + row] = v;
      }
    }
  }
  __syncthreads();

  if (tid < MM){
    size_t base = (size_t)ho*B_SZ + b0 + tid;
    out[base] = pmu[tid] + pmu[128+tid];
    out[(size_t)HOC*B_SZ + base] = sf2 - (pvar[tid] + pvar[128+tid]);
  }
}

// ---------------- launch ----------------
extern "C" void kernel_launch(void* const* d_in, const int* in_sizes, int n_in,
                              void* d_out, int out_size){
  const float* x      = (const float*)d_in[0];
  const float* z      = (const float*)d_in[1];
  const float* u_mean = (const float*)d_in[2];
  const float* u_tril = (const float*)d_in[3];
  const float* theta  = (const float*)d_in[4];
  float* out = (float*)d_out;

  cudaFuncSetAttribute(k_factor, cudaFuncAttributeMaxDynamicSharedMemorySize, N_TOT);
  cudaFuncSetAttribute(k_main,   cudaFuncAttributeMaxDynamicSharedMemorySize, SMEM_MAIN);

  k_prep<<<(NH*B_SZ + HOC*MM)/4, 256>>>(x, z, theta);
  k_factor<<<HOC, 256, N_TOT>>>(u_mean, u_tril);
  k_main<<<dim3(B_SZ/MM, HOC), 256, SMEM_MAIN>>>(out);
}